// round 12
// baseline (speedup 1.0000x reference)
#include <cuda_runtime.h>
#include <cuda_bf16.h>
#include <math.h>
#include <stdint.h>

// Problem constants
#define BB 4
#define SS 2048
#define DD 1024
#define HH 16
#define HD 64
#define EE 8
#define DFF 4096
#define NSLOT 16        // E*SLOTS
#define ROWS (BB*SS)    // 8192
#define SSEG 8
#define SCHUNK (SS/SSEG)  // 256

// tcgen05 availability: only in arch-specific (sm_103a/sm_100a-family) device pass
#if defined(__CUDA_ARCH__) && (defined(__CUDA_ARCH_FEAT_SM103_ALL) || defined(__CUDA_ARCH_FEAT_SM100_ALL) || defined(__CUDA_ARCH_SPECIFIC__) || defined(__CUDA_ARCH_FAMILY_SPECIFIC__))
#define TCOK 1
#else
#define TCOK 0
#endif

// ---------------- scratch (static __device__ globals; no allocation) ----------------
__device__ float g_h[ROWS * DD];
__device__ __nv_bfloat16 g_hb[ROWS * DD];
__device__ __nv_bfloat16 g_qb[ROWS * DD];
__device__ __nv_bfloat16 g_kvb[ROWS * 128];
__device__ __nv_bfloat16 g_vT[BB * HD * SS];   // [b][dim][seq]
__device__ __nv_bfloat16 g_ccb[ROWS * DD];
__device__ __nv_bfloat16 g_wqT[DD * DD];    // [N=D][K=D]
__device__ __nv_bfloat16 g_wkvT[128 * DD];  // [N=128][K=D]
__device__ __nv_bfloat16 g_woT[DD * DD];    // [N=D][K=D]
__device__ float g_x1[ROWS * DD];
__device__ float g_m[ROWS * DD];
__device__ float g_logits[ROWS * NSLOT];
__device__ float g_dispatch[ROWS * NSLOT];
__device__ float g_combine[ROWS * NSLOT];
__device__ float g_xs[BB * NSLOT * DD];
__device__ float g_xs_part[SSEG * BB * NSLOT * DD];
__device__ float g_hid[EE * 8 * DFF];
__device__ float g_ys[BB * NSLOT * DD];

// ---------------- asm helpers ----------------
__device__ __forceinline__ unsigned smem_u32(const void* p) {
    return (unsigned)__cvta_generic_to_shared(p);
}
__device__ __forceinline__ void mma16816(float* d, const unsigned* a, const unsigned* b) {
    asm volatile("mma.sync.aligned.m16n8k16.row.col.f32.bf16.bf16.f32 "
                 "{%0,%1,%2,%3}, {%4,%5,%6,%7}, {%8,%9}, {%0,%1,%2,%3};\n"
                 : "+f"(d[0]), "+f"(d[1]), "+f"(d[2]), "+f"(d[3])
                 : "r"(a[0]), "r"(a[1]), "r"(a[2]), "r"(a[3]), "r"(b[0]), "r"(b[1]));
}
__device__ __forceinline__ void ldsm4(unsigned* r, unsigned a) {
    asm volatile("ldmatrix.sync.aligned.m8n8.x4.shared.b16 {%0,%1,%2,%3}, [%4];\n"
                 : "=r"(r[0]), "=r"(r[1]), "=r"(r[2]), "=r"(r[3]) : "r"(a));
}
__device__ __forceinline__ void ldsm4t(unsigned* r, unsigned a) {
    asm volatile("ldmatrix.sync.aligned.m8n8.x4.trans.shared.b16 {%0,%1,%2,%3}, [%4];\n"
                 : "=r"(r[0]), "=r"(r[1]), "=r"(r[2]), "=r"(r[3]) : "r"(a));
}
__device__ __forceinline__ unsigned pack_bf16(float a, float b) {
    __nv_bfloat162 t;
    t.x = __float2bfloat16(a);
    t.y = __float2bfloat16(b);
    return *reinterpret_cast<unsigned*>(&t);
}
__device__ __forceinline__ float ex2(float x) {
    float y;
    asm("ex2.approx.f32 %0, %1;" : "=f"(y) : "f"(x));
    return y;
}
__device__ __forceinline__ void cp16(unsigned dst, const void* src) {
    asm volatile("cp.async.cg.shared.global [%0], [%1], 16;\n" :: "r"(dst), "l"(src));
}
__device__ __forceinline__ void cp_commit() {
    asm volatile("cp.async.commit_group;\n");
}
template<int N>
__device__ __forceinline__ void cp_wait() {
    asm volatile("cp.async.wait_group %0;\n" :: "n"(N));
}

#if TCOK
// ---------------- tcgen05 helpers (arch-specific pass only) ----------------
__device__ __forceinline__ uint32_t elect_one() {
    uint32_t pred;
    asm volatile("{\n\t.reg .pred p;\n\telect.sync _|p, 0xFFFFFFFF;\n\t"
                 "selp.b32 %0, 1, 0, p;\n\t}" : "=r"(pred));
    return pred;
}
#define TC_ALLOC(smem_addr, ncols) \
    asm volatile("tcgen05.alloc.cta_group::1.sync.aligned.shared::cta.b32 [%0], %1;" \
                 :: "r"((uint32_t)(smem_addr)), "r"((uint32_t)(ncols)) : "memory")
#define TC_RELINQ() \
    asm volatile("tcgen05.relinquish_alloc_permit.cta_group::1.sync.aligned;")
#define TC_DEALLOC(tmem, ncols) \
    asm volatile("tcgen05.dealloc.cta_group::1.sync.aligned.b32 %0, %1;" \
                 :: "r"(tmem), "r"((uint32_t)(ncols)))
#define TC_COMMIT(mbar) \
    asm volatile("tcgen05.commit.cta_group::1.mbarrier::arrive::one.shared::cluster.b64 [%0];" \
                 :: "r"((uint32_t)(mbar)) : "memory")
#define TC_FENCE_AFTER()  asm volatile("tcgen05.fence::after_thread_sync;" ::: "memory")
#define TC_FENCE_BEFORE() asm volatile("tcgen05.fence::before_thread_sync;" ::: "memory")
#define TC_WAIT_LD()      asm volatile("tcgen05.wait::ld.sync.aligned;" ::: "memory")
#define MBAR_INIT(mbar, cnt) \
    asm volatile("mbarrier.init.shared.b64 [%0], %1;" \
                 :: "r"((uint32_t)(mbar)), "r"((uint32_t)(cnt)) : "memory")
#define MBAR_INVAL(mbar) \
    asm volatile("mbarrier.inval.shared.b64 [%0];" :: "r"((uint32_t)(mbar)) : "memory")
#define FENCE_PROXY() asm volatile("fence.proxy.async.shared::cta;" ::: "memory")

__device__ __forceinline__ void mbar_wait(uint32_t mbar, uint32_t parity) {
    uint32_t done;
    asm volatile("{\n\t.reg .pred p;\n\t"
                 "mbarrier.try_wait.parity.acquire.cta.shared::cta.b64 p, [%1], %2;\n\t"
                 "selp.b32 %0, 1, 0, p;\n\t}"
                 : "=r"(done) : "r"(mbar), "r"(parity) : "memory");
    if (!done) {
        asm volatile("{\n\t.reg .pred P1;\n\t"
                     "WL_%=:\n\t"
                     "mbarrier.try_wait.parity.acquire.cta.shared::cta.b64 P1, [%0], %1, 0x989680;\n\t"
                     "@P1 bra.uni WD_%=;\n\t"
                     "bra.uni WL_%=;\n\t"
                     "WD_%=:\n\t}"
                     :: "r"(mbar), "r"(parity) : "memory");
    }
}
__device__ __forceinline__ void tc_mma_f16_ss(uint32_t d, uint64_t ad, uint64_t bd,
                                              uint32_t idesc, bool en) {
    uint32_t e = en ? 1u : 0u, z = 0u;
    asm volatile("{\n\t.reg .pred p;\n\tsetp.ne.u32 p, %5, 0;\n\t"
                 "tcgen05.mma.cta_group::1.kind::f16 [%0], %1, %2, %3, {%4,%4,%4,%4}, p;\n\t}"
                 :: "r"(d), "l"(ad), "l"(bd), "r"(idesc), "r"(z), "r"(e) : "memory");
}
__device__ __forceinline__ uint32_t ld_shared_u32(uint32_t addr) {
    uint32_t v;
    asm volatile("ld.shared.b32 %0, [%1];" : "=r"(v) : "r"(addr));
    return v;
}
// SW128 smem descriptor, K-major: layout 2, version 1, SBO=64, LBO=1
__device__ __forceinline__ uint64_t make_desc(uint32_t addr) {
    const uint64_t base = (uint64_t(2) << 61) | (uint64_t(1) << 46)
                        | (uint64_t(64) << 32) | (uint64_t(1) << 16);
    return base | ((uint64_t)(addr >> 4) & 0x3FFF);
}
#define LDTM_X32(r, addr) \
    asm volatile("tcgen05.ld.sync.aligned.32x32b.x32.b32 " \
        "{%0,%1,%2,%3,%4,%5,%6,%7,%8,%9,%10,%11,%12,%13,%14,%15," \
        "%16,%17,%18,%19,%20,%21,%22,%23,%24,%25,%26,%27,%28,%29,%30,%31}, [%32];" \
        : "=r"((r)[0]),"=r"((r)[1]),"=r"((r)[2]),"=r"((r)[3]), \
          "=r"((r)[4]),"=r"((r)[5]),"=r"((r)[6]),"=r"((r)[7]), \
          "=r"((r)[8]),"=r"((r)[9]),"=r"((r)[10]),"=r"((r)[11]), \
          "=r"((r)[12]),"=r"((r)[13]),"=r"((r)[14]),"=r"((r)[15]), \
          "=r"((r)[16]),"=r"((r)[17]),"=r"((r)[18]),"=r"((r)[19]), \
          "=r"((r)[20]),"=r"((r)[21]),"=r"((r)[22]),"=r"((r)[23]), \
          "=r"((r)[24]),"=r"((r)[25]),"=r"((r)[26]),"=r"((r)[27]), \
          "=r"((r)[28]),"=r"((r)[29]),"=r"((r)[30]),"=r"((r)[31]) \
        : "r"(addr))
#endif // TCOK

// ---------------- layernorm ----------------
__global__ void ln_kernel(const float* __restrict__ x, const float* __restrict__ gamma,
                          float* __restrict__ out, __nv_bfloat16* __restrict__ ob) {
    long long row = blockIdx.x;
    const float* p = x + row * DD;
    float v[4];
    float s = 0.f, sq = 0.f;
#pragma unroll
    for (int i = 0; i < 4; i++) {
        v[i] = p[threadIdx.x + i * 256];
        s += v[i];
        sq += v[i] * v[i];
    }
    __shared__ float rs[8], rq[8];
#pragma unroll
    for (int o = 16; o; o >>= 1) {
        s  += __shfl_xor_sync(0xFFFFFFFFu, s, o);
        sq += __shfl_xor_sync(0xFFFFFFFFu, sq, o);
    }
    int w = threadIdx.x >> 5;
    if ((threadIdx.x & 31) == 0) { rs[w] = s; rq[w] = sq; }
    __syncthreads();
    if (threadIdx.x == 0) {
        float ts = 0.f, tq = 0.f;
        for (int i = 0; i < 8; i++) { ts += rs[i]; tq += rq[i]; }
        rs[0] = ts; rq[0] = tq;
    }
    __syncthreads();
    float mean = rs[0] * (1.f / (float)DD);
    float var  = rq[0] * (1.f / (float)DD) - mean * mean;
    float rstd = rsqrtf(var + 1e-5f);
    float* o = out + row * DD;
#pragma unroll
    for (int i = 0; i < 4; i++) {
        int d = threadIdx.x + i * 256;
        float val = gamma[d] * (v[i] - mean) * rstd;
        o[d] = val;
        if (ob) ob[row * DD + d] = __float2bfloat16(val);
    }
}

// ---------------- weight transpose + convert ----------------
__global__ void transpose_cvt_kernel(const float* __restrict__ in,
                                     __nv_bfloat16* __restrict__ out, int R, int C) {
    __shared__ float t[32][33];
    int c0 = blockIdx.x * 32, r0 = blockIdx.y * 32;
    for (int i = threadIdx.y; i < 32; i += 8)
        t[i][threadIdx.x] = in[(long long)(r0 + i) * C + c0 + threadIdx.x];
    __syncthreads();
    for (int i = threadIdx.y; i < 32; i += 8)
        out[(long long)(c0 + i) * R + r0 + threadIdx.x] = __float2bfloat16(t[threadIdx.x][i]);
}

// ---------------- v transpose ----------------
__global__ void vT_kernel(const __nv_bfloat16* __restrict__ kvb,
                          __nv_bfloat16* __restrict__ vT) {
    __shared__ __nv_bfloat16 t[32][33];
    int s0 = blockIdx.x * 32, d0 = blockIdx.y * 32, b = blockIdx.z;
    for (int i = threadIdx.y; i < 32; i += 8)
        t[i][threadIdx.x] = kvb[((long long)(b * SS + s0 + i)) * 128 + 64 + d0 + threadIdx.x];
    __syncthreads();
    for (int i = threadIdx.y; i < 32; i += 8)
        vT[((long long)(b * HD + d0 + i)) * SS + s0 + threadIdx.x] = t[threadIdx.x][i];
}

// ---------------- unified bf16 GEMM: 3-stage pipeline, one mbarrier per buffer ----------------
template<bool ADD, bool OUTBF>
__global__ __launch_bounds__(256) __cluster_dims__(1, 1, 1) void gemm_kernel(
    const __nv_bfloat16* __restrict__ A, const __nv_bfloat16* __restrict__ BT,
    const float* __restrict__ AddP, float* __restrict__ Cf,
    __nv_bfloat16* __restrict__ Cb, int M, int N, int K, float alpha) {
    extern __shared__ char smraw[];
    uint32_t sb0 = smem_u32(smraw);
    uint32_t sbase = (sb0 + 1023u) & ~1023u;
    int tid = threadIdx.x, lane = tid & 31, wrp = tid >> 5;
    int row0 = blockIdx.y * 128, col0 = blockIdx.x * 128;
    const uint32_t T0 = sbase + 1024;

    auto loadA = [&](uint32_t off, int k0) {
#pragma unroll
        for (int i = 0; i < 4; i++) {
            int idx = i * 256 + tid;
            int r = idx >> 3, ch = idx & 7;
            cp16(off + r * 128 + ((ch ^ (r & 7)) << 4),
                 A + (long long)(row0 + r) * K + k0 + ch * 8);
        }
    };
    auto loadB = [&](uint32_t off, int k0) {
#pragma unroll
        for (int i = 0; i < 4; i++) {
            int idx = i * 256 + tid;
            int r = idx >> 3, ch = idx & 7;
            cp16(off + r * 128 + ((ch ^ (r & 7)) << 4),
                 BT + (long long)(col0 + r) * K + k0 + ch * 8);
        }
    };
    int NT = K / 64;

#if TCOK
    const uint32_t BOFF = T0 + 3 * 16384;
    if (wrp == 0) { TC_ALLOC(sbase, 128); TC_RELINQ(); }
    if (tid == 0) {
        MBAR_INIT(sbase + 8, 1);
        MBAR_INIT(sbase + 16, 1);
        MBAR_INIT(sbase + 24, 1);
    }
    __syncthreads();
    uint32_t tmem = ld_shared_u32(sbase);
    const uint32_t IDESC = 0x490u | (16u << 17) | (8u << 24);
    auto mb = [&](int i) -> uint32_t { return sbase + 8 + (uint32_t)i * 8; };

    loadA(T0, 0); loadB(BOFF, 0); cp_commit();
    if (NT > 1) { loadA(T0 + 16384, 64); loadB(BOFF + 16384, 64); cp_commit(); }

    for (int t = 0; t < NT; t++) {
        uint32_t sA = T0 + (uint32_t)(t % 3) * 16384;
        uint32_t sB = BOFF + (uint32_t)(t % 3) * 16384;
        if (t + 1 < NT) cp_wait<1>();
        else cp_wait<0>();
        FENCE_PROXY();
        __syncthreads();
        if (wrp == 0 && elect_one()) {
            uint64_t ad = make_desc(sA);
            uint64_t bd = make_desc(sB);
#pragma unroll
            for (int kk = 0; kk < 4; kk++)
                tc_mma_f16_ss(tmem, ad + kk * 2, bd + kk * 2, IDESC, (t > 0) || (kk > 0));
            TC_COMMIT(mb(t % 3));
        }
        if (t + 2 < NT) {
            if (t >= 1) mbar_wait(mb((t - 1) % 3), (uint32_t)(((t - 1) / 3) & 1));
            loadA(T0 + (uint32_t)((t + 2) % 3) * 16384, (t + 2) * 64);
            loadB(BOFF + (uint32_t)((t + 2) % 3) * 16384, (t + 2) * 64);
            cp_commit();
        }
    }
    for (int tt = (NT >= 3 ? NT - 3 : 0); tt < NT; tt++)
        mbar_wait(mb(tt % 3), (uint32_t)((tt / 3) & 1));
    TC_FENCE_AFTER();

    {
        long long r = row0 + (wrp & 3) * 32 + lane;
        int cbase = (wrp >> 2) * 64;
#pragma unroll
        for (int cg = 0; cg < 2; cg++) {
            uint32_t regs[32];
            LDTM_X32(regs, tmem + cbase + cg * 32);
            TC_WAIT_LD();
            int c0 = col0 + cbase + cg * 32;
            if (OUTBF) {
#pragma unroll
                for (int i = 0; i < 32; i += 2) {
                    __nv_bfloat162 p;
                    p.x = __float2bfloat16(__uint_as_float(regs[i]) * alpha);
                    p.y = __float2bfloat16(__uint_as_float(regs[i + 1]) * alpha);
                    *(__nv_bfloat162*)(Cb + r * N + c0 + i) = p;
                }
            } else {
#pragma unroll
                for (int i = 0; i < 32; i += 2) {
                    float v0 = __uint_as_float(regs[i]) * alpha;
                    float v1 = __uint_as_float(regs[i + 1]) * alpha;
                    if (ADD) {
                        float2 a = *(const float2*)(AddP + r * N + c0 + i);
                        v0 += a.x; v1 += a.y;
                    }
                    *(float2*)(Cf + r * N + c0 + i) = make_float2(v0, v1);
                }
            }
        }
    }
    TC_FENCE_BEFORE();
    __syncthreads();
    if (tid == 0) { MBAR_INVAL(mb(0)); MBAR_INVAL(mb(1)); MBAR_INVAL(mb(2)); }
    __syncthreads();
    if (wrp == 0) TC_DEALLOC(tmem, 128);
#else
    const __nv_bfloat16* As[2] = { (const __nv_bfloat16*)(smraw + (T0 - sb0)),
                                   (const __nv_bfloat16*)(smraw + (T0 - sb0) + 16384) };
    const __nv_bfloat16* Bs[2] = { (const __nv_bfloat16*)(smraw + (T0 - sb0) + 32768),
                                   (const __nv_bfloat16*)(smraw + (T0 - sb0) + 49152) };
    int wm = wrp >> 2, wn = wrp & 3;

    float acc[4][4][4];
#pragma unroll
    for (int mt = 0; mt < 4; mt++)
#pragma unroll
        for (int nt = 0; nt < 4; nt++)
#pragma unroll
            for (int i = 0; i < 4; i++) acc[mt][nt][i] = 0.f;

    loadA(T0, 0); loadB(T0 + 32768, 0); cp_commit();
    for (int t = 0; t < NT; t++) {
        if (t + 1 < NT) {
            loadA(T0 + (uint32_t)((t + 1) & 1) * 16384, (t + 1) * 64);
            loadB(T0 + 32768 + (uint32_t)((t + 1) & 1) * 16384, (t + 1) * 64);
            cp_commit();
            cp_wait<1>();
        } else cp_wait<0>();
        __syncthreads();
        const __nv_bfloat16* as = As[t & 1];
        const __nv_bfloat16* bs = Bs[t & 1];
#pragma unroll
        for (int kk = 0; kk < 4; kk++) {
            unsigned af[4][4], bf[2][4];
#pragma unroll
            for (int mt = 0; mt < 4; mt++) {
                int r = wm * 64 + mt * 16 + (lane & 15);
                int chunk = ((kk * 2 + (lane >> 4)) ^ (r & 7));
                ldsm4(af[mt], smem_u32(as + r * 64 + chunk * 8));
            }
#pragma unroll
            for (int np = 0; np < 2; np++) {
                int nrow = wn * 32 + (2 * np + ((lane >> 4) & 1)) * 8 + (lane & 7);
                int chunk = ((kk * 2 + ((lane >> 3) & 1)) ^ (nrow & 7));
                ldsm4(bf[np], smem_u32(bs + nrow * 64 + chunk * 8));
            }
#pragma unroll
            for (int mt = 0; mt < 4; mt++)
#pragma unroll
                for (int nt = 0; nt < 4; nt++)
                    mma16816(acc[mt][nt], af[mt], bf[nt >> 1] + (nt & 1) * 2);
        }
        __syncthreads();
    }
#pragma unroll
    for (int mt = 0; mt < 4; mt++) {
#pragma unroll
        for (int nt = 0; nt < 4; nt++) {
            int r = row0 + wm * 64 + mt * 16 + (lane >> 2);
            int c = col0 + wn * 32 + nt * 8 + 2 * (lane & 3);
            float v0 = acc[mt][nt][0] * alpha, v1 = acc[mt][nt][1] * alpha;
            float v2 = acc[mt][nt][2] * alpha, v3 = acc[mt][nt][3] * alpha;
            if (OUTBF) {
                __nv_bfloat162 p0; p0.x = __float2bfloat16(v0); p0.y = __float2bfloat16(v1);
                __nv_bfloat162 p1; p1.x = __float2bfloat16(v2); p1.y = __float2bfloat16(v3);
                *(__nv_bfloat162*)(Cb + (long long)r * N + c) = p0;
                *(__nv_bfloat162*)(Cb + (long long)(r + 8) * N + c) = p1;
            } else {
                if (ADD) {
                    float2 a0 = *(const float2*)(AddP + (long long)r * N + c);
                    float2 a1 = *(const float2*)(AddP + (long long)(r + 8) * N + c);
                    v0 += a0.x; v1 += a0.y; v2 += a1.x; v3 += a1.y;
                }
                *(float2*)(Cf + (long long)r * N + c) = make_float2(v0, v1);
                *(float2*)(Cf + (long long)(r + 8) * N + c) = make_float2(v2, v3);
            }
        }
    }
#endif
}

// ---------------- flash attention: R8/R11 version (passing, unchanged) ----------------
__global__ __launch_bounds__(256) __cluster_dims__(1, 1, 1) void flash_kernel(
    const __nv_bfloat16* __restrict__ qb, const __nv_bfloat16* __restrict__ kvb,
    const __nv_bfloat16* __restrict__ vT, __nv_bfloat16* __restrict__ ccb) {
    int tid = threadIdx.x, lane = tid & 31, wrp = tid >> 5;
    int b = blockIdx.y >> 4, h = blockIdx.y & 15;
    long long qrow0 = (long long)b * SS + blockIdx.x * 128;

#if TCOK
    extern __shared__ char smraw[];
    uint32_t sb0 = smem_u32(smraw);
    uint32_t sbase = (sb0 + 1023u) & ~1023u;
    const uint32_t QOFF = sbase + 2048;
    const uint32_t K0 = QOFF + 16384;
    const uint32_t V0 = K0 + 16384;
    const uint32_t POFF = V0 + 16384;
    float* lsp = (float*)(smraw + (sbase - sb0) + 512);
    char* pgen = smraw + (POFF - sb0);

    if (wrp == 0) { TC_ALLOC(sbase, 128); TC_RELINQ(); }
    if (tid == 0) { MBAR_INIT(sbase + 8, 1); MBAR_INIT(sbase + 16, 1); }
    __syncthreads();
    uint32_t tmem = ld_shared_u32(sbase);
    const uint32_t mbS = sbase + 8, mbP = sbase + 16;
    const int S_OFF = 0, O_OFF = 64;

#pragma unroll
    for (int i = 0; i < 4; i++) {
        int idx = i * 256 + tid;
        int r = idx >> 3, ch = idx & 7;
        cp16(QOFF + r * 128 + ((ch ^ (r & 7)) << 4),
             qb + (qrow0 + r) * DD + h * 64 + ch * 8);
    }
    auto loadKV = [&](int buf, int kt) {
#pragma unroll
        for (int i = 0; i < 2; i++) {
            int idx = i * 256 + tid;
            int r = idx >> 3, ch = idx & 7;
            uint32_t sw = r * 128 + ((ch ^ (r & 7)) << 4);
            cp16(K0 + buf * 8192 + sw,
                 kvb + ((long long)b * SS + kt * 64 + r) * 128 + ch * 8);
            cp16(V0 + buf * 8192 + sw,
                 vT + ((long long)(b * HD + r)) * SS + kt * 64 + ch * 8);
        }
        cp_commit();
    };
    loadKV(0, 0);

    const uint32_t IDESC = 0x490u | (8u << 17) | (8u << 24);
    int my_half = wrp >> 2;
    int rrow = (wrp & 3) * 32 + lane;
    float ls = 0.f;

    for (int kt = 0; kt < SS / 64; kt++) {
        if (kt + 1 < SS / 64) { loadKV((kt + 1) & 1, kt + 1); cp_wait<1>(); }
        else cp_wait<0>();
        FENCE_PROXY();
        __syncthreads();
        uint32_t kbuf = K0 + (uint32_t)(kt & 1) * 8192;
        uint32_t vbuf = V0 + (uint32_t)(kt & 1) * 8192;

        if (wrp == 0 && elect_one()) {
            uint64_t qd = make_desc(QOFF);
            uint64_t kd = make_desc(kbuf);
#pragma unroll
            for (int kk = 0; kk < 4; kk++)
                tc_mma_f16_ss(tmem + S_OFF, qd + kk * 2, kd + kk * 2, IDESC, kk > 0);
            TC_COMMIT(mbS);
        }
        mbar_wait(mbS, (uint32_t)(kt & 1));
        TC_FENCE_AFTER();

        uint32_t sreg[32];
        LDTM_X32(sreg, tmem + S_OFF + my_half * 32);
        TC_WAIT_LD();
        float p[32];
#pragma unroll
        for (int i = 0; i < 32; i++) {
            p[i] = ex2(__uint_as_float(sreg[i]));
            ls += p[i];
        }
        uint32_t pw[16];
#pragma unroll
        for (int i = 0; i < 16; i++) pw[i] = pack_bf16(p[2 * i], p[2 * i + 1]);
#pragma unroll
        for (int j = 0; j < 4; j++) {
            int ch = my_half * 4 + j;
            *(uint4*)(pgen + rrow * 128 + ((ch ^ (rrow & 7)) << 4)) =
                make_uint4(pw[4 * j], pw[4 * j + 1], pw[4 * j + 2], pw[4 * j + 3]);
        }
        FENCE_PROXY();
        TC_FENCE_BEFORE();
        __syncthreads();

        if (wrp == 0 && elect_one()) {
            TC_FENCE_AFTER();
            uint64_t pd = make_desc(POFF);
            uint64_t vd = make_desc(vbuf);
#pragma unroll
            for (int kk = 0; kk < 4; kk++)
                tc_mma_f16_ss(tmem + O_OFF, pd + kk * 2, vd + kk * 2,
                              IDESC, (kt > 0) || (kk > 0));
            TC_COMMIT(mbP);
        }
        mbar_wait(mbP, (uint32_t)(kt & 1));
        TC_FENCE_AFTER();
    }

    lsp[my_half * 128 + rrow] = ls;
    __syncthreads();
    float inv = 1.f / (lsp[rrow] + lsp[128 + rrow]);

    uint32_t oreg[32];
    LDTM_X32(oreg, tmem + O_OFF + my_half * 32);
    TC_WAIT_LD();
    long long gr = qrow0 + rrow;
    int c0 = h * 64 + my_half * 32;
#pragma unroll
    for (int i = 0; i < 32; i += 2) {
        __nv_bfloat162 pv;
        pv.x = __float2bfloat16(__uint_as_float(oreg[i]) * inv);
        pv.y = __float2bfloat16(__uint_as_float(oreg[i + 1]) * inv);
        *(__nv_bfloat162*)(ccb + gr * DD + c0 + i) = pv;
    }
    TC_FENCE_BEFORE();
    __syncthreads();
    if (tid == 0) { MBAR_INVAL(mbS); MBAR_INVAL(mbP); }
    __syncthreads();
    if (wrp == 0) TC_DEALLOC(tmem, 128);
#else
    // ================= HMMA fallback (R6 version) =================
    __shared__ __nv_bfloat16 Qs[128 * 64];
    __shared__ __nv_bfloat16 Ks[2][64 * 64];
    __shared__ __nv_bfloat16 Vs[2][64 * 64];
    int w = wrp;

    auto loadKV = [&](int st, int kt) {
#pragma unroll
        for (int i = 0; i < 2; i++) {
            int idx = i * 2048 + tid * 8;
            int r = idx >> 6, c = idx & 63;
            int chunk = (c >> 3) ^ (r & 7);
            long long grow = (long long)b * SS + kt * 64 + r;
            cp16(smem_u32(&Ks[st][r * 64 + chunk * 8]), kvb + grow * 128 + c);
            cp16(smem_u32(&Vs[st][r * 64 + chunk * 8]), kvb + grow * 128 + 64 + c);
        }
        cp_commit();
    };

#pragma unroll
    for (int i = 0; i < 4; i++) {
        int idx = i * 2048 + tid * 8;
        int r = idx >> 6, c = idx & 63;
        int chunk = (c >> 3) ^ (r & 7);
        cp16(smem_u32(Qs + r * 64 + chunk * 8), qb + (qrow0 + r) * DD + h * 64 + c);
    }
    loadKV(0, 0);
    cp_wait<0>();
    __syncthreads();

    unsigned qa[4][4];
    {
        int r = w * 16 + (lane & 15);
#pragma unroll
        for (int kk = 0; kk < 4; kk++) {
            int chunk = ((kk * 2 + (lane >> 4)) ^ (r & 7));
            ldsm4(qa[kk], smem_u32(Qs + r * 64 + chunk * 8));
        }
    }

    float o[8][4];
#pragma unroll
    for (int nt = 0; nt < 8; nt++)
#pragma unroll
        for (int i = 0; i < 4; i++) o[nt][i] = 0.f;
    float ls0 = 0.f, ls1 = 0.f;

    for (int kt = 0; kt < SS / 64; kt++) {
        if (kt + 1 < SS / 64) { loadKV((kt + 1) & 1, kt + 1); cp_wait<1>(); }
        else cp_wait<0>();
        __syncthreads();
        const __nv_bfloat16* ks = Ks[kt & 1];
        const __nv_bfloat16* vs = Vs[kt & 1];

        float sf[8][4];
#pragma unroll
        for (int nt = 0; nt < 8; nt++)
#pragma unroll
            for (int i = 0; i < 4; i++) sf[nt][i] = 0.f;
#pragma unroll
        for (int kk = 0; kk < 4; kk++) {
#pragma unroll
            for (int np = 0; np < 4; np++) {
                unsigned bbf[4];
                int krow = (2 * np + ((lane >> 4) & 1)) * 8 + (lane & 7);
                int chunk = ((kk * 2 + ((lane >> 3) & 1)) ^ (krow & 7));
                ldsm4(bbf, smem_u32(ks + krow * 64 + chunk * 8));
                mma16816(sf[2 * np], qa[kk], bbf);
                mma16816(sf[2 * np + 1], qa[kk], bbf + 2);
            }
        }
#pragma unroll
        for (int nt = 0; nt < 8; nt++) {
            sf[nt][0] = ex2(sf[nt][0]);
            sf[nt][1] = ex2(sf[nt][1]);
            sf[nt][2] = ex2(sf[nt][2]);
            sf[nt][3] = ex2(sf[nt][3]);
            ls0 += sf[nt][0] + sf[nt][1];
            ls1 += sf[nt][2] + sf[nt][3];
        }
#pragma unroll
        for (int j = 0; j < 4; j++) {
            unsigned pa[4];
            pa[0] = pack_bf16(sf[2 * j][0], sf[2 * j][1]);
            pa[1] = pack_bf16(sf[2 * j][2], sf[2 * j][3]);
            pa[2] = pack_bf16(sf[2 * j + 1][0], sf[2 * j + 1][1]);
            pa[3] = pack_bf16(sf[2 * j + 1][2], sf[2 * j + 1][3]);
#pragma unroll
            for (int np = 0; np < 4; np++) {
                unsigned vv[4];
                int vrow = j * 16 + (lane & 7) + ((lane >> 3) & 1) * 8;
                int cgrp = 2 * np + ((lane >> 4) & 1);
                int chunk = (cgrp ^ (vrow & 7));
                ldsm4t(vv, smem_u32(vs + vrow * 64 + chunk * 8));
                mma16816(o[2 * np], pa, vv);
                mma16816(o[2 * np + 1], pa, vv + 2);
            }
        }
        __syncthreads();
    }

    ls0 += __shfl_xor_sync(0xFFFFFFFFu, ls0, 1);
    ls0 += __shfl_xor_sync(0xFFFFFFFFu, ls0, 2);
    ls1 += __shfl_xor_sync(0xFFFFFFFFu, ls1, 1);
    ls1 += __shfl_xor_sync(0xFFFFFFFFu, ls1, 2);
    float inv0 = 1.f / ls0, inv1 = 1.f / ls1;

    long long gr = qrow0 + w * 16 + (lane >> 2);
#pragma unroll
    for (int nt = 0; nt < 8; nt++) {
        int c = h * 64 + nt * 8 + 2 * (lane & 3);
        __nv_bfloat162 p0, p1;
        p0.x = __float2bfloat16(o[nt][0] * inv0);
        p0.y = __float2bfloat16(o[nt][1] * inv0);
        p1.x = __float2bfloat16(o[nt][2] * inv1);
        p1.y = __float2bfloat16(o[nt][3] * inv1);
        *(__nv_bfloat162*)(ccb + gr * DD + c) = p0;
        *(__nv_bfloat162*)(ccb + (gr + 8) * DD + c) = p1;
    }
#endif
}

// ---------------- logits + dispatch softmax ----------------
__global__ void logits_kernel(const float* __restrict__ m, const float* __restrict__ phi,
                              float* __restrict__ logits, float* __restrict__ dispatch) {
    __shared__ float ms[DD];
    __shared__ float part[8][NSLOT];
    __shared__ float ls[NSLOT];
    long long row = blockIdx.x;
    const float* mr = m + row * DD;
    for (int i = threadIdx.x; i < DD; i += 128) ms[i] = mr[i];
    __syncthreads();
    int e = threadIdx.x % NSLOT, c = threadIdx.x / NSLOT;
    float acc = 0.f;
    for (int d = c * 128; d < c * 128 + 128; d++) acc += ms[d] * phi[d * NSLOT + e];
    part[c][e] = acc;
    __syncthreads();
    if (threadIdx.x < NSLOT) {
        float l = 0.f;
        for (int cc = 0; cc < 8; cc++) l += part[cc][threadIdx.x];
        logits[row * NSLOT + threadIdx.x] = l;
        ls[threadIdx.x] = l;
    }
    __syncthreads();
    if (threadIdx.x < NSLOT) {
        float mx = ls[0];
        for (int j = 1; j < NSLOT; j++) mx = fmaxf(mx, ls[j]);
        float s = 0.f;
        for (int j = 0; j < NSLOT; j++) s += expf(ls[j] - mx);
        dispatch[row * NSLOT + threadIdx.x] = expf(ls[threadIdx.x] - mx) / s;
    }
}

// ---------------- combine softmax over sequence axis ----------------
__global__ void combine_kernel(const float* __restrict__ logits, float* __restrict__ comb) {
    int b = blockIdx.x >> 4, e = blockIdx.x & 15;
    const float* base = logits + ((long long)b * SS) * NSLOT + e;
    float v[8];
    float mx = -1e30f;
#pragma unroll
    for (int i = 0; i < 8; i++) {
        int s = threadIdx.x + i * 256;
        v[i] = base[(long long)s * NSLOT];
        mx = fmaxf(mx, v[i]);
    }
    __shared__ float red[8];
#pragma unroll
    for (int o = 16; o; o >>= 1) mx = fmaxf(mx, __shfl_xor_sync(0xFFFFFFFFu, mx, o));
    int w = threadIdx.x >> 5;
    if ((threadIdx.x & 31) == 0) red[w] = mx;
    __syncthreads();
    if (threadIdx.x == 0) {
        float t = red[0];
        for (int i = 1; i < 8; i++) t = fmaxf(t, red[i]);
        red[0] = t;
    }
    __syncthreads();
    mx = red[0];
    __syncthreads();
    float s = 0.f;
#pragma unroll
    for (int i = 0; i < 8; i++) { v[i] = expf(v[i] - mx); s += v[i]; }
#pragma unroll
    for (int o = 16; o; o >>= 1) s += __shfl_xor_sync(0xFFFFFFFFu, s, o);
    if ((threadIdx.x & 31) == 0) red[w] = s;
    __syncthreads();
    if (threadIdx.x == 0) {
        float t = 0.f;
        for (int i = 0; i < 8; i++) t += red[i];
        red[0] = t;
    }
    __syncthreads();
    float inv = 1.0f / red[0];
    float* ob = comb + ((long long)b * SS) * NSLOT + e;
#pragma unroll
    for (int i = 0; i < 8; i++) {
        int sidx = threadIdx.x + i * 256;
        ob[(long long)sidx * NSLOT] = v[i] * inv;
    }
}

// ---------------- xs partials + reduce ----------------
__global__ void xs_part_kernel(const float* __restrict__ dispatch, const float* __restrict__ m,
                               float* __restrict__ part) {
    int d = blockIdx.x * 256 + threadIdx.x;
    int b = blockIdx.y, seg = blockIdx.z;
    int s0 = seg * SCHUNK;
    __shared__ float ds[SCHUNK][NSLOT];
    for (int i = threadIdx.x; i < SCHUNK * NSLOT; i += 256)
        ds[i >> 4][i & 15] = dispatch[((long long)b * SS + s0) * NSLOT + i];
    __syncthreads();
    float acc[NSLOT];
#pragma unroll
    for (int e = 0; e < NSLOT; e++) acc[e] = 0.f;
    const float* mb = m + ((long long)b * SS + s0) * DD + d;
    for (int s = 0; s < SCHUNK; s++) {
        float mv = mb[(long long)s * DD];
#pragma unroll
        for (int e = 0; e < NSLOT; e++) acc[e] += ds[s][e] * mv;
    }
#pragma unroll
    for (int e = 0; e < NSLOT; e++)
        part[(((long long)seg * BB + b) * NSLOT + e) * DD + d] = acc[e];
}

__global__ void xs_reduce_kernel(const float* __restrict__ part, float* __restrict__ xs) {
    int i = blockIdx.x * 256 + threadIdx.x;
    float a = 0.f;
#pragma unroll
    for (int seg = 0; seg < SSEG; seg++)
        a += part[(long long)seg * BB * NSLOT * DD + i];
    xs[i] = a;
}

// ---------------- expert FFN1: hid = gelu(xs4 @ w1 + b1) ----------------
__global__ void ffn1_kernel(const float* __restrict__ xs, const float* __restrict__ w1,
                            const float* __restrict__ b1, float* __restrict__ hid) {
    int e = blockIdx.x;
    int f = blockIdx.y * 256 + threadIdx.x;
    __shared__ float xss[8][DD];
    for (int i = threadIdx.x; i < 8 * DD; i += 256) {
        int r = i >> 10, d = i & 1023;
        int b = r >> 1, slot = r & 1;
        xss[r][d] = xs[((long long)(b * NSLOT + e * 2 + slot)) * DD + d];
    }
    __syncthreads();
    float acc[8] = {0.f, 0.f, 0.f, 0.f, 0.f, 0.f, 0.f, 0.f};
    const float* w = w1 + (long long)e * DD * DFF + f;
    for (int d = 0; d < DD; d++) {
        float wv = w[(long long)d * DFF];
#pragma unroll
        for (int r = 0; r < 8; r++) acc[r] += xss[r][d] * wv;
    }
    float bias = b1[e * DFF + f];
#pragma unroll
    for (int r = 0; r < 8; r++) {
        float vv = acc[r] + bias;
        float g = 0.5f * vv * (1.0f + erff(vv * 0.70710678118654752f));
        hid[((long long)(e * 8 + r)) * DFF + f] = g;
    }
}

// ---------------- expert FFN2: ys = hid @ w2 + b2 ----------------
__global__ void ffn2_kernel(const float* __restrict__ hid, const float* __restrict__ w2,
                            const float* __restrict__ b2, float* __restrict__ ys) {
    int e = blockIdx.x;
    int d = blockIdx.y * 256 + threadIdx.x;
    float acc[8] = {0.f, 0.f, 0.f, 0.f, 0.f, 0.f, 0.f, 0.f};
    const float* w = w2 + (long long)e * DFF * DD + d;
    const float* hb = hid + (long long)e * 8 * DFF;
    for (int f = 0; f < DFF; f++) {
        float wv = w[(long long)f * DD];
#pragma unroll
        for (int r = 0; r < 8; r++) acc[r] += hb[(long long)r * DFF + f] * wv;
    }
    float bias = b2[e * DD + d];
#pragma unroll
    for (int r = 0; r < 8; r++) {
        int b = r >> 1, slot = r & 1;
        ys[((long long)(b * NSLOT + e * 2 + slot)) * DD + d] = acc[r] + bias;
    }
}

// ---------------- final: out = m + combine @ ys ----------------
__global__ void final_kernel(const float* __restrict__ m, const float* __restrict__ comb,
                             const float* __restrict__ ys, float* __restrict__ out) {
    long long idx = (long long)blockIdx.x * 256 + threadIdx.x;
    int d = (int)(idx & 1023);
    long long row = idx >> 10;
    int b = (int)(row >> 11);
    float acc = m[idx];
    const float* c = comb + row * NSLOT;
    const float* yb = ys + (long long)b * NSLOT * DD + d;
#pragma unroll
    for (int j = 0; j < NSLOT; j++) acc += c[j] * yb[(long long)j * DD];
    out[idx] = acc;
}

// ---------------- launch ----------------
extern "C" void kernel_launch(void* const* d_in, const int* in_sizes, int n_in,
                              void* d_out, int out_size) {
    const float* x        = (const float*)d_in[0];
    const float* wq       = (const float*)d_in[1];
    const float* wkv      = (const float*)d_in[2];
    const float* wo       = (const float*)d_in[3];
    const float* gm_attn  = (const float*)d_in[4];
    const float* gm_moe   = (const float*)d_in[5];
    const float* phi      = (const float*)d_in[6];
    const float* w1       = (const float*)d_in[7];
    const float* b1       = (const float*)d_in[8];
    const float* w2       = (const float*)d_in[9];
    const float* b2       = (const float*)d_in[10];
    float* out = (float*)d_out;

    float *h, *x1, *m, *lg, *dp, *cb, *xs, *xsp, *hid, *ys;
    __nv_bfloat16 *hb, *qb, *kvb, *vt, *ccb, *wqT, *wkvT, *woT;
    cudaGetSymbolAddress((void**)&h,    g_h);
    cudaGetSymbolAddress((void**)&hb,   g_hb);
    cudaGetSymbolAddress((void**)&qb,   g_qb);
    cudaGetSymbolAddress((void**)&kvb,  g_kvb);
    cudaGetSymbolAddress((void**)&vt,   g_vT);
    cudaGetSymbolAddress((void**)&ccb,  g_ccb);
    cudaGetSymbolAddress((void**)&wqT,  g_wqT);
    cudaGetSymbolAddress((void**)&wkvT, g_wkvT);
    cudaGetSymbolAddress((void**)&woT,  g_woT);
    cudaGetSymbolAddress((void**)&x1,   g_x1);
    cudaGetSymbolAddress((void**)&m,    g_m);
    cudaGetSymbolAddress((void**)&lg,   g_logits);
    cudaGetSymbolAddress((void**)&dp,   g_dispatch);
    cudaGetSymbolAddress((void**)&cb,   g_combine);
    cudaGetSymbolAddress((void**)&xs,   g_xs);
    cudaGetSymbolAddress((void**)&xsp,  g_xs_part);
    cudaGetSymbolAddress((void**)&hid,  g_hid);
    cudaGetSymbolAddress((void**)&ys,   g_ys);

    const int G_SMEM = 1024 + 1024 + 6 * 16384; // 100352
    cudaFuncSetAttribute(gemm_kernel<false, true>,
                         cudaFuncAttributeMaxDynamicSharedMemorySize, G_SMEM);
    cudaFuncSetAttribute(gemm_kernel<true, false>,
                         cudaFuncAttributeMaxDynamicSharedMemorySize, G_SMEM);
    const int F_SMEM = 1024 + 2048 + 4 * 16384;
    cudaFuncSetAttribute(flash_kernel,
                         cudaFuncAttributeMaxDynamicSharedMemorySize, F_SMEM);

    // Launch order rearranged (dependency-equivalent) so launch index 3 = gemm_q
    // for the ncu capture window. flash launched twice: delta vs R11 == flash cost.

    // 0) ln: h = LN(x), hb
    ln_kernel<<<ROWS, 256>>>(x, gm_attn, h, hb);
    // 1) wq transpose
    transpose_cvt_kernel<<<dim3(32, 32), dim3(32, 8)>>>(wq, wqT, DD, DD);
    // 2) wkv transpose
    transpose_cvt_kernel<<<dim3(4, 32), dim3(32, 8)>>>(wkv, wkvT, DD, 128);
    // 3) gemm_q  <-- ncu capture target
    gemm_kernel<false, true><<<dim3(8, 64), 256, G_SMEM>>>(
        hb, wqT, nullptr, nullptr, qb, ROWS, DD, DD, 0.125f * 1.4426950408889634f);
    // 4) wo transpose
    transpose_cvt_kernel<<<dim3(32, 32), dim3(32, 8)>>>(wo, woT, DD, DD);
    // 5) gemm_kv
    gemm_kernel<false, true><<<dim3(1, 64), 256, G_SMEM>>>(
        hb, wkvT, nullptr, nullptr, kvb, ROWS, 128, DD, 1.0f);
    // 6) vT
    vT_kernel<<<dim3(SS / 32, HD / 32, BB), dim3(32, 8)>>>(kvb, vt);
    // 7) flash (measurement: launched twice; idempotent)
    flash_kernel<<<dim3(SS / 128, BB * HH), 256, F_SMEM>>>(qb, kvb, vt, ccb);
    // 8) flash duplicate
    flash_kernel<<<dim3(SS / 128, BB * HH), 256, F_SMEM>>>(qb, kvb, vt, ccb);
    // 9) x1 = concat @ wo + h
    gemm_kernel<true, false><<<dim3(8, 64), 256, G_SMEM>>>(
        ccb, woT, h, x1, nullptr, ROWS, DD, DD, 1.0f);
    // 10) m = LN(x1)
    ln_kernel<<<ROWS, 256>>>(x1, gm_moe, m, nullptr);
    // 11) logits + dispatch
    logits_kernel<<<ROWS, 128>>>(m, phi, lg, dp);
    // 12) combine
    combine_kernel<<<BB * NSLOT, 256>>>(lg, cb);
    // 13) xs partials
    xs_part_kernel<<<dim3(DD / 256, BB, SSEG), 256>>>(dp, m, xsp);
    // 14) xs reduce
    xs_reduce_kernel<<<(BB * NSLOT * DD) / 256, 256>>>(xsp, xs);
    // 15) ffn1
    ffn1_kernel<<<dim3(EE, DFF / 256), 256>>>(xs, w1, b1, hid);
    // 16) ffn2
    ffn2_kernel<<<dim3(EE, DD / 256), 256>>>(hid, w2, b2, ys);
    // 17) final
    final_kernel<<<(ROWS * DD) / 256, 256>>>(m, cb, ys, out);
}

// round 13
// speedup vs baseline: 2.8934x; 2.8934x over previous
#include <cuda_runtime.h>
#include <cuda_bf16.h>
#include <math.h>
#include <stdint.h>

// Problem constants
#define BB 4
#define SS 2048
#define DD 1024
#define HH 16
#define HD 64
#define EE 8
#define DFF 4096
#define NSLOT 16        // E*SLOTS
#define ROWS (BB*SS)    // 8192
#define SSEG 8
#define SCHUNK (SS/SSEG)  // 256
#define FSEG 8
#define FCH (DFF/FSEG)    // 512

// tcgen05 availability: only in arch-specific (sm_103a/sm_100a-family) device pass
#if defined(__CUDA_ARCH__) && (defined(__CUDA_ARCH_FEAT_SM103_ALL) || defined(__CUDA_ARCH_FEAT_SM100_ALL) || defined(__CUDA_ARCH_SPECIFIC__) || defined(__CUDA_ARCH_FAMILY_SPECIFIC__))
#define TCOK 1
#else
#define TCOK 0
#endif

// ---------------- scratch (static __device__ globals; no allocation) ----------------
__device__ float g_h[ROWS * DD];
__device__ __nv_bfloat16 g_hb[ROWS * DD];
__device__ __nv_bfloat16 g_qb[ROWS * DD];
__device__ __nv_bfloat16 g_kvb[ROWS * 128];
__device__ __nv_bfloat16 g_vT[BB * HD * SS];   // [b][dim][seq]
__device__ __nv_bfloat16 g_ccb[ROWS * DD];
__device__ __nv_bfloat16 g_wqT[DD * DD];    // [N=D][K=D]
__device__ __nv_bfloat16 g_wkvT[128 * DD];  // [N=128][K=D]
__device__ __nv_bfloat16 g_woT[DD * DD];    // [N=D][K=D]
__device__ float g_phiT[NSLOT * DD];        // [16][1024]
__device__ float g_x1[ROWS * DD];
__device__ float g_m[ROWS * DD];
__device__ float g_logits[ROWS * NSLOT];
__device__ float g_dispatch[ROWS * NSLOT];
__device__ float g_combine[ROWS * NSLOT];
__device__ float g_xs[BB * NSLOT * DD];
__device__ float g_xs_part[SSEG * BB * NSLOT * DD];
__device__ float g_hidT[EE * DFF * 8];      // [e][f][8 rows]
__device__ float g_ys_part[FSEG * BB * NSLOT * DD];
__device__ float g_ys[BB * NSLOT * DD];

// ---------------- asm helpers ----------------
__device__ __forceinline__ unsigned smem_u32(const void* p) {
    return (unsigned)__cvta_generic_to_shared(p);
}
__device__ __forceinline__ void mma16816(float* d, const unsigned* a, const unsigned* b) {
    asm volatile("mma.sync.aligned.m16n8k16.row.col.f32.bf16.bf16.f32 "
                 "{%0,%1,%2,%3}, {%4,%5,%6,%7}, {%8,%9}, {%0,%1,%2,%3};\n"
                 : "+f"(d[0]), "+f"(d[1]), "+f"(d[2]), "+f"(d[3])
                 : "r"(a[0]), "r"(a[1]), "r"(a[2]), "r"(a[3]), "r"(b[0]), "r"(b[1]));
}
__device__ __forceinline__ void ldsm4(unsigned* r, unsigned a) {
    asm volatile("ldmatrix.sync.aligned.m8n8.x4.shared.b16 {%0,%1,%2,%3}, [%4];\n"
                 : "=r"(r[0]), "=r"(r[1]), "=r"(r[2]), "=r"(r[3]) : "r"(a));
}
__device__ __forceinline__ void ldsm4t(unsigned* r, unsigned a) {
    asm volatile("ldmatrix.sync.aligned.m8n8.x4.trans.shared.b16 {%0,%1,%2,%3}, [%4];\n"
                 : "=r"(r[0]), "=r"(r[1]), "=r"(r[2]), "=r"(r[3]) : "r"(a));
}
__device__ __forceinline__ unsigned pack_bf16(float a, float b) {
    __nv_bfloat162 t;
    t.x = __float2bfloat16(a);
    t.y = __float2bfloat16(b);
    return *reinterpret_cast<unsigned*>(&t);
}
__device__ __forceinline__ float ex2(float x) {
    float y;
    asm("ex2.approx.f32 %0, %1;" : "=f"(y) : "f"(x));
    return y;
}
__device__ __forceinline__ void cp16(unsigned dst, const void* src) {
    asm volatile("cp.async.cg.shared.global [%0], [%1], 16;\n" :: "r"(dst), "l"(src));
}
__device__ __forceinline__ void cp_commit() {
    asm volatile("cp.async.commit_group;\n");
}
template<int N>
__device__ __forceinline__ void cp_wait() {
    asm volatile("cp.async.wait_group %0;\n" :: "n"(N));
}

#if TCOK
// ---------------- tcgen05 helpers (arch-specific pass only) ----------------
__device__ __forceinline__ uint32_t elect_one() {
    uint32_t pred;
    asm volatile("{\n\t.reg .pred p;\n\telect.sync _|p, 0xFFFFFFFF;\n\t"
                 "selp.b32 %0, 1, 0, p;\n\t}" : "=r"(pred));
    return pred;
}
#define TC_ALLOC(smem_addr, ncols) \
    asm volatile("tcgen05.alloc.cta_group::1.sync.aligned.shared::cta.b32 [%0], %1;" \
                 :: "r"((uint32_t)(smem_addr)), "r"((uint32_t)(ncols)) : "memory")
#define TC_RELINQ() \
    asm volatile("tcgen05.relinquish_alloc_permit.cta_group::1.sync.aligned;")
#define TC_DEALLOC(tmem, ncols) \
    asm volatile("tcgen05.dealloc.cta_group::1.sync.aligned.b32 %0, %1;" \
                 :: "r"(tmem), "r"((uint32_t)(ncols)))
#define TC_COMMIT(mbar) \
    asm volatile("tcgen05.commit.cta_group::1.mbarrier::arrive::one.shared::cluster.b64 [%0];" \
                 :: "r"((uint32_t)(mbar)) : "memory")
#define TC_FENCE_AFTER()  asm volatile("tcgen05.fence::after_thread_sync;" ::: "memory")
#define TC_FENCE_BEFORE() asm volatile("tcgen05.fence::before_thread_sync;" ::: "memory")
#define TC_WAIT_LD()      asm volatile("tcgen05.wait::ld.sync.aligned;" ::: "memory")
#define MBAR_INIT(mbar, cnt) \
    asm volatile("mbarrier.init.shared.b64 [%0], %1;" \
                 :: "r"((uint32_t)(mbar)), "r"((uint32_t)(cnt)) : "memory")
#define MBAR_INVAL(mbar) \
    asm volatile("mbarrier.inval.shared.b64 [%0];" :: "r"((uint32_t)(mbar)) : "memory")
#define FENCE_PROXY() asm volatile("fence.proxy.async.shared::cta;" ::: "memory")

__device__ __forceinline__ void mbar_wait(uint32_t mbar, uint32_t parity) {
    uint32_t done;
    asm volatile("{\n\t.reg .pred p;\n\t"
                 "mbarrier.try_wait.parity.acquire.cta.shared::cta.b64 p, [%1], %2;\n\t"
                 "selp.b32 %0, 1, 0, p;\n\t}"
                 : "=r"(done) : "r"(mbar), "r"(parity) : "memory");
    if (!done) {
        asm volatile("{\n\t.reg .pred P1;\n\t"
                     "WL_%=:\n\t"
                     "mbarrier.try_wait.parity.acquire.cta.shared::cta.b64 P1, [%0], %1, 0x989680;\n\t"
                     "@P1 bra.uni WD_%=;\n\t"
                     "bra.uni WL_%=;\n\t"
                     "WD_%=:\n\t}"
                     :: "r"(mbar), "r"(parity) : "memory");
    }
}
__device__ __forceinline__ void tc_mma_f16_ss(uint32_t d, uint64_t ad, uint64_t bd,
                                              uint32_t idesc, bool en) {
    uint32_t e = en ? 1u : 0u, z = 0u;
    asm volatile("{\n\t.reg .pred p;\n\tsetp.ne.u32 p, %5, 0;\n\t"
                 "tcgen05.mma.cta_group::1.kind::f16 [%0], %1, %2, %3, {%4,%4,%4,%4}, p;\n\t}"
                 :: "r"(d), "l"(ad), "l"(bd), "r"(idesc), "r"(z), "r"(e) : "memory");
}
__device__ __forceinline__ uint32_t ld_shared_u32(uint32_t addr) {
    uint32_t v;
    asm volatile("ld.shared.b32 %0, [%1];" : "=r"(v) : "r"(addr));
    return v;
}
// SW128 smem descriptor, K-major: layout 2, version 1, SBO=64, LBO=1
__device__ __forceinline__ uint64_t make_desc(uint32_t addr) {
    const uint64_t base = (uint64_t(2) << 61) | (uint64_t(1) << 46)
                        | (uint64_t(64) << 32) | (uint64_t(1) << 16);
    return base | ((uint64_t)(addr >> 4) & 0x3FFF);
}
#define LDTM_X32(r, addr) \
    asm volatile("tcgen05.ld.sync.aligned.32x32b.x32.b32 " \
        "{%0,%1,%2,%3,%4,%5,%6,%7,%8,%9,%10,%11,%12,%13,%14,%15," \
        "%16,%17,%18,%19,%20,%21,%22,%23,%24,%25,%26,%27,%28,%29,%30,%31}, [%32];" \
        : "=r"((r)[0]),"=r"((r)[1]),"=r"((r)[2]),"=r"((r)[3]), \
          "=r"((r)[4]),"=r"((r)[5]),"=r"((r)[6]),"=r"((r)[7]), \
          "=r"((r)[8]),"=r"((r)[9]),"=r"((r)[10]),"=r"((r)[11]), \
          "=r"((r)[12]),"=r"((r)[13]),"=r"((r)[14]),"=r"((r)[15]), \
          "=r"((r)[16]),"=r"((r)[17]),"=r"((r)[18]),"=r"((r)[19]), \
          "=r"((r)[20]),"=r"((r)[21]),"=r"((r)[22]),"=r"((r)[23]), \
          "=r"((r)[24]),"=r"((r)[25]),"=r"((r)[26]),"=r"((r)[27]), \
          "=r"((r)[28]),"=r"((r)[29]),"=r"((r)[30]),"=r"((r)[31]) \
        : "r"(addr))
#endif // TCOK

// ---------------- layernorm ----------------
__global__ void ln_kernel(const float* __restrict__ x, const float* __restrict__ gamma,
                          float* __restrict__ out, __nv_bfloat16* __restrict__ ob) {
    long long row = blockIdx.x;
    const float* p = x + row * DD;
    float v[4];
    float s = 0.f, sq = 0.f;
#pragma unroll
    for (int i = 0; i < 4; i++) {
        v[i] = p[threadIdx.x + i * 256];
        s += v[i];
        sq += v[i] * v[i];
    }
    __shared__ float rs[8], rq[8];
#pragma unroll
    for (int o = 16; o; o >>= 1) {
        s  += __shfl_xor_sync(0xFFFFFFFFu, s, o);
        sq += __shfl_xor_sync(0xFFFFFFFFu, sq, o);
    }
    int w = threadIdx.x >> 5;
    if ((threadIdx.x & 31) == 0) { rs[w] = s; rq[w] = sq; }
    __syncthreads();
    if (threadIdx.x == 0) {
        float ts = 0.f, tq = 0.f;
        for (int i = 0; i < 8; i++) { ts += rs[i]; tq += rq[i]; }
        rs[0] = ts; rq[0] = tq;
    }
    __syncthreads();
    float mean = rs[0] * (1.f / (float)DD);
    float var  = rq[0] * (1.f / (float)DD) - mean * mean;
    float rstd = rsqrtf(var + 1e-5f);
    float* o = out + row * DD;
#pragma unroll
    for (int i = 0; i < 4; i++) {
        int d = threadIdx.x + i * 256;
        float val = gamma[d] * (v[i] - mean) * rstd;
        o[d] = val;
        if (ob) ob[row * DD + d] = __float2bfloat16(val);
    }
}

// ---------------- weight transpose + convert ----------------
__global__ void transpose_cvt_kernel(const float* __restrict__ in,
                                     __nv_bfloat16* __restrict__ out, int R, int C) {
    __shared__ float t[32][33];
    int c0 = blockIdx.x * 32, r0 = blockIdx.y * 32;
    for (int i = threadIdx.y; i < 32; i += 8)
        t[i][threadIdx.x] = in[(long long)(r0 + i) * C + c0 + threadIdx.x];
    __syncthreads();
    for (int i = threadIdx.y; i < 32; i += 8)
        out[(long long)(c0 + i) * R + r0 + threadIdx.x] = __float2bfloat16(t[threadIdx.x][i]);
}

// ---------------- phi transpose (float): phiT[e][d] = phi[d][e] ----------------
__global__ void phiT_kernel(const float* __restrict__ phi, float* __restrict__ phiT) {
    int d = blockIdx.x * 256 + threadIdx.x;
#pragma unroll
    for (int e = 0; e < NSLOT; e++)
        phiT[e * DD + d] = phi[d * NSLOT + e];
}

// ---------------- v transpose ----------------
__global__ void vT_kernel(const __nv_bfloat16* __restrict__ kvb,
                          __nv_bfloat16* __restrict__ vT) {
    __shared__ __nv_bfloat16 t[32][33];
    int s0 = blockIdx.x * 32, d0 = blockIdx.y * 32, b = blockIdx.z;
    for (int i = threadIdx.y; i < 32; i += 8)
        t[i][threadIdx.x] = kvb[((long long)(b * SS + s0 + i)) * 128 + 64 + d0 + threadIdx.x];
    __syncthreads();
    for (int i = threadIdx.y; i < 32; i += 8)
        vT[((long long)(b * HD + d0 + i)) * SS + s0 + threadIdx.x] = t[threadIdx.x][i];
}

// ---------------- unified bf16 GEMM (R11 version, passing) ----------------
template<bool ADD, bool OUTBF>
__global__ __launch_bounds__(256) __cluster_dims__(1, 1, 1) void gemm_kernel(
    const __nv_bfloat16* __restrict__ A, const __nv_bfloat16* __restrict__ BT,
    const float* __restrict__ AddP, float* __restrict__ Cf,
    __nv_bfloat16* __restrict__ Cb, int M, int N, int K, float alpha) {
    extern __shared__ char smraw[];
    uint32_t sb0 = smem_u32(smraw);
    uint32_t sbase = (sb0 + 1023u) & ~1023u;
    int tid = threadIdx.x, lane = tid & 31, wrp = tid >> 5;
    int row0 = blockIdx.y * 128, col0 = blockIdx.x * 128;
    const uint32_t T0 = sbase + 1024;

    auto loadA = [&](uint32_t off, int k0) {
#pragma unroll
        for (int i = 0; i < 4; i++) {
            int idx = i * 256 + tid;
            int r = idx >> 3, ch = idx & 7;
            cp16(off + r * 128 + ((ch ^ (r & 7)) << 4),
                 A + (long long)(row0 + r) * K + k0 + ch * 8);
        }
    };
    auto loadB = [&](uint32_t off, int k0) {
#pragma unroll
        for (int i = 0; i < 4; i++) {
            int idx = i * 256 + tid;
            int r = idx >> 3, ch = idx & 7;
            cp16(off + r * 128 + ((ch ^ (r & 7)) << 4),
                 BT + (long long)(col0 + r) * K + k0 + ch * 8);
        }
    };
    int NT = K / 64;

#if TCOK
    const uint32_t BOFF = T0 + 3 * 16384;
    if (wrp == 0) { TC_ALLOC(sbase, 128); TC_RELINQ(); }
    if (tid == 0) {
        MBAR_INIT(sbase + 8, 1);
        MBAR_INIT(sbase + 16, 1);
        MBAR_INIT(sbase + 24, 1);
    }
    __syncthreads();
    uint32_t tmem = ld_shared_u32(sbase);
    const uint32_t IDESC = 0x490u | (16u << 17) | (8u << 24);
    auto mb = [&](int i) -> uint32_t { return sbase + 8 + (uint32_t)i * 8; };

    loadA(T0, 0); loadB(BOFF, 0); cp_commit();
    if (NT > 1) { loadA(T0 + 16384, 64); loadB(BOFF + 16384, 64); cp_commit(); }

    for (int t = 0; t < NT; t++) {
        uint32_t sA = T0 + (uint32_t)(t % 3) * 16384;
        uint32_t sB = BOFF + (uint32_t)(t % 3) * 16384;
        if (t + 1 < NT) cp_wait<1>();
        else cp_wait<0>();
        FENCE_PROXY();
        __syncthreads();
        if (wrp == 0 && elect_one()) {
            uint64_t ad = make_desc(sA);
            uint64_t bd = make_desc(sB);
#pragma unroll
            for (int kk = 0; kk < 4; kk++)
                tc_mma_f16_ss(tmem, ad + kk * 2, bd + kk * 2, IDESC, (t > 0) || (kk > 0));
            TC_COMMIT(mb(t % 3));
        }
        if (t + 2 < NT) {
            if (t >= 1) mbar_wait(mb((t - 1) % 3), (uint32_t)(((t - 1) / 3) & 1));
            loadA(T0 + (uint32_t)((t + 2) % 3) * 16384, (t + 2) * 64);
            loadB(BOFF + (uint32_t)((t + 2) % 3) * 16384, (t + 2) * 64);
            cp_commit();
        }
    }
    for (int tt = (NT >= 3 ? NT - 3 : 0); tt < NT; tt++)
        mbar_wait(mb(tt % 3), (uint32_t)((tt / 3) & 1));
    TC_FENCE_AFTER();

    {
        long long r = row0 + (wrp & 3) * 32 + lane;
        int cbase = (wrp >> 2) * 64;
#pragma unroll
        for (int cg = 0; cg < 2; cg++) {
            uint32_t regs[32];
            LDTM_X32(regs, tmem + cbase + cg * 32);
            TC_WAIT_LD();
            int c0 = col0 + cbase + cg * 32;
            if (OUTBF) {
#pragma unroll
                for (int i = 0; i < 32; i += 2) {
                    __nv_bfloat162 p;
                    p.x = __float2bfloat16(__uint_as_float(regs[i]) * alpha);
                    p.y = __float2bfloat16(__uint_as_float(regs[i + 1]) * alpha);
                    *(__nv_bfloat162*)(Cb + r * N + c0 + i) = p;
                }
            } else {
#pragma unroll
                for (int i = 0; i < 32; i += 2) {
                    float v0 = __uint_as_float(regs[i]) * alpha;
                    float v1 = __uint_as_float(regs[i + 1]) * alpha;
                    if (ADD) {
                        float2 a = *(const float2*)(AddP + r * N + c0 + i);
                        v0 += a.x; v1 += a.y;
                    }
                    *(float2*)(Cf + r * N + c0 + i) = make_float2(v0, v1);
                }
            }
        }
    }
    TC_FENCE_BEFORE();
    __syncthreads();
    if (tid == 0) { MBAR_INVAL(mb(0)); MBAR_INVAL(mb(1)); MBAR_INVAL(mb(2)); }
    __syncthreads();
    if (wrp == 0) TC_DEALLOC(tmem, 128);
#else
    const __nv_bfloat16* As[2] = { (const __nv_bfloat16*)(smraw + (T0 - sb0)),
                                   (const __nv_bfloat16*)(smraw + (T0 - sb0) + 16384) };
    const __nv_bfloat16* Bs[2] = { (const __nv_bfloat16*)(smraw + (T0 - sb0) + 32768),
                                   (const __nv_bfloat16*)(smraw + (T0 - sb0) + 49152) };
    int wm = wrp >> 2, wn = wrp & 3;

    float acc[4][4][4];
#pragma unroll
    for (int mt = 0; mt < 4; mt++)
#pragma unroll
        for (int nt = 0; nt < 4; nt++)
#pragma unroll
            for (int i = 0; i < 4; i++) acc[mt][nt][i] = 0.f;

    loadA(T0, 0); loadB(T0 + 32768, 0); cp_commit();
    for (int t = 0; t < NT; t++) {
        if (t + 1 < NT) {
            loadA(T0 + (uint32_t)((t + 1) & 1) * 16384, (t + 1) * 64);
            loadB(T0 + 32768 + (uint32_t)((t + 1) & 1) * 16384, (t + 1) * 64);
            cp_commit();
            cp_wait<1>();
        } else cp_wait<0>();
        __syncthreads();
        const __nv_bfloat16* as = As[t & 1];
        const __nv_bfloat16* bs = Bs[t & 1];
#pragma unroll
        for (int kk = 0; kk < 4; kk++) {
            unsigned af[4][4], bf[2][4];
#pragma unroll
            for (int mt = 0; mt < 4; mt++) {
                int r = wm * 64 + mt * 16 + (lane & 15);
                int chunk = ((kk * 2 + (lane >> 4)) ^ (r & 7));
                ldsm4(af[mt], smem_u32(as + r * 64 + chunk * 8));
            }
#pragma unroll
            for (int np = 0; np < 2; np++) {
                int nrow = wn * 32 + (2 * np + ((lane >> 4) & 1)) * 8 + (lane & 7);
                int chunk = ((kk * 2 + ((lane >> 3) & 1)) ^ (nrow & 7));
                ldsm4(bf[np], smem_u32(bs + nrow * 64 + chunk * 8));
            }
#pragma unroll
            for (int mt = 0; mt < 4; mt++)
#pragma unroll
                for (int nt = 0; nt < 4; nt++)
                    mma16816(acc[mt][nt], af[mt], bf[nt >> 1] + (nt & 1) * 2);
        }
        __syncthreads();
    }
#pragma unroll
    for (int mt = 0; mt < 4; mt++) {
#pragma unroll
        for (int nt = 0; nt < 4; nt++) {
            int r = row0 + wm * 64 + mt * 16 + (lane >> 2);
            int c = col0 + wn * 32 + nt * 8 + 2 * (lane & 3);
            float v0 = acc[mt][nt][0] * alpha, v1 = acc[mt][nt][1] * alpha;
            float v2 = acc[mt][nt][2] * alpha, v3 = acc[mt][nt][3] * alpha;
            if (OUTBF) {
                __nv_bfloat162 p0; p0.x = __float2bfloat16(v0); p0.y = __float2bfloat16(v1);
                __nv_bfloat162 p1; p1.x = __float2bfloat16(v2); p1.y = __float2bfloat16(v3);
                *(__nv_bfloat162*)(Cb + (long long)r * N + c) = p0;
                *(__nv_bfloat162*)(Cb + (long long)(r + 8) * N + c) = p1;
            } else {
                if (ADD) {
                    float2 a0 = *(const float2*)(AddP + (long long)r * N + c);
                    float2 a1 = *(const float2*)(AddP + (long long)(r + 8) * N + c);
                    v0 += a0.x; v1 += a0.y; v2 += a1.x; v3 += a1.y;
                }
                *(float2*)(Cf + (long long)r * N + c) = make_float2(v0, v1);
                *(float2*)(Cf + (long long)(r + 8) * N + c) = make_float2(v2, v3);
            }
        }
    }
#endif
}

// ---------------- flash attention: R8/R11 version (passing, unchanged) ----------------
__global__ __launch_bounds__(256) __cluster_dims__(1, 1, 1) void flash_kernel(
    const __nv_bfloat16* __restrict__ qb, const __nv_bfloat16* __restrict__ kvb,
    const __nv_bfloat16* __restrict__ vT, __nv_bfloat16* __restrict__ ccb) {
    int tid = threadIdx.x, lane = tid & 31, wrp = tid >> 5;
    int b = blockIdx.y >> 4, h = blockIdx.y & 15;
    long long qrow0 = (long long)b * SS + blockIdx.x * 128;

#if TCOK
    extern __shared__ char smraw[];
    uint32_t sb0 = smem_u32(smraw);
    uint32_t sbase = (sb0 + 1023u) & ~1023u;
    const uint32_t QOFF = sbase + 2048;
    const uint32_t K0 = QOFF + 16384;
    const uint32_t V0 = K0 + 16384;
    const uint32_t POFF = V0 + 16384;
    float* lsp = (float*)(smraw + (sbase - sb0) + 512);
    char* pgen = smraw + (POFF - sb0);

    if (wrp == 0) { TC_ALLOC(sbase, 128); TC_RELINQ(); }
    if (tid == 0) { MBAR_INIT(sbase + 8, 1); MBAR_INIT(sbase + 16, 1); }
    __syncthreads();
    uint32_t tmem = ld_shared_u32(sbase);
    const uint32_t mbS = sbase + 8, mbP = sbase + 16;
    const int S_OFF = 0, O_OFF = 64;

#pragma unroll
    for (int i = 0; i < 4; i++) {
        int idx = i * 256 + tid;
        int r = idx >> 3, ch = idx & 7;
        cp16(QOFF + r * 128 + ((ch ^ (r & 7)) << 4),
             qb + (qrow0 + r) * DD + h * 64 + ch * 8);
    }
    auto loadKV = [&](int buf, int kt) {
#pragma unroll
        for (int i = 0; i < 2; i++) {
            int idx = i * 256 + tid;
            int r = idx >> 3, ch = idx & 7;
            uint32_t sw = r * 128 + ((ch ^ (r & 7)) << 4);
            cp16(K0 + buf * 8192 + sw,
                 kvb + ((long long)b * SS + kt * 64 + r) * 128 + ch * 8);
            cp16(V0 + buf * 8192 + sw,
                 vT + ((long long)(b * HD + r)) * SS + kt * 64 + ch * 8);
        }
        cp_commit();
    };
    loadKV(0, 0);

    const uint32_t IDESC = 0x490u | (8u << 17) | (8u << 24);
    int my_half = wrp >> 2;
    int rrow = (wrp & 3) * 32 + lane;
    float ls = 0.f;

    for (int kt = 0; kt < SS / 64; kt++) {
        if (kt + 1 < SS / 64) { loadKV((kt + 1) & 1, kt + 1); cp_wait<1>(); }
        else cp_wait<0>();
        FENCE_PROXY();
        __syncthreads();
        uint32_t kbuf = K0 + (uint32_t)(kt & 1) * 8192;
        uint32_t vbuf = V0 + (uint32_t)(kt & 1) * 8192;

        if (wrp == 0 && elect_one()) {
            uint64_t qd = make_desc(QOFF);
            uint64_t kd = make_desc(kbuf);
#pragma unroll
            for (int kk = 0; kk < 4; kk++)
                tc_mma_f16_ss(tmem + S_OFF, qd + kk * 2, kd + kk * 2, IDESC, kk > 0);
            TC_COMMIT(mbS);
        }
        mbar_wait(mbS, (uint32_t)(kt & 1));
        TC_FENCE_AFTER();

        uint32_t sreg[32];
        LDTM_X32(sreg, tmem + S_OFF + my_half * 32);
        TC_WAIT_LD();
        float p[32];
#pragma unroll
        for (int i = 0; i < 32; i++) {
            p[i] = ex2(__uint_as_float(sreg[i]));
            ls += p[i];
        }
        uint32_t pw[16];
#pragma unroll
        for (int i = 0; i < 16; i++) pw[i] = pack_bf16(p[2 * i], p[2 * i + 1]);
#pragma unroll
        for (int j = 0; j < 4; j++) {
            int ch = my_half * 4 + j;
            *(uint4*)(pgen + rrow * 128 + ((ch ^ (rrow & 7)) << 4)) =
                make_uint4(pw[4 * j], pw[4 * j + 1], pw[4 * j + 2], pw[4 * j + 3]);
        }
        FENCE_PROXY();
        TC_FENCE_BEFORE();
        __syncthreads();

        if (wrp == 0 && elect_one()) {
            TC_FENCE_AFTER();
            uint64_t pd = make_desc(POFF);
            uint64_t vd = make_desc(vbuf);
#pragma unroll
            for (int kk = 0; kk < 4; kk++)
                tc_mma_f16_ss(tmem + O_OFF, pd + kk * 2, vd + kk * 2,
                              IDESC, (kt > 0) || (kk > 0));
            TC_COMMIT(mbP);
        }
        mbar_wait(mbP, (uint32_t)(kt & 1));
        TC_FENCE_AFTER();
    }

    lsp[my_half * 128 + rrow] = ls;
    __syncthreads();
    float inv = 1.f / (lsp[rrow] + lsp[128 + rrow]);

    uint32_t oreg[32];
    LDTM_X32(oreg, tmem + O_OFF + my_half * 32);
    TC_WAIT_LD();
    long long gr = qrow0 + rrow;
    int c0 = h * 64 + my_half * 32;
#pragma unroll
    for (int i = 0; i < 32; i += 2) {
        __nv_bfloat162 pv;
        pv.x = __float2bfloat16(__uint_as_float(oreg[i]) * inv);
        pv.y = __float2bfloat16(__uint_as_float(oreg[i + 1]) * inv);
        *(__nv_bfloat162*)(ccb + gr * DD + c0 + i) = pv;
    }
    TC_FENCE_BEFORE();
    __syncthreads();
    if (tid == 0) { MBAR_INVAL(mbS); MBAR_INVAL(mbP); }
    __syncthreads();
    if (wrp == 0) TC_DEALLOC(tmem, 128);
#else
    // ================= HMMA fallback (R6 version) =================
    __shared__ __nv_bfloat16 Qs[128 * 64];
    __shared__ __nv_bfloat16 Ks[2][64 * 64];
    __shared__ __nv_bfloat16 Vs[2][64 * 64];
    int w = wrp;

    auto loadKV = [&](int st, int kt) {
#pragma unroll
        for (int i = 0; i < 2; i++) {
            int idx = i * 2048 + tid * 8;
            int r = idx >> 6, c = idx & 63;
            int chunk = (c >> 3) ^ (r & 7);
            long long grow = (long long)b * SS + kt * 64 + r;
            cp16(smem_u32(&Ks[st][r * 64 + chunk * 8]), kvb + grow * 128 + c);
            cp16(smem_u32(&Vs[st][r * 64 + chunk * 8]), kvb + grow * 128 + 64 + c);
        }
        cp_commit();
    };

#pragma unroll
    for (int i = 0; i < 4; i++) {
        int idx = i * 2048 + tid * 8;
        int r = idx >> 6, c = idx & 63;
        int chunk = (c >> 3) ^ (r & 7);
        cp16(smem_u32(Qs + r * 64 + chunk * 8), qb + (qrow0 + r) * DD + h * 64 + c);
    }
    loadKV(0, 0);
    cp_wait<0>();
    __syncthreads();

    unsigned qa[4][4];
    {
        int r = w * 16 + (lane & 15);
#pragma unroll
        for (int kk = 0; kk < 4; kk++) {
            int chunk = ((kk * 2 + (lane >> 4)) ^ (r & 7));
            ldsm4(qa[kk], smem_u32(Qs + r * 64 + chunk * 8));
        }
    }

    float o[8][4];
#pragma unroll
    for (int nt = 0; nt < 8; nt++)
#pragma unroll
        for (int i = 0; i < 4; i++) o[nt][i] = 0.f;
    float ls0 = 0.f, ls1 = 0.f;

    for (int kt = 0; kt < SS / 64; kt++) {
        if (kt + 1 < SS / 64) { loadKV((kt + 1) & 1, kt + 1); cp_wait<1>(); }
        else cp_wait<0>();
        __syncthreads();
        const __nv_bfloat16* ks = Ks[kt & 1];
        const __nv_bfloat16* vs = Vs[kt & 1];

        float sf[8][4];
#pragma unroll
        for (int nt = 0; nt < 8; nt++)
#pragma unroll
            for (int i = 0; i < 4; i++) sf[nt][i] = 0.f;
#pragma unroll
        for (int kk = 0; kk < 4; kk++) {
#pragma unroll
            for (int np = 0; np < 4; np++) {
                unsigned bbf[4];
                int krow = (2 * np + ((lane >> 4) & 1)) * 8 + (lane & 7);
                int chunk = ((kk * 2 + ((lane >> 3) & 1)) ^ (krow & 7));
                ldsm4(bbf, smem_u32(ks + krow * 64 + chunk * 8));
                mma16816(sf[2 * np], qa[kk], bbf);
                mma16816(sf[2 * np + 1], qa[kk], bbf + 2);
            }
        }
#pragma unroll
        for (int nt = 0; nt < 8; nt++) {
            sf[nt][0] = ex2(sf[nt][0]);
            sf[nt][1] = ex2(sf[nt][1]);
            sf[nt][2] = ex2(sf[nt][2]);
            sf[nt][3] = ex2(sf[nt][3]);
            ls0 += sf[nt][0] + sf[nt][1];
            ls1 += sf[nt][2] + sf[nt][3];
        }
#pragma unroll
        for (int j = 0; j < 4; j++) {
            unsigned pa[4];
            pa[0] = pack_bf16(sf[2 * j][0], sf[2 * j][1]);
            pa[1] = pack_bf16(sf[2 * j][2], sf[2 * j][3]);
            pa[2] = pack_bf16(sf[2 * j + 1][0], sf[2 * j + 1][1]);
            pa[3] = pack_bf16(sf[2 * j + 1][2], sf[2 * j + 1][3]);
#pragma unroll
            for (int np = 0; np < 4; np++) {
                unsigned vv[4];
                int vrow = j * 16 + (lane & 7) + ((lane >> 3) & 1) * 8;
                int cgrp = 2 * np + ((lane >> 4) & 1);
                int chunk = (cgrp ^ (vrow & 7));
                ldsm4t(vv, smem_u32(vs + vrow * 64 + chunk * 8));
                mma16816(o[2 * np], pa, vv);
                mma16816(o[2 * np + 1], pa, vv + 2);
            }
        }
        __syncthreads();
    }

    ls0 += __shfl_xor_sync(0xFFFFFFFFu, ls0, 1);
    ls0 += __shfl_xor_sync(0xFFFFFFFFu, ls0, 2);
    ls1 += __shfl_xor_sync(0xFFFFFFFFu, ls1, 1);
    ls1 += __shfl_xor_sync(0xFFFFFFFFu, ls1, 2);
    float inv0 = 1.f / ls0, inv1 = 1.f / ls1;

    long long gr = qrow0 + w * 16 + (lane >> 2);
#pragma unroll
    for (int nt = 0; nt < 8; nt++) {
        int c = h * 64 + nt * 8 + 2 * (lane & 3);
        __nv_bfloat162 p0, p1;
        p0.x = __float2bfloat16(o[nt][0] * inv0);
        p0.y = __float2bfloat16(o[nt][1] * inv0);
        p1.x = __float2bfloat16(o[nt][2] * inv1);
        p1.y = __float2bfloat16(o[nt][3] * inv1);
        *(__nv_bfloat162*)(ccb + gr * DD + c) = p0;
        *(__nv_bfloat162*)(ccb + (gr + 8) * DD + c) = p1;
    }
#endif
}

// ---------------- logits + dispatch softmax (vectorized, phiT) ----------------
// grid ROWS, 128 threads. t: e = t&15, seg = t>>4 (8 segs x 128 d).
__global__ __launch_bounds__(128) void logits_kernel(
    const float* __restrict__ m, const float* __restrict__ phiT,
    float* __restrict__ logits, float* __restrict__ dispatch) {
    __shared__ float4 msv[DD / 4];
    __shared__ float part[8][NSLOT];
    __shared__ float lsm[NSLOT];
    long long row = blockIdx.x;
    int tid = threadIdx.x;
    const float4* mr = (const float4*)(m + row * DD);
    msv[tid] = mr[tid];
    msv[tid + 128] = mr[tid + 128];
    __syncthreads();
    int e = tid & 15, seg = tid >> 4;
    const float4* pe = (const float4*)(phiT + e * DD) + seg * 32;
    const float4* ms = msv + seg * 32;
    float acc = 0.f;
#pragma unroll
    for (int i = 0; i < 32; i++) {
        float4 mv = ms[i];
        float4 pv = pe[i];
        acc += mv.x * pv.x + mv.y * pv.y + mv.z * pv.z + mv.w * pv.w;
    }
    part[seg][e] = acc;
    __syncthreads();
    if (tid < NSLOT) {
        float l = 0.f;
#pragma unroll
        for (int s = 0; s < 8; s++) l += part[s][tid];
        logits[row * NSLOT + tid] = l;
        lsm[tid] = l;
    }
    __syncthreads();
    if (tid < NSLOT) {
        float mx = lsm[0];
        for (int j = 1; j < NSLOT; j++) mx = fmaxf(mx, lsm[j]);
        float s = 0.f;
        for (int j = 0; j < NSLOT; j++) s += expf(lsm[j] - mx);
        dispatch[row * NSLOT + tid] = expf(lsm[tid] - mx) / s;
    }
}

// ---------------- combine softmax over sequence axis ----------------
__global__ void combine_kernel(const float* __restrict__ logits, float* __restrict__ comb) {
    int b = blockIdx.x >> 4, e = blockIdx.x & 15;
    const float* base = logits + ((long long)b * SS) * NSLOT + e;
    float v[8];
    float mx = -1e30f;
#pragma unroll
    for (int i = 0; i < 8; i++) {
        int s = threadIdx.x + i * 256;
        v[i] = base[(long long)s * NSLOT];
        mx = fmaxf(mx, v[i]);
    }
    __shared__ float red[8];
#pragma unroll
    for (int o = 16; o; o >>= 1) mx = fmaxf(mx, __shfl_xor_sync(0xFFFFFFFFu, mx, o));
    int w = threadIdx.x >> 5;
    if ((threadIdx.x & 31) == 0) red[w] = mx;
    __syncthreads();
    if (threadIdx.x == 0) {
        float t = red[0];
        for (int i = 1; i < 8; i++) t = fmaxf(t, red[i]);
        red[0] = t;
    }
    __syncthreads();
    mx = red[0];
    __syncthreads();
    float s = 0.f;
#pragma unroll
    for (int i = 0; i < 8; i++) { v[i] = expf(v[i] - mx); s += v[i]; }
#pragma unroll
    for (int o = 16; o; o >>= 1) s += __shfl_xor_sync(0xFFFFFFFFu, s, o);
    if ((threadIdx.x & 31) == 0) red[w] = s;
    __syncthreads();
    if (threadIdx.x == 0) {
        float t = 0.f;
        for (int i = 0; i < 8; i++) t += red[i];
        red[0] = t;
    }
    __syncthreads();
    float inv = 1.0f / red[0];
    float* ob = comb + ((long long)b * SS) * NSLOT + e;
#pragma unroll
    for (int i = 0; i < 8; i++) {
        int sidx = threadIdx.x + i * 256;
        ob[(long long)sidx * NSLOT] = v[i] * inv;
    }
}

// ---------------- xs partials (float4 LDS for dispatch) + reduce ----------------
__global__ void xs_part_kernel(const float* __restrict__ dispatch, const float* __restrict__ m,
                               float* __restrict__ part) {
    int d = blockIdx.x * 256 + threadIdx.x;
    int b = blockIdx.y, seg = blockIdx.z;
    int s0 = seg * SCHUNK;
    __shared__ __align__(16) float ds[SCHUNK][NSLOT];
    for (int i = threadIdx.x; i < SCHUNK * NSLOT; i += 256)
        ds[i >> 4][i & 15] = dispatch[((long long)b * SS + s0) * NSLOT + i];
    __syncthreads();
    float acc[NSLOT];
#pragma unroll
    for (int e = 0; e < NSLOT; e++) acc[e] = 0.f;
    const float* mb = m + ((long long)b * SS + s0) * DD + d;
    for (int s = 0; s < SCHUNK; s++) {
        float mv = mb[(long long)s * DD];
        const float4* dr = (const float4*)ds[s];
#pragma unroll
        for (int q = 0; q < 4; q++) {
            float4 dv = dr[q];
            acc[q * 4 + 0] += dv.x * mv;
            acc[q * 4 + 1] += dv.y * mv;
            acc[q * 4 + 2] += dv.z * mv;
            acc[q * 4 + 3] += dv.w * mv;
        }
    }
#pragma unroll
    for (int e = 0; e < NSLOT; e++)
        part[(((long long)seg * BB + b) * NSLOT + e) * DD + d] = acc[e];
}

__global__ void xs_reduce_kernel(const float* __restrict__ part, float* __restrict__ xs) {
    int i = blockIdx.x * 256 + threadIdx.x;
    float a = 0.f;
#pragma unroll
    for (int seg = 0; seg < SSEG; seg++)
        a += part[(long long)seg * BB * NSLOT * DD + i];
    xs[i] = a;
}

// ---------------- expert FFN1: hidT[e][f][r] = gelu(xs @ w1 + b1) ----------------
// grid (EE, DFF/256), 256 threads, 1 f per thread. xs staged transposed [d][8].
__global__ __launch_bounds__(256) void ffn1_kernel(
    const float* __restrict__ xs, const float* __restrict__ w1,
    const float* __restrict__ b1, float* __restrict__ hidT) {
    int e = blockIdx.x;
    int f = blockIdx.y * 256 + threadIdx.x;
    __shared__ __align__(16) float xst[DD][8];
    for (int i = threadIdx.x; i < 8 * DD; i += 256) {
        int r = i >> 10, d = i & 1023;
        int b = r >> 1, slot = r & 1;
        xst[d][r] = xs[((long long)(b * NSLOT + e * 2 + slot)) * DD + d];
    }
    __syncthreads();
    float acc[8] = {0.f, 0.f, 0.f, 0.f, 0.f, 0.f, 0.f, 0.f};
    const float* w = w1 + (long long)e * DD * DFF + f;
    for (int d = 0; d < DD; d++) {
        float wv = w[(long long)d * DFF];
        float4 x0 = *(const float4*)&xst[d][0];
        float4 x1 = *(const float4*)&xst[d][4];
        acc[0] += x0.x * wv; acc[1] += x0.y * wv;
        acc[2] += x0.z * wv; acc[3] += x0.w * wv;
        acc[4] += x1.x * wv; acc[5] += x1.y * wv;
        acc[6] += x1.z * wv; acc[7] += x1.w * wv;
    }
    float bias = b1[e * DFF + f];
    float* hout = hidT + ((long long)e * DFF + f) * 8;
#pragma unroll
    for (int r = 0; r < 8; r++) {
        float vv = acc[r] + bias;
        hout[r] = 0.5f * vv * (1.0f + erff(vv * 0.70710678118654752f));
    }
}

// ---------------- expert FFN2 partials: ysp[fs][row][d] ----------------
// grid (EE, FSEG), 256 threads, 4 d per thread (float4).
__global__ __launch_bounds__(256) void ffn2_kernel(
    const float* __restrict__ hidT, const float* __restrict__ w2,
    float* __restrict__ ysp) {
    int e = blockIdx.x, fs = blockIdx.y;
    int f0 = fs * FCH;
    int tid = threadIdx.x;
    __shared__ __align__(16) float hs[FCH][8];
    for (int i = tid; i < FCH * 8; i += 256) {
        int f = i >> 3, r = i & 7;
        hs[f][r] = hidT[((long long)e * DFF + f0 + f) * 8 + r];
    }
    __syncthreads();
    float4 acc[8];
#pragma unroll
    for (int r = 0; r < 8; r++) acc[r] = make_float4(0.f, 0.f, 0.f, 0.f);
    const float4* w = (const float4*)(w2 + (long long)e * DFF * DD + (long long)f0 * DD) + tid;
    for (int f = 0; f < FCH; f++) {
        float4 wv = w[(long long)f * (DD / 4)];
        float4 h0 = *(const float4*)&hs[f][0];
        float4 h1 = *(const float4*)&hs[f][4];
        acc[0].x += wv.x * h0.x; acc[0].y += wv.y * h0.x; acc[0].z += wv.z * h0.x; acc[0].w += wv.w * h0.x;
        acc[1].x += wv.x * h0.y; acc[1].y += wv.y * h0.y; acc[1].z += wv.z * h0.y; acc[1].w += wv.w * h0.y;
        acc[2].x += wv.x * h0.z; acc[2].y += wv.y * h0.z; acc[2].z += wv.z * h0.z; acc[2].w += wv.w * h0.z;
        acc[3].x += wv.x * h0.w; acc[3].y += wv.y * h0.w; acc[3].z += wv.z * h0.w; acc[3].w += wv.w * h0.w;
        acc[4].x += wv.x * h1.x; acc[4].y += wv.y * h1.x; acc[4].z += wv.z * h1.x; acc[4].w += wv.w * h1.x;
        acc[5].x += wv.x * h1.y; acc[5].y += wv.y * h1.y; acc[5].z += wv.z * h1.y; acc[5].w += wv.w * h1.y;
        acc[6].x += wv.x * h1.z; acc[6].y += wv.y * h1.z; acc[6].z += wv.z * h1.z; acc[6].w += wv.w * h1.z;
        acc[7].x += wv.x * h1.w; acc[7].y += wv.y * h1.w; acc[7].z += wv.z * h1.w; acc[7].w += wv.w * h1.w;
    }
#pragma unroll
    for (int r = 0; r < 8; r++) {
        int b = r >> 1, slot = r & 1;
        int rowl = b * NSLOT + e * 2 + slot;
        *(float4*)(ysp + ((long long)fs * BB * NSLOT + rowl) * DD + tid * 4) = acc[r];
    }
}

// ---------------- ys reduce + bias ----------------
__global__ void ys_reduce_kernel(const float* __restrict__ ysp, const float* __restrict__ b2,
                                 float* __restrict__ ys) {
    int i = blockIdx.x * 256 + threadIdx.x;   // over BB*NSLOT*DD
    int row = i >> 10, d = i & 1023;
    int e = (row & 15) >> 1;
    float a = b2[e * DD + d];
#pragma unroll
    for (int fs = 0; fs < FSEG; fs++)
        a += ysp[(long long)fs * BB * NSLOT * DD + i];
    ys[i] = a;
}

// ---------------- final: out = m + combine @ ys (row per block, float4) ----------------
__global__ __launch_bounds__(256) void final_kernel(
    const float* __restrict__ m, const float* __restrict__ comb,
    const float* __restrict__ ys, float* __restrict__ out) {
    long long row = blockIdx.x;
    int b = (int)(row >> 11);
    int tid = threadIdx.x;
    __shared__ float cs[NSLOT];
    if (tid < NSLOT) cs[tid] = comb[row * NSLOT + tid];
    __syncthreads();
    float4 acc = *(const float4*)(m + row * DD + tid * 4);
    const float* yb = ys + (long long)b * NSLOT * DD + tid * 4;
#pragma unroll
    for (int j = 0; j < NSLOT; j++) {
        float4 yv = *(const float4*)(yb + (long long)j * DD);
        float c = cs[j];
        acc.x += c * yv.x; acc.y += c * yv.y;
        acc.z += c * yv.z; acc.w += c * yv.w;
    }
    *(float4*)(out + row * DD + tid * 4) = acc;
}

// ---------------- launch ----------------
extern "C" void kernel_launch(void* const* d_in, const int* in_sizes, int n_in,
                              void* d_out, int out_size) {
    const float* x        = (const float*)d_in[0];
    const float* wq       = (const float*)d_in[1];
    const float* wkv      = (const float*)d_in[2];
    const float* wo       = (const float*)d_in[3];
    const float* gm_attn  = (const float*)d_in[4];
    const float* gm_moe   = (const float*)d_in[5];
    const float* phi      = (const float*)d_in[6];
    const float* w1       = (const float*)d_in[7];
    const float* b1       = (const float*)d_in[8];
    const float* w2       = (const float*)d_in[9];
    const float* b2       = (const float*)d_in[10];
    float* out = (float*)d_out;

    float *h, *x1, *m, *lg, *dp, *cb, *xs, *xsp, *hidT, *ysp, *ys, *phiT;
    __nv_bfloat16 *hb, *qb, *kvb, *vt, *ccb, *wqT, *wkvT, *woT;
    cudaGetSymbolAddress((void**)&h,    g_h);
    cudaGetSymbolAddress((void**)&hb,   g_hb);
    cudaGetSymbolAddress((void**)&qb,   g_qb);
    cudaGetSymbolAddress((void**)&kvb,  g_kvb);
    cudaGetSymbolAddress((void**)&vt,   g_vT);
    cudaGetSymbolAddress((void**)&ccb,  g_ccb);
    cudaGetSymbolAddress((void**)&wqT,  g_wqT);
    cudaGetSymbolAddress((void**)&wkvT, g_wkvT);
    cudaGetSymbolAddress((void**)&woT,  g_woT);
    cudaGetSymbolAddress((void**)&phiT, g_phiT);
    cudaGetSymbolAddress((void**)&x1,   g_x1);
    cudaGetSymbolAddress((void**)&m,    g_m);
    cudaGetSymbolAddress((void**)&lg,   g_logits);
    cudaGetSymbolAddress((void**)&dp,   g_dispatch);
    cudaGetSymbolAddress((void**)&cb,   g_combine);
    cudaGetSymbolAddress((void**)&xs,   g_xs);
    cudaGetSymbolAddress((void**)&xsp,  g_xs_part);
    cudaGetSymbolAddress((void**)&hidT, g_hidT);
    cudaGetSymbolAddress((void**)&ysp,  g_ys_part);
    cudaGetSymbolAddress((void**)&ys,   g_ys);

    const int G_SMEM = 1024 + 1024 + 6 * 16384; // 100352
    cudaFuncSetAttribute(gemm_kernel<false, true>,
                         cudaFuncAttributeMaxDynamicSharedMemorySize, G_SMEM);
    cudaFuncSetAttribute(gemm_kernel<true, false>,
                         cudaFuncAttributeMaxDynamicSharedMemorySize, G_SMEM);
    const int F_SMEM = 1024 + 2048 + 4 * 16384;
    cudaFuncSetAttribute(flash_kernel,
                         cudaFuncAttributeMaxDynamicSharedMemorySize, F_SMEM);

    // 0) ln: h = LN(x), hb
    ln_kernel<<<ROWS, 256>>>(x, gm_attn, h, hb);
    // 1) wq transpose
    transpose_cvt_kernel<<<dim3(32, 32), dim3(32, 8)>>>(wq, wqT, DD, DD);
    // 2) wkv transpose
    transpose_cvt_kernel<<<dim3(4, 32), dim3(32, 8)>>>(wkv, wkvT, DD, 128);
    // 3) gemm_q (ncu capture slot)
    gemm_kernel<false, true><<<dim3(8, 64), 256, G_SMEM>>>(
        hb, wqT, nullptr, nullptr, qb, ROWS, DD, DD, 0.125f * 1.4426950408889634f);
    // 4) wo transpose
    transpose_cvt_kernel<<<dim3(32, 32), dim3(32, 8)>>>(wo, woT, DD, DD);
    // 5) phi transpose
    phiT_kernel<<<DD / 256, 256>>>(phi, phiT);
    // 6) gemm_kv
    gemm_kernel<false, true><<<dim3(1, 64), 256, G_SMEM>>>(
        hb, wkvT, nullptr, nullptr, kvb, ROWS, 128, DD, 1.0f);
    // 7) vT
    vT_kernel<<<dim3(SS / 32, HD / 32, BB), dim3(32, 8)>>>(kvb, vt);
    // 8) flash
    flash_kernel<<<dim3(SS / 128, BB * HH), 256, F_SMEM>>>(qb, kvb, vt, ccb);
    // 9) x1 = concat @ wo + h
    gemm_kernel<true, false><<<dim3(8, 64), 256, G_SMEM>>>(
        ccb, woT, h, x1, nullptr, ROWS, DD, DD, 1.0f);
    // 10) m = LN(x1)
    ln_kernel<<<ROWS, 256>>>(x1, gm_moe, m, nullptr);
    // 11) logits + dispatch (vectorized)
    logits_kernel<<<ROWS, 128>>>(m, phiT, lg, dp);
    // 12) combine
    combine_kernel<<<BB * NSLOT, 256>>>(lg, cb);
    // 13) xs partials
    xs_part_kernel<<<dim3(DD / 256, BB, SSEG), 256>>>(dp, m, xsp);
    // 14) xs reduce
    xs_reduce_kernel<<<(BB * NSLOT * DD) / 256, 256>>>(xsp, xs);
    // 15) ffn1 -> hidT
    ffn1_kernel<<<dim3(EE, DFF / 256), 256>>>(xs, w1, b1, hidT);
    // 16) ffn2 partials
    ffn2_kernel<<<dim3(EE, FSEG), 256>>>(hidT, w2, ysp);
    // 17) ys reduce + bias
    ys_reduce_kernel<<<(BB * NSLOT * DD) / 256, 256>>>(ysp, b2, ys);
    // 18) final (row per block, float4)
    final_kernel<<<ROWS, 256>>>(m, cb, ys, out);
}

// round 14
// speedup vs baseline: 3.4924x; 1.2070x over previous
#include <cuda_runtime.h>
#include <cuda_bf16.h>
#include <math.h>
#include <stdint.h>

// Problem constants
#define BB 4
#define SS 2048
#define DD 1024
#define HH 16
#define HD 64
#define EE 8
#define DFF 4096
#define NSLOT 16        // E*SLOTS
#define ROWS (BB*SS)    // 8192
#define SSEG 8
#define SCHUNK (SS/SSEG)  // 256
#define FSEG 32
#define FCH (DFF/FSEG)    // 128
#define FS1 4
#define DS1 4
#define F1CH (DFF/FS1)    // 1024
#define D1CH (DD/DS1)     // 256

// tcgen05 availability: only in arch-specific (sm_103a/sm_100a-family) device pass
#if defined(__CUDA_ARCH__) && (defined(__CUDA_ARCH_FEAT_SM103_ALL) || defined(__CUDA_ARCH_FEAT_SM100_ALL) || defined(__CUDA_ARCH_SPECIFIC__) || defined(__CUDA_ARCH_FAMILY_SPECIFIC__))
#define TCOK 1
#else
#define TCOK 0
#endif

// ---------------- scratch (static __device__ globals; no allocation) ----------------
__device__ float g_h[ROWS * DD];
__device__ __nv_bfloat16 g_hb[ROWS * DD];
__device__ __nv_bfloat16 g_qb[ROWS * DD];
__device__ __nv_bfloat16 g_kvb[ROWS * 128];
__device__ __nv_bfloat16 g_vT[BB * HD * SS];   // [b][dim][seq]
__device__ __nv_bfloat16 g_ccb[ROWS * DD];
__device__ __nv_bfloat16 g_wqT[DD * DD];    // [N=D][K=D]
__device__ __nv_bfloat16 g_wkvT[128 * DD];  // [N=128][K=D]
__device__ __nv_bfloat16 g_woT[DD * DD];    // [N=D][K=D]
__device__ float g_phiT[NSLOT * DD];        // [16][1024]
__device__ float g_x1[ROWS * DD];
__device__ float g_m[ROWS * DD];
__device__ float g_logits[ROWS * NSLOT];
__device__ float g_dispatch[ROWS * NSLOT];
__device__ float g_combine[ROWS * NSLOT];
__device__ float g_xs[BB * NSLOT * DD];
__device__ float g_xs_part[SSEG * BB * NSLOT * DD];
__device__ float g_h1p[DS1 * 8 * EE * DFF]; // [ds][r][e][f]
__device__ float g_hidT[EE * DFF * 8];      // [e][f][8 rows]
__device__ float g_ys_part[FSEG * BB * NSLOT * DD];
__device__ float g_ys[BB * NSLOT * DD];

// ---------------- asm helpers ----------------
__device__ __forceinline__ unsigned smem_u32(const void* p) {
    return (unsigned)__cvta_generic_to_shared(p);
}
__device__ __forceinline__ void mma16816(float* d, const unsigned* a, const unsigned* b) {
    asm volatile("mma.sync.aligned.m16n8k16.row.col.f32.bf16.bf16.f32 "
                 "{%0,%1,%2,%3}, {%4,%5,%6,%7}, {%8,%9}, {%0,%1,%2,%3};\n"
                 : "+f"(d[0]), "+f"(d[1]), "+f"(d[2]), "+f"(d[3])
                 : "r"(a[0]), "r"(a[1]), "r"(a[2]), "r"(a[3]), "r"(b[0]), "r"(b[1]));
}
__device__ __forceinline__ void ldsm4(unsigned* r, unsigned a) {
    asm volatile("ldmatrix.sync.aligned.m8n8.x4.shared.b16 {%0,%1,%2,%3}, [%4];\n"
                 : "=r"(r[0]), "=r"(r[1]), "=r"(r[2]), "=r"(r[3]) : "r"(a));
}
__device__ __forceinline__ void ldsm4t(unsigned* r, unsigned a) {
    asm volatile("ldmatrix.sync.aligned.m8n8.x4.trans.shared.b16 {%0,%1,%2,%3}, [%4];\n"
                 : "=r"(r[0]), "=r"(r[1]), "=r"(r[2]), "=r"(r[3]) : "r"(a));
}
__device__ __forceinline__ unsigned pack_bf16(float a, float b) {
    __nv_bfloat162 t;
    t.x = __float2bfloat16(a);
    t.y = __float2bfloat16(b);
    return *reinterpret_cast<unsigned*>(&t);
}
__device__ __forceinline__ float ex2(float x) {
    float y;
    asm("ex2.approx.f32 %0, %1;" : "=f"(y) : "f"(x));
    return y;
}
__device__ __forceinline__ void cp16(unsigned dst, const void* src) {
    asm volatile("cp.async.cg.shared.global [%0], [%1], 16;\n" :: "r"(dst), "l"(src));
}
__device__ __forceinline__ void cp_commit() {
    asm volatile("cp.async.commit_group;\n");
}
template<int N>
__device__ __forceinline__ void cp_wait() {
    asm volatile("cp.async.wait_group %0;\n" :: "n"(N));
}

#if TCOK
// ---------------- tcgen05 helpers (arch-specific pass only) ----------------
__device__ __forceinline__ uint32_t elect_one() {
    uint32_t pred;
    asm volatile("{\n\t.reg .pred p;\n\telect.sync _|p, 0xFFFFFFFF;\n\t"
                 "selp.b32 %0, 1, 0, p;\n\t}" : "=r"(pred));
    return pred;
}
#define TC_ALLOC(smem_addr, ncols) \
    asm volatile("tcgen05.alloc.cta_group::1.sync.aligned.shared::cta.b32 [%0], %1;" \
                 :: "r"((uint32_t)(smem_addr)), "r"((uint32_t)(ncols)) : "memory")
#define TC_RELINQ() \
    asm volatile("tcgen05.relinquish_alloc_permit.cta_group::1.sync.aligned;")
#define TC_DEALLOC(tmem, ncols) \
    asm volatile("tcgen05.dealloc.cta_group::1.sync.aligned.b32 %0, %1;" \
                 :: "r"(tmem), "r"((uint32_t)(ncols)))
#define TC_COMMIT(mbar) \
    asm volatile("tcgen05.commit.cta_group::1.mbarrier::arrive::one.shared::cluster.b64 [%0];" \
                 :: "r"((uint32_t)(mbar)) : "memory")
#define TC_FENCE_AFTER()  asm volatile("tcgen05.fence::after_thread_sync;" ::: "memory")
#define TC_FENCE_BEFORE() asm volatile("tcgen05.fence::before_thread_sync;" ::: "memory")
#define TC_WAIT_LD()      asm volatile("tcgen05.wait::ld.sync.aligned;" ::: "memory")
#define MBAR_INIT(mbar, cnt) \
    asm volatile("mbarrier.init.shared.b64 [%0], %1;" \
                 :: "r"((uint32_t)(mbar)), "r"((uint32_t)(cnt)) : "memory")
#define MBAR_INVAL(mbar) \
    asm volatile("mbarrier.inval.shared.b64 [%0];" :: "r"((uint32_t)(mbar)) : "memory")
#define FENCE_PROXY() asm volatile("fence.proxy.async.shared::cta;" ::: "memory")

__device__ __forceinline__ void mbar_wait(uint32_t mbar, uint32_t parity) {
    uint32_t done;
    asm volatile("{\n\t.reg .pred p;\n\t"
                 "mbarrier.try_wait.parity.acquire.cta.shared::cta.b64 p, [%1], %2;\n\t"
                 "selp.b32 %0, 1, 0, p;\n\t}"
                 : "=r"(done) : "r"(mbar), "r"(parity) : "memory");
    if (!done) {
        asm volatile("{\n\t.reg .pred P1;\n\t"
                     "WL_%=:\n\t"
                     "mbarrier.try_wait.parity.acquire.cta.shared::cta.b64 P1, [%0], %1, 0x989680;\n\t"
                     "@P1 bra.uni WD_%=;\n\t"
                     "bra.uni WL_%=;\n\t"
                     "WD_%=:\n\t}"
                     :: "r"(mbar), "r"(parity) : "memory");
    }
}
__device__ __forceinline__ void tc_mma_f16_ss(uint32_t d, uint64_t ad, uint64_t bd,
                                              uint32_t idesc, bool en) {
    uint32_t e = en ? 1u : 0u, z = 0u;
    asm volatile("{\n\t.reg .pred p;\n\tsetp.ne.u32 p, %5, 0;\n\t"
                 "tcgen05.mma.cta_group::1.kind::f16 [%0], %1, %2, %3, {%4,%4,%4,%4}, p;\n\t}"
                 :: "r"(d), "l"(ad), "l"(bd), "r"(idesc), "r"(z), "r"(e) : "memory");
}
__device__ __forceinline__ uint32_t ld_shared_u32(uint32_t addr) {
    uint32_t v;
    asm volatile("ld.shared.b32 %0, [%1];" : "=r"(v) : "r"(addr));
    return v;
}
// SW128 smem descriptor, K-major: layout 2, version 1, SBO=64, LBO=1
__device__ __forceinline__ uint64_t make_desc(uint32_t addr) {
    const uint64_t base = (uint64_t(2) << 61) | (uint64_t(1) << 46)
                        | (uint64_t(64) << 32) | (uint64_t(1) << 16);
    return base | ((uint64_t)(addr >> 4) & 0x3FFF);
}
#define LDTM_X32(r, addr) \
    asm volatile("tcgen05.ld.sync.aligned.32x32b.x32.b32 " \
        "{%0,%1,%2,%3,%4,%5,%6,%7,%8,%9,%10,%11,%12,%13,%14,%15," \
        "%16,%17,%18,%19,%20,%21,%22,%23,%24,%25,%26,%27,%28,%29,%30,%31}, [%32];" \
        : "=r"((r)[0]),"=r"((r)[1]),"=r"((r)[2]),"=r"((r)[3]), \
          "=r"((r)[4]),"=r"((r)[5]),"=r"((r)[6]),"=r"((r)[7]), \
          "=r"((r)[8]),"=r"((r)[9]),"=r"((r)[10]),"=r"((r)[11]), \
          "=r"((r)[12]),"=r"((r)[13]),"=r"((r)[14]),"=r"((r)[15]), \
          "=r"((r)[16]),"=r"((r)[17]),"=r"((r)[18]),"=r"((r)[19]), \
          "=r"((r)[20]),"=r"((r)[21]),"=r"((r)[22]),"=r"((r)[23]), \
          "=r"((r)[24]),"=r"((r)[25]),"=r"((r)[26]),"=r"((r)[27]), \
          "=r"((r)[28]),"=r"((r)[29]),"=r"((r)[30]),"=r"((r)[31]) \
        : "r"(addr))
#endif // TCOK

// ---------------- layernorm ----------------
__global__ void ln_kernel(const float* __restrict__ x, const float* __restrict__ gamma,
                          float* __restrict__ out, __nv_bfloat16* __restrict__ ob) {
    long long row = blockIdx.x;
    const float* p = x + row * DD;
    float v[4];
    float s = 0.f, sq = 0.f;
#pragma unroll
    for (int i = 0; i < 4; i++) {
        v[i] = p[threadIdx.x + i * 256];
        s += v[i];
        sq += v[i] * v[i];
    }
    __shared__ float rs[8], rq[8];
#pragma unroll
    for (int o = 16; o; o >>= 1) {
        s  += __shfl_xor_sync(0xFFFFFFFFu, s, o);
        sq += __shfl_xor_sync(0xFFFFFFFFu, sq, o);
    }
    int w = threadIdx.x >> 5;
    if ((threadIdx.x & 31) == 0) { rs[w] = s; rq[w] = sq; }
    __syncthreads();
    if (threadIdx.x == 0) {
        float ts = 0.f, tq = 0.f;
        for (int i = 0; i < 8; i++) { ts += rs[i]; tq += rq[i]; }
        rs[0] = ts; rq[0] = tq;
    }
    __syncthreads();
    float mean = rs[0] * (1.f / (float)DD);
    float var  = rq[0] * (1.f / (float)DD) - mean * mean;
    float rstd = rsqrtf(var + 1e-5f);
    float* o = out + row * DD;
#pragma unroll
    for (int i = 0; i < 4; i++) {
        int d = threadIdx.x + i * 256;
        float val = gamma[d] * (v[i] - mean) * rstd;
        o[d] = val;
        if (ob) ob[row * DD + d] = __float2bfloat16(val);
    }
}

// ---------------- weight transpose + convert ----------------
__global__ void transpose_cvt_kernel(const float* __restrict__ in,
                                     __nv_bfloat16* __restrict__ out, int R, int C) {
    __shared__ float t[32][33];
    int c0 = blockIdx.x * 32, r0 = blockIdx.y * 32;
    for (int i = threadIdx.y; i < 32; i += 8)
        t[i][threadIdx.x] = in[(long long)(r0 + i) * C + c0 + threadIdx.x];
    __syncthreads();
    for (int i = threadIdx.y; i < 32; i += 8)
        out[(long long)(c0 + i) * R + r0 + threadIdx.x] = __float2bfloat16(t[threadIdx.x][i]);
}

// ---------------- phi transpose ----------------
__global__ void phiT_kernel(const float* __restrict__ phi, float* __restrict__ phiT) {
    int d = blockIdx.x * 256 + threadIdx.x;
#pragma unroll
    for (int e = 0; e < NSLOT; e++)
        phiT[e * DD + d] = phi[d * NSLOT + e];
}

// ---------------- v transpose ----------------
__global__ void vT_kernel(const __nv_bfloat16* __restrict__ kvb,
                          __nv_bfloat16* __restrict__ vT) {
    __shared__ __nv_bfloat16 t[32][33];
    int s0 = blockIdx.x * 32, d0 = blockIdx.y * 32, b = blockIdx.z;
    for (int i = threadIdx.y; i < 32; i += 8)
        t[i][threadIdx.x] = kvb[((long long)(b * SS + s0 + i)) * 128 + 64 + d0 + threadIdx.x];
    __syncthreads();
    for (int i = threadIdx.y; i < 32; i += 8)
        vT[((long long)(b * HD + d0 + i)) * SS + s0 + threadIdx.x] = t[threadIdx.x][i];
}

// ---------------- unified bf16 GEMM (R11 version, passing) ----------------
template<bool ADD, bool OUTBF>
__global__ __launch_bounds__(256) __cluster_dims__(1, 1, 1) void gemm_kernel(
    const __nv_bfloat16* __restrict__ A, const __nv_bfloat16* __restrict__ BT,
    const float* __restrict__ AddP, float* __restrict__ Cf,
    __nv_bfloat16* __restrict__ Cb, int M, int N, int K, float alpha) {
    extern __shared__ char smraw[];
    uint32_t sb0 = smem_u32(smraw);
    uint32_t sbase = (sb0 + 1023u) & ~1023u;
    int tid = threadIdx.x, lane = tid & 31, wrp = tid >> 5;
    int row0 = blockIdx.y * 128, col0 = blockIdx.x * 128;
    const uint32_t T0 = sbase + 1024;

    auto loadA = [&](uint32_t off, int k0) {
#pragma unroll
        for (int i = 0; i < 4; i++) {
            int idx = i * 256 + tid;
            int r = idx >> 3, ch = idx & 7;
            cp16(off + r * 128 + ((ch ^ (r & 7)) << 4),
                 A + (long long)(row0 + r) * K + k0 + ch * 8);
        }
    };
    auto loadB = [&](uint32_t off, int k0) {
#pragma unroll
        for (int i = 0; i < 4; i++) {
            int idx = i * 256 + tid;
            int r = idx >> 3, ch = idx & 7;
            cp16(off + r * 128 + ((ch ^ (r & 7)) << 4),
                 BT + (long long)(col0 + r) * K + k0 + ch * 8);
        }
    };
    int NT = K / 64;

#if TCOK
    const uint32_t BOFF = T0 + 3 * 16384;
    if (wrp == 0) { TC_ALLOC(sbase, 128); TC_RELINQ(); }
    if (tid == 0) {
        MBAR_INIT(sbase + 8, 1);
        MBAR_INIT(sbase + 16, 1);
        MBAR_INIT(sbase + 24, 1);
    }
    __syncthreads();
    uint32_t tmem = ld_shared_u32(sbase);
    const uint32_t IDESC = 0x490u | (16u << 17) | (8u << 24);
    auto mb = [&](int i) -> uint32_t { return sbase + 8 + (uint32_t)i * 8; };

    loadA(T0, 0); loadB(BOFF, 0); cp_commit();
    if (NT > 1) { loadA(T0 + 16384, 64); loadB(BOFF + 16384, 64); cp_commit(); }

    for (int t = 0; t < NT; t++) {
        uint32_t sA = T0 + (uint32_t)(t % 3) * 16384;
        uint32_t sB = BOFF + (uint32_t)(t % 3) * 16384;
        if (t + 1 < NT) cp_wait<1>();
        else cp_wait<0>();
        FENCE_PROXY();
        __syncthreads();
        if (wrp == 0 && elect_one()) {
            uint64_t ad = make_desc(sA);
            uint64_t bd = make_desc(sB);
#pragma unroll
            for (int kk = 0; kk < 4; kk++)
                tc_mma_f16_ss(tmem, ad + kk * 2, bd + kk * 2, IDESC, (t > 0) || (kk > 0));
            TC_COMMIT(mb(t % 3));
        }
        if (t + 2 < NT) {
            if (t >= 1) mbar_wait(mb((t - 1) % 3), (uint32_t)(((t - 1) / 3) & 1));
            loadA(T0 + (uint32_t)((t + 2) % 3) * 16384, (t + 2) * 64);
            loadB(BOFF + (uint32_t)((t + 2) % 3) * 16384, (t + 2) * 64);
            cp_commit();
        }
    }
    for (int tt = (NT >= 3 ? NT - 3 : 0); tt < NT; tt++)
        mbar_wait(mb(tt % 3), (uint32_t)((tt / 3) & 1));
    TC_FENCE_AFTER();

    {
        long long r = row0 + (wrp & 3) * 32 + lane;
        int cbase = (wrp >> 2) * 64;
#pragma unroll
        for (int cg = 0; cg < 2; cg++) {
            uint32_t regs[32];
            LDTM_X32(regs, tmem + cbase + cg * 32);
            TC_WAIT_LD();
            int c0 = col0 + cbase + cg * 32;
            if (OUTBF) {
#pragma unroll
                for (int i = 0; i < 32; i += 2) {
                    __nv_bfloat162 p;
                    p.x = __float2bfloat16(__uint_as_float(regs[i]) * alpha);
                    p.y = __float2bfloat16(__uint_as_float(regs[i + 1]) * alpha);
                    *(__nv_bfloat162*)(Cb + r * N + c0 + i) = p;
                }
            } else {
#pragma unroll
                for (int i = 0; i < 32; i += 2) {
                    float v0 = __uint_as_float(regs[i]) * alpha;
                    float v1 = __uint_as_float(regs[i + 1]) * alpha;
                    if (ADD) {
                        float2 a = *(const float2*)(AddP + r * N + c0 + i);
                        v0 += a.x; v1 += a.y;
                    }
                    *(float2*)(Cf + r * N + c0 + i) = make_float2(v0, v1);
                }
            }
        }
    }
    TC_FENCE_BEFORE();
    __syncthreads();
    if (tid == 0) { MBAR_INVAL(mb(0)); MBAR_INVAL(mb(1)); MBAR_INVAL(mb(2)); }
    __syncthreads();
    if (wrp == 0) TC_DEALLOC(tmem, 128);
#else
    const __nv_bfloat16* As[2] = { (const __nv_bfloat16*)(smraw + (T0 - sb0)),
                                   (const __nv_bfloat16*)(smraw + (T0 - sb0) + 16384) };
    const __nv_bfloat16* Bs[2] = { (const __nv_bfloat16*)(smraw + (T0 - sb0) + 32768),
                                   (const __nv_bfloat16*)(smraw + (T0 - sb0) + 49152) };
    int wm = wrp >> 2, wn = wrp & 3;

    float acc[4][4][4];
#pragma unroll
    for (int mt = 0; mt < 4; mt++)
#pragma unroll
        for (int nt = 0; nt < 4; nt++)
#pragma unroll
            for (int i = 0; i < 4; i++) acc[mt][nt][i] = 0.f;

    loadA(T0, 0); loadB(T0 + 32768, 0); cp_commit();
    for (int t = 0; t < NT; t++) {
        if (t + 1 < NT) {
            loadA(T0 + (uint32_t)((t + 1) & 1) * 16384, (t + 1) * 64);
            loadB(T0 + 32768 + (uint32_t)((t + 1) & 1) * 16384, (t + 1) * 64);
            cp_commit();
            cp_wait<1>();
        } else cp_wait<0>();
        __syncthreads();
        const __nv_bfloat16* as = As[t & 1];
        const __nv_bfloat16* bs = Bs[t & 1];
#pragma unroll
        for (int kk = 0; kk < 4; kk++) {
            unsigned af[4][4], bf[2][4];
#pragma unroll
            for (int mt = 0; mt < 4; mt++) {
                int r = wm * 64 + mt * 16 + (lane & 15);
                int chunk = ((kk * 2 + (lane >> 4)) ^ (r & 7));
                ldsm4(af[mt], smem_u32(as + r * 64 + chunk * 8));
            }
#pragma unroll
            for (int np = 0; np < 2; np++) {
                int nrow = wn * 32 + (2 * np + ((lane >> 4) & 1)) * 8 + (lane & 7);
                int chunk = ((kk * 2 + ((lane >> 3) & 1)) ^ (nrow & 7));
                ldsm4(bf[np], smem_u32(bs + nrow * 64 + chunk * 8));
            }
#pragma unroll
            for (int mt = 0; mt < 4; mt++)
#pragma unroll
                for (int nt = 0; nt < 4; nt++)
                    mma16816(acc[mt][nt], af[mt], bf[nt >> 1] + (nt & 1) * 2);
        }
        __syncthreads();
    }
#pragma unroll
    for (int mt = 0; mt < 4; mt++) {
#pragma unroll
        for (int nt = 0; nt < 4; nt++) {
            int r = row0 + wm * 64 + mt * 16 + (lane >> 2);
            int c = col0 + wn * 32 + nt * 8 + 2 * (lane & 3);
            float v0 = acc[mt][nt][0] * alpha, v1 = acc[mt][nt][1] * alpha;
            float v2 = acc[mt][nt][2] * alpha, v3 = acc[mt][nt][3] * alpha;
            if (OUTBF) {
                __nv_bfloat162 p0; p0.x = __float2bfloat16(v0); p0.y = __float2bfloat16(v1);
                __nv_bfloat162 p1; p1.x = __float2bfloat16(v2); p1.y = __float2bfloat16(v3);
                *(__nv_bfloat162*)(Cb + (long long)r * N + c) = p0;
                *(__nv_bfloat162*)(Cb + (long long)(r + 8) * N + c) = p1;
            } else {
                if (ADD) {
                    float2 a0 = *(const float2*)(AddP + (long long)r * N + c);
                    float2 a1 = *(const float2*)(AddP + (long long)(r + 8) * N + c);
                    v0 += a0.x; v1 += a0.y; v2 += a1.x; v3 += a1.y;
                }
                *(float2*)(Cf + (long long)r * N + c) = make_float2(v0, v1);
                *(float2*)(Cf + (long long)(r + 8) * N + c) = make_float2(v2, v3);
            }
        }
    }
#endif
}

// ---------------- flash attention: R8/R11 version (passing, unchanged) ----------------
__global__ __launch_bounds__(256) __cluster_dims__(1, 1, 1) void flash_kernel(
    const __nv_bfloat16* __restrict__ qb, const __nv_bfloat16* __restrict__ kvb,
    const __nv_bfloat16* __restrict__ vT, __nv_bfloat16* __restrict__ ccb) {
    int tid = threadIdx.x, lane = tid & 31, wrp = tid >> 5;
    int b = blockIdx.y >> 4, h = blockIdx.y & 15;
    long long qrow0 = (long long)b * SS + blockIdx.x * 128;

#if TCOK
    extern __shared__ char smraw[];
    uint32_t sb0 = smem_u32(smraw);
    uint32_t sbase = (sb0 + 1023u) & ~1023u;
    const uint32_t QOFF = sbase + 2048;
    const uint32_t K0 = QOFF + 16384;
    const uint32_t V0 = K0 + 16384;
    const uint32_t POFF = V0 + 16384;
    float* lsp = (float*)(smraw + (sbase - sb0) + 512);
    char* pgen = smraw + (POFF - sb0);

    if (wrp == 0) { TC_ALLOC(sbase, 128); TC_RELINQ(); }
    if (tid == 0) { MBAR_INIT(sbase + 8, 1); MBAR_INIT(sbase + 16, 1); }
    __syncthreads();
    uint32_t tmem = ld_shared_u32(sbase);
    const uint32_t mbS = sbase + 8, mbP = sbase + 16;
    const int S_OFF = 0, O_OFF = 64;

#pragma unroll
    for (int i = 0; i < 4; i++) {
        int idx = i * 256 + tid;
        int r = idx >> 3, ch = idx & 7;
        cp16(QOFF + r * 128 + ((ch ^ (r & 7)) << 4),
             qb + (qrow0 + r) * DD + h * 64 + ch * 8);
    }
    auto loadKV = [&](int buf, int kt) {
#pragma unroll
        for (int i = 0; i < 2; i++) {
            int idx = i * 256 + tid;
            int r = idx >> 3, ch = idx & 7;
            uint32_t sw = r * 128 + ((ch ^ (r & 7)) << 4);
            cp16(K0 + buf * 8192 + sw,
                 kvb + ((long long)b * SS + kt * 64 + r) * 128 + ch * 8);
            cp16(V0 + buf * 8192 + sw,
                 vT + ((long long)(b * HD + r)) * SS + kt * 64 + ch * 8);
        }
        cp_commit();
    };
    loadKV(0, 0);

    const uint32_t IDESC = 0x490u | (8u << 17) | (8u << 24);
    int my_half = wrp >> 2;
    int rrow = (wrp & 3) * 32 + lane;
    float ls = 0.f;

    for (int kt = 0; kt < SS / 64; kt++) {
        if (kt + 1 < SS / 64) { loadKV((kt + 1) & 1, kt + 1); cp_wait<1>(); }
        else cp_wait<0>();
        FENCE_PROXY();
        __syncthreads();
        uint32_t kbuf = K0 + (uint32_t)(kt & 1) * 8192;
        uint32_t vbuf = V0 + (uint32_t)(kt & 1) * 8192;

        if (wrp == 0 && elect_one()) {
            uint64_t qd = make_desc(QOFF);
            uint64_t kd = make_desc(kbuf);
#pragma unroll
            for (int kk = 0; kk < 4; kk++)
                tc_mma_f16_ss(tmem + S_OFF, qd + kk * 2, kd + kk * 2, IDESC, kk > 0);
            TC_COMMIT(mbS);
        }
        mbar_wait(mbS, (uint32_t)(kt & 1));
        TC_FENCE_AFTER();

        uint32_t sreg[32];
        LDTM_X32(sreg, tmem + S_OFF + my_half * 32);
        TC_WAIT_LD();
        float p[32];
#pragma unroll
        for (int i = 0; i < 32; i++) {
            p[i] = ex2(__uint_as_float(sreg[i]));
            ls += p[i];
        }
        uint32_t pw[16];
#pragma unroll
        for (int i = 0; i < 16; i++) pw[i] = pack_bf16(p[2 * i], p[2 * i + 1]);
#pragma unroll
        for (int j = 0; j < 4; j++) {
            int ch = my_half * 4 + j;
            *(uint4*)(pgen + rrow * 128 + ((ch ^ (rrow & 7)) << 4)) =
                make_uint4(pw[4 * j], pw[4 * j + 1], pw[4 * j + 2], pw[4 * j + 3]);
        }
        FENCE_PROXY();
        TC_FENCE_BEFORE();
        __syncthreads();

        if (wrp == 0 && elect_one()) {
            TC_FENCE_AFTER();
            uint64_t pd = make_desc(POFF);
            uint64_t vd = make_desc(vbuf);
#pragma unroll
            for (int kk = 0; kk < 4; kk++)
                tc_mma_f16_ss(tmem + O_OFF, pd + kk * 2, vd + kk * 2,
                              IDESC, (kt > 0) || (kk > 0));
            TC_COMMIT(mbP);
        }
        mbar_wait(mbP, (uint32_t)(kt & 1));
        TC_FENCE_AFTER();
    }

    lsp[my_half * 128 + rrow] = ls;
    __syncthreads();
    float inv = 1.f / (lsp[rrow] + lsp[128 + rrow]);

    uint32_t oreg[32];
    LDTM_X32(oreg, tmem + O_OFF + my_half * 32);
    TC_WAIT_LD();
    long long gr = qrow0 + rrow;
    int c0 = h * 64 + my_half * 32;
#pragma unroll
    for (int i = 0; i < 32; i += 2) {
        __nv_bfloat162 pv;
        pv.x = __float2bfloat16(__uint_as_float(oreg[i]) * inv);
        pv.y = __float2bfloat16(__uint_as_float(oreg[i + 1]) * inv);
        *(__nv_bfloat162*)(ccb + gr * DD + c0 + i) = pv;
    }
    TC_FENCE_BEFORE();
    __syncthreads();
    if (tid == 0) { MBAR_INVAL(mbS); MBAR_INVAL(mbP); }
    __syncthreads();
    if (wrp == 0) TC_DEALLOC(tmem, 128);
#else
    // ================= HMMA fallback (R6 version) =================
    __shared__ __nv_bfloat16 Qs[128 * 64];
    __shared__ __nv_bfloat16 Ks[2][64 * 64];
    __shared__ __nv_bfloat16 Vs[2][64 * 64];
    int w = wrp;

    auto loadKV = [&](int st, int kt) {
#pragma unroll
        for (int i = 0; i < 2; i++) {
            int idx = i * 2048 + tid * 8;
            int r = idx >> 6, c = idx & 63;
            int chunk = (c >> 3) ^ (r & 7);
            long long grow = (long long)b * SS + kt * 64 + r;
            cp16(smem_u32(&Ks[st][r * 64 + chunk * 8]), kvb + grow * 128 + c);
            cp16(smem_u32(&Vs[st][r * 64 + chunk * 8]), kvb + grow * 128 + 64 + c);
        }
        cp_commit();
    };

#pragma unroll
    for (int i = 0; i < 4; i++) {
        int idx = i * 2048 + tid * 8;
        int r = idx >> 6, c = idx & 63;
        int chunk = (c >> 3) ^ (r & 7);
        cp16(smem_u32(Qs + r * 64 + chunk * 8), qb + (qrow0 + r) * DD + h * 64 + c);
    }
    loadKV(0, 0);
    cp_wait<0>();
    __syncthreads();

    unsigned qa[4][4];
    {
        int r = w * 16 + (lane & 15);
#pragma unroll
        for (int kk = 0; kk < 4; kk++) {
            int chunk = ((kk * 2 + (lane >> 4)) ^ (r & 7));
            ldsm4(qa[kk], smem_u32(Qs + r * 64 + chunk * 8));
        }
    }

    float o[8][4];
#pragma unroll
    for (int nt = 0; nt < 8; nt++)
#pragma unroll
        for (int i = 0; i < 4; i++) o[nt][i] = 0.f;
    float ls0 = 0.f, ls1 = 0.f;

    for (int kt = 0; kt < SS / 64; kt++) {
        if (kt + 1 < SS / 64) { loadKV((kt + 1) & 1, kt + 1); cp_wait<1>(); }
        else cp_wait<0>();
        __syncthreads();
        const __nv_bfloat16* ks = Ks[kt & 1];
        const __nv_bfloat16* vs = Vs[kt & 1];

        float sf[8][4];
#pragma unroll
        for (int nt = 0; nt < 8; nt++)
#pragma unroll
            for (int i = 0; i < 4; i++) sf[nt][i] = 0.f;
#pragma unroll
        for (int kk = 0; kk < 4; kk++) {
#pragma unroll
            for (int np = 0; np < 4; np++) {
                unsigned bbf[4];
                int krow = (2 * np + ((lane >> 4) & 1)) * 8 + (lane & 7);
                int chunk = ((kk * 2 + ((lane >> 3) & 1)) ^ (krow & 7));
                ldsm4(bbf, smem_u32(ks + krow * 64 + chunk * 8));
                mma16816(sf[2 * np], qa[kk], bbf);
                mma16816(sf[2 * np + 1], qa[kk], bbf + 2);
            }
        }
#pragma unroll
        for (int nt = 0; nt < 8; nt++) {
            sf[nt][0] = ex2(sf[nt][0]);
            sf[nt][1] = ex2(sf[nt][1]);
            sf[nt][2] = ex2(sf[nt][2]);
            sf[nt][3] = ex2(sf[nt][3]);
            ls0 += sf[nt][0] + sf[nt][1];
            ls1 += sf[nt][2] + sf[nt][3];
        }
#pragma unroll
        for (int j = 0; j < 4; j++) {
            unsigned pa[4];
            pa[0] = pack_bf16(sf[2 * j][0], sf[2 * j][1]);
            pa[1] = pack_bf16(sf[2 * j][2], sf[2 * j][3]);
            pa[2] = pack_bf16(sf[2 * j + 1][0], sf[2 * j + 1][1]);
            pa[3] = pack_bf16(sf[2 * j + 1][2], sf[2 * j + 1][3]);
#pragma unroll
            for (int np = 0; np < 4; np++) {
                unsigned vv[4];
                int vrow = j * 16 + (lane & 7) + ((lane >> 3) & 1) * 8;
                int cgrp = 2 * np + ((lane >> 4) & 1);
                int chunk = (cgrp ^ (vrow & 7));
                ldsm4t(vv, smem_u32(vs + vrow * 64 + chunk * 8));
                mma16816(o[2 * np], pa, vv);
                mma16816(o[2 * np + 1], pa, vv + 2);
            }
        }
        __syncthreads();
    }

    ls0 += __shfl_xor_sync(0xFFFFFFFFu, ls0, 1);
    ls0 += __shfl_xor_sync(0xFFFFFFFFu, ls0, 2);
    ls1 += __shfl_xor_sync(0xFFFFFFFFu, ls1, 1);
    ls1 += __shfl_xor_sync(0xFFFFFFFFu, ls1, 2);
    float inv0 = 1.f / ls0, inv1 = 1.f / ls1;

    long long gr = qrow0 + w * 16 + (lane >> 2);
#pragma unroll
    for (int nt = 0; nt < 8; nt++) {
        int c = h * 64 + nt * 8 + 2 * (lane & 3);
        __nv_bfloat162 p0, p1;
        p0.x = __float2bfloat16(o[nt][0] * inv0);
        p0.y = __float2bfloat16(o[nt][1] * inv0);
        p1.x = __float2bfloat16(o[nt][2] * inv1);
        p1.y = __float2bfloat16(o[nt][3] * inv1);
        *(__nv_bfloat162*)(ccb + gr * DD + c) = p0;
        *(__nv_bfloat162*)(ccb + (gr + 8) * DD + c) = p1;
    }
#endif
}

// ---------------- logits + dispatch softmax (vectorized, phiT) ----------------
__global__ __launch_bounds__(128) void logits_kernel(
    const float* __restrict__ m, const float* __restrict__ phiT,
    float* __restrict__ logits, float* __restrict__ dispatch) {
    __shared__ float4 msv[DD / 4];
    __shared__ float part[8][NSLOT];
    __shared__ float lsm[NSLOT];
    long long row = blockIdx.x;
    int tid = threadIdx.x;
    const float4* mr = (const float4*)(m + row * DD);
    msv[tid] = mr[tid];
    msv[tid + 128] = mr[tid + 128];
    __syncthreads();
    int e = tid & 15, seg = tid >> 4;
    const float4* pe = (const float4*)(phiT + e * DD) + seg * 32;
    const float4* ms = msv + seg * 32;
    float acc = 0.f;
#pragma unroll
    for (int i = 0; i < 32; i++) {
        float4 mv = ms[i];
        float4 pv = pe[i];
        acc += mv.x * pv.x + mv.y * pv.y + mv.z * pv.z + mv.w * pv.w;
    }
    part[seg][e] = acc;
    __syncthreads();
    if (tid < NSLOT) {
        float l = 0.f;
#pragma unroll
        for (int s = 0; s < 8; s++) l += part[s][tid];
        logits[row * NSLOT + tid] = l;
        lsm[tid] = l;
    }
    __syncthreads();
    if (tid < NSLOT) {
        float mx = lsm[0];
        for (int j = 1; j < NSLOT; j++) mx = fmaxf(mx, lsm[j]);
        float s = 0.f;
        for (int j = 0; j < NSLOT; j++) s += expf(lsm[j] - mx);
        dispatch[row * NSLOT + tid] = expf(lsm[tid] - mx) / s;
    }
}

// ---------------- combine softmax over sequence axis ----------------
__global__ void combine_kernel(const float* __restrict__ logits, float* __restrict__ comb) {
    int b = blockIdx.x >> 4, e = blockIdx.x & 15;
    const float* base = logits + ((long long)b * SS) * NSLOT + e;
    float v[8];
    float mx = -1e30f;
#pragma unroll
    for (int i = 0; i < 8; i++) {
        int s = threadIdx.x + i * 256;
        v[i] = base[(long long)s * NSLOT];
        mx = fmaxf(mx, v[i]);
    }
    __shared__ float red[8];
#pragma unroll
    for (int o = 16; o; o >>= 1) mx = fmaxf(mx, __shfl_xor_sync(0xFFFFFFFFu, mx, o));
    int w = threadIdx.x >> 5;
    if ((threadIdx.x & 31) == 0) red[w] = mx;
    __syncthreads();
    if (threadIdx.x == 0) {
        float t = red[0];
        for (int i = 1; i < 8; i++) t = fmaxf(t, red[i]);
        red[0] = t;
    }
    __syncthreads();
    mx = red[0];
    __syncthreads();
    float s = 0.f;
#pragma unroll
    for (int i = 0; i < 8; i++) { v[i] = expf(v[i] - mx); s += v[i]; }
#pragma unroll
    for (int o = 16; o; o >>= 1) s += __shfl_xor_sync(0xFFFFFFFFu, s, o);
    if ((threadIdx.x & 31) == 0) red[w] = s;
    __syncthreads();
    if (threadIdx.x == 0) {
        float t = 0.f;
        for (int i = 0; i < 8; i++) t += red[i];
        red[0] = t;
    }
    __syncthreads();
    float inv = 1.0f / red[0];
    float* ob = comb + ((long long)b * SS) * NSLOT + e;
#pragma unroll
    for (int i = 0; i < 8; i++) {
        int sidx = threadIdx.x + i * 256;
        ob[(long long)sidx * NSLOT] = v[i] * inv;
    }
}

// ---------------- xs partials + reduce ----------------
__global__ void xs_part_kernel(const float* __restrict__ dispatch, const float* __restrict__ m,
                               float* __restrict__ part) {
    int d = blockIdx.x * 256 + threadIdx.x;
    int b = blockIdx.y, seg = blockIdx.z;
    int s0 = seg * SCHUNK;
    __shared__ __align__(16) float ds[SCHUNK][NSLOT];
    for (int i = threadIdx.x; i < SCHUNK * NSLOT; i += 256)
        ds[i >> 4][i & 15] = dispatch[((long long)b * SS + s0) * NSLOT + i];
    __syncthreads();
    float acc[NSLOT];
#pragma unroll
    for (int e = 0; e < NSLOT; e++) acc[e] = 0.f;
    const float* mb = m + ((long long)b * SS + s0) * DD + d;
    for (int s = 0; s < SCHUNK; s++) {
        float mv = mb[(long long)s * DD];
        const float4* dr = (const float4*)ds[s];
#pragma unroll
        for (int q = 0; q < 4; q++) {
            float4 dv = dr[q];
            acc[q * 4 + 0] += dv.x * mv;
            acc[q * 4 + 1] += dv.y * mv;
            acc[q * 4 + 2] += dv.z * mv;
            acc[q * 4 + 3] += dv.w * mv;
        }
    }
#pragma unroll
    for (int e = 0; e < NSLOT; e++)
        part[(((long long)seg * BB + b) * NSLOT + e) * DD + d] = acc[e];
}

__global__ void xs_reduce_kernel(const float* __restrict__ part, float* __restrict__ xs) {
    int i = blockIdx.x * 256 + threadIdx.x;
    float a = 0.f;
#pragma unroll
    for (int seg = 0; seg < SSEG; seg++)
        a += part[(long long)seg * BB * NSLOT * DD + i];
    xs[i] = a;
}

// ---------------- expert FFN1 partials: h1p[ds][r][e][f] (float4 w1 loads) ----------------
// grid (EE, FS1, DS1), 256 threads, 4 consecutive f per thread.
__global__ __launch_bounds__(256) void ffn1_kernel(
    const float* __restrict__ xs, const float* __restrict__ w1,
    float* __restrict__ h1p) {
    int e = blockIdx.x, fs = blockIdx.y, ds = blockIdx.z;
    int f0 = fs * F1CH, d0 = ds * D1CH;
    int tid = threadIdx.x;
    __shared__ __align__(16) float xst[D1CH][8];
    for (int i = tid; i < D1CH * 8; i += 256) {
        int d = i & (D1CH - 1), r = i >> 8;  // D1CH==256
        int b = r >> 1, slot = r & 1;
        xst[d][r] = xs[((long long)(b * NSLOT + e * 2 + slot)) * DD + d0 + d];
    }
    __syncthreads();
    float4 acc[8];
#pragma unroll
    for (int r = 0; r < 8; r++) acc[r] = make_float4(0.f, 0.f, 0.f, 0.f);
    const float4* w = (const float4*)(w1 + (long long)e * DD * DFF
                                      + (long long)d0 * DFF + f0) + tid;
    for (int d = 0; d < D1CH; d++) {
        float4 wv = w[(long long)d * (DFF / 4)];
        float4 x0 = *(const float4*)&xst[d][0];
        float4 x1 = *(const float4*)&xst[d][4];
        acc[0].x += wv.x * x0.x; acc[0].y += wv.y * x0.x; acc[0].z += wv.z * x0.x; acc[0].w += wv.w * x0.x;
        acc[1].x += wv.x * x0.y; acc[1].y += wv.y * x0.y; acc[1].z += wv.z * x0.y; acc[1].w += wv.w * x0.y;
        acc[2].x += wv.x * x0.z; acc[2].y += wv.y * x0.z; acc[2].z += wv.z * x0.z; acc[2].w += wv.w * x0.z;
        acc[3].x += wv.x * x0.w; acc[3].y += wv.y * x0.w; acc[3].z += wv.z * x0.w; acc[3].w += wv.w * x0.w;
        acc[4].x += wv.x * x1.x; acc[4].y += wv.y * x1.x; acc[4].z += wv.z * x1.x; acc[4].w += wv.w * x1.x;
        acc[5].x += wv.x * x1.y; acc[5].y += wv.y * x1.y; acc[5].z += wv.z * x1.y; acc[5].w += wv.w * x1.y;
        acc[6].x += wv.x * x1.z; acc[6].y += wv.y * x1.z; acc[6].z += wv.z * x1.z; acc[6].w += wv.w * x1.z;
        acc[7].x += wv.x * x1.w; acc[7].y += wv.y * x1.w; acc[7].z += wv.z * x1.w; acc[7].w += wv.w * x1.w;
    }
#pragma unroll
    for (int r = 0; r < 8; r++) {
        // layout [ds][r][e][f]: coalesced float4 stores over f
        *(float4*)(h1p + (((long long)ds * 8 + r) * EE + e) * DFF + f0 + tid * 4) = acc[r];
    }
}

// ---------------- h1 reduce + bias + gelu -> hidT[e][f][r] ----------------
__global__ void h1_reduce_kernel(const float* __restrict__ h1p, const float* __restrict__ b1,
                                 float* __restrict__ hidT) {
    int i = blockIdx.x * 256 + threadIdx.x;      // over 8 * EE * DFF
    int r = i / (EE * DFF);
    int rem = i - r * (EE * DFF);                // e*DFF + f
    float a = b1[rem];
#pragma unroll
    for (int ds = 0; ds < DS1; ds++)
        a += h1p[((long long)ds * 8 + r) * EE * DFF + rem];
    hidT[(long long)rem * 8 + r] = 0.5f * a * (1.0f + erff(a * 0.70710678118654752f));
}

// ---------------- expert FFN2 partials: ysp[fs][row][d] ----------------
// grid (EE, FSEG=32), 256 threads, 4 d per thread (float4).
__global__ __launch_bounds__(256) void ffn2_kernel(
    const float* __restrict__ hidT, const float* __restrict__ w2,
    float* __restrict__ ysp) {
    int e = blockIdx.x, fs = blockIdx.y;
    int f0 = fs * FCH;
    int tid = threadIdx.x;
    __shared__ __align__(16) float hs[FCH][8];
    for (int i = tid; i < FCH * 8; i += 256) {
        int f = i >> 3, r = i & 7;
        hs[f][r] = hidT[((long long)e * DFF + f0 + f) * 8 + r];
    }
    __syncthreads();
    float4 acc[8];
#pragma unroll
    for (int r = 0; r < 8; r++) acc[r] = make_float4(0.f, 0.f, 0.f, 0.f);
    const float4* w = (const float4*)(w2 + (long long)e * DFF * DD + (long long)f0 * DD) + tid;
    for (int f = 0; f < FCH; f++) {
        float4 wv = w[(long long)f * (DD / 4)];
        float4 h0 = *(const float4*)&hs[f][0];
        float4 h1 = *(const float4*)&hs[f][4];
        acc[0].x += wv.x * h0.x; acc[0].y += wv.y * h0.x; acc[0].z += wv.z * h0.x; acc[0].w += wv.w * h0.x;
        acc[1].x += wv.x * h0.y; acc[1].y += wv.y * h0.y; acc[1].z += wv.z * h0.y; acc[1].w += wv.w * h0.y;
        acc[2].x += wv.x * h0.z; acc[2].y += wv.y * h0.z; acc[2].z += wv.z * h0.z; acc[2].w += wv.w * h0.z;
        acc[3].x += wv.x * h0.w; acc[3].y += wv.y * h0.w; acc[3].z += wv.z * h0.w; acc[3].w += wv.w * h0.w;
        acc[4].x += wv.x * h1.x; acc[4].y += wv.y * h1.x; acc[4].z += wv.z * h1.x; acc[4].w += wv.w * h1.x;
        acc[5].x += wv.x * h1.y; acc[5].y += wv.y * h1.y; acc[5].z += wv.z * h1.y; acc[5].w += wv.w * h1.y;
        acc[6].x += wv.x * h1.z; acc[6].y += wv.y * h1.z; acc[6].z += wv.z * h1.z; acc[6].w += wv.w * h1.z;
        acc[7].x += wv.x * h1.w; acc[7].y += wv.y * h1.w; acc[7].z += wv.z * h1.w; acc[7].w += wv.w * h1.w;
    }
#pragma unroll
    for (int r = 0; r < 8; r++) {
        int b = r >> 1, slot = r & 1;
        int rowl = b * NSLOT + e * 2 + slot;
        *(float4*)(ysp + ((long long)fs * BB * NSLOT + rowl) * DD + tid * 4) = acc[r];
    }
}

// ---------------- ys reduce + bias ----------------
__global__ void ys_reduce_kernel(const float* __restrict__ ysp, const float* __restrict__ b2,
                                 float* __restrict__ ys) {
    int i = blockIdx.x * 256 + threadIdx.x;   // over BB*NSLOT*DD
    int row = i >> 10, d = i & 1023;
    int e = (row & 15) >> 1;
    float a = b2[e * DD + d];
#pragma unroll
    for (int fs = 0; fs < FSEG; fs++)
        a += ysp[(long long)fs * BB * NSLOT * DD + i];
    ys[i] = a;
}

// ---------------- final: out = m + combine @ ys (row per block, float4) ----------------
__global__ __launch_bounds__(256) void final_kernel(
    const float* __restrict__ m, const float* __restrict__ comb,
    const float* __restrict__ ys, float* __restrict__ out) {
    long long row = blockIdx.x;
    int b = (int)(row >> 11);
    int tid = threadIdx.x;
    __shared__ float cs[NSLOT];
    if (tid < NSLOT) cs[tid] = comb[row * NSLOT + tid];
    __syncthreads();
    float4 acc = *(const float4*)(m + row * DD + tid * 4);
    const float* yb = ys + (long long)b * NSLOT * DD + tid * 4;
#pragma unroll
    for (int j = 0; j < NSLOT; j++) {
        float4 yv = *(const float4*)(yb + (long long)j * DD);
        float c = cs[j];
        acc.x += c * yv.x; acc.y += c * yv.y;
        acc.z += c * yv.z; acc.w += c * yv.w;
    }
    *(float4*)(out + row * DD + tid * 4) = acc;
}

// ---------------- launch ----------------
extern "C" void kernel_launch(void* const* d_in, const int* in_sizes, int n_in,
                              void* d_out, int out_size) {
    const float* x        = (const float*)d_in[0];
    const float* wq       = (const float*)d_in[1];
    const float* wkv      = (const float*)d_in[2];
    const float* wo       = (const float*)d_in[3];
    const float* gm_attn  = (const float*)d_in[4];
    const float* gm_moe   = (const float*)d_in[5];
    const float* phi      = (const float*)d_in[6];
    const float* w1       = (const float*)d_in[7];
    const float* b1       = (const float*)d_in[8];
    const float* w2       = (const float*)d_in[9];
    const float* b2       = (const float*)d_in[10];
    float* out = (float*)d_out;

    float *h, *x1, *m, *lg, *dp, *cb, *xs, *xsp, *h1p, *hidT, *ysp, *ys, *phiT;
    __nv_bfloat16 *hb, *qb, *kvb, *vt, *ccb, *wqT, *wkvT, *woT;
    cudaGetSymbolAddress((void**)&h,    g_h);
    cudaGetSymbolAddress((void**)&hb,   g_hb);
    cudaGetSymbolAddress((void**)&qb,   g_qb);
    cudaGetSymbolAddress((void**)&kvb,  g_kvb);
    cudaGetSymbolAddress((void**)&vt,   g_vT);
    cudaGetSymbolAddress((void**)&ccb,  g_ccb);
    cudaGetSymbolAddress((void**)&wqT,  g_wqT);
    cudaGetSymbolAddress((void**)&wkvT, g_wkvT);
    cudaGetSymbolAddress((void**)&woT,  g_woT);
    cudaGetSymbolAddress((void**)&phiT, g_phiT);
    cudaGetSymbolAddress((void**)&x1,   g_x1);
    cudaGetSymbolAddress((void**)&m,    g_m);
    cudaGetSymbolAddress((void**)&lg,   g_logits);
    cudaGetSymbolAddress((void**)&dp,   g_dispatch);
    cudaGetSymbolAddress((void**)&cb,   g_combine);
    cudaGetSymbolAddress((void**)&xs,   g_xs);
    cudaGetSymbolAddress((void**)&xsp,  g_xs_part);
    cudaGetSymbolAddress((void**)&h1p,  g_h1p);
    cudaGetSymbolAddress((void**)&hidT, g_hidT);
    cudaGetSymbolAddress((void**)&ysp,  g_ys_part);
    cudaGetSymbolAddress((void**)&ys,   g_ys);

    const int G_SMEM = 1024 + 1024 + 6 * 16384; // 100352
    cudaFuncSetAttribute(gemm_kernel<false, true>,
                         cudaFuncAttributeMaxDynamicSharedMemorySize, G_SMEM);
    cudaFuncSetAttribute(gemm_kernel<true, false>,
                         cudaFuncAttributeMaxDynamicSharedMemorySize, G_SMEM);
    const int F_SMEM = 1024 + 2048 + 4 * 16384;
    cudaFuncSetAttribute(flash_kernel,
                         cudaFuncAttributeMaxDynamicSharedMemorySize, F_SMEM);

    // 0) ln: h = LN(x), hb
    ln_kernel<<<ROWS, 256>>>(x, gm_attn, h, hb);
    // 1) wq transpose
    transpose_cvt_kernel<<<dim3(32, 32), dim3(32, 8)>>>(wq, wqT, DD, DD);
    // 2) wkv transpose
    transpose_cvt_kernel<<<dim3(4, 32), dim3(32, 8)>>>(wkv, wkvT, DD, 128);
    // 3) gemm_q (ncu capture slot)
    gemm_kernel<false, true><<<dim3(8, 64), 256, G_SMEM>>>(
        hb, wqT, nullptr, nullptr, qb, ROWS, DD, DD, 0.125f * 1.4426950408889634f);
    // 4) wo transpose
    transpose_cvt_kernel<<<dim3(32, 32), dim3(32, 8)>>>(wo, woT, DD, DD);
    // 5) phi transpose
    phiT_kernel<<<DD / 256, 256>>>(phi, phiT);
    // 6) gemm_kv
    gemm_kernel<false, true><<<dim3(1, 64), 256, G_SMEM>>>(
        hb, wkvT, nullptr, nullptr, kvb, ROWS, 128, DD, 1.0f);
    // 7) vT
    vT_kernel<<<dim3(SS / 32, HD / 32, BB), dim3(32, 8)>>>(kvb, vt);
    // 8) flash
    flash_kernel<<<dim3(SS / 128, BB * HH), 256, F_SMEM>>>(qb, kvb, vt, ccb);
    // 9) x1 = concat @ wo + h
    gemm_kernel<true, false><<<dim3(8, 64), 256, G_SMEM>>>(
        ccb, woT, h, x1, nullptr, ROWS, DD, DD, 1.0f);
    // 10) m = LN(x1)
    ln_kernel<<<ROWS, 256>>>(x1, gm_moe, m, nullptr);
    // 11) logits + dispatch
    logits_kernel<<<ROWS, 128>>>(m, phiT, lg, dp);
    // 12) combine
    combine_kernel<<<BB * NSLOT, 256>>>(lg, cb);
    // 13) xs partials
    xs_part_kernel<<<dim3(DD / 256, BB, SSEG), 256>>>(dp, m, xsp);
    // 14) xs reduce
    xs_reduce_kernel<<<(BB * NSLOT * DD) / 256, 256>>>(xsp, xs);
    // 15) ffn1 partials (float4 w1 loads, d-split)
    ffn1_kernel<<<dim3(EE, FS1, DS1), 256>>>(xs, w1, h1p);
    // 16) h1 reduce + bias + gelu
    h1_reduce_kernel<<<(8 * EE * DFF) / 256, 256>>>(h1p, b1, hidT);
    // 17) ffn2 partials (FSEG=32)
    ffn2_kernel<<<dim3(EE, FSEG), 256>>>(hidT, w2, ysp);
    // 18) ys reduce + bias
    ys_reduce_kernel<<<(BB * NSLOT * DD) / 256, 256>>>(ysp, b2, ys);
    // 19) final
    final_kernel<<<ROWS, 256>>>(m, cb, ys, out);
}

// round 15
// speedup vs baseline: 3.5056x; 1.0038x over previous
#include <cuda_runtime.h>
#include <cuda_bf16.h>
#include <math.h>
#include <stdint.h>

// Problem constants
#define BB 4
#define SS 2048
#define DD 1024
#define HH 16
#define HD 64
#define EE 8
#define DFF 4096
#define NSLOT 16        // E*SLOTS
#define ROWS (BB*SS)    // 8192
#define SSEG 8
#define SCHUNK (SS/SSEG)  // 256
#define FSEG 32
#define FCH (DFF/FSEG)    // 128
#define FS1 4
#define DS1 4
#define F1CH (DFF/FS1)    // 1024
#define D1CH (DD/DS1)     // 256

// tcgen05 availability: only in arch-specific (sm_103a/sm_100a-family) device pass
#if defined(__CUDA_ARCH__) && (defined(__CUDA_ARCH_FEAT_SM103_ALL) || defined(__CUDA_ARCH_FEAT_SM100_ALL) || defined(__CUDA_ARCH_SPECIFIC__) || defined(__CUDA_ARCH_FAMILY_SPECIFIC__))
#define TCOK 1
#else
#define TCOK 0
#endif

// ---------------- scratch (static __device__ globals; no allocation) ----------------
__device__ float g_h[ROWS * DD];
__device__ __nv_bfloat16 g_hb[ROWS * DD];
__device__ __nv_bfloat16 g_qb[ROWS * DD];
__device__ __nv_bfloat16 g_kvb[ROWS * 128];
__device__ __nv_bfloat16 g_vT[BB * HD * SS];   // [b][dim][seq]
__device__ __nv_bfloat16 g_ccb[ROWS * DD];
__device__ __nv_bfloat16 g_wqT[DD * DD];    // [N=D][K=D]
__device__ __nv_bfloat16 g_wkvT[128 * DD];  // [N=128][K=D]
__device__ __nv_bfloat16 g_woT[DD * DD];    // [N=D][K=D]
__device__ float g_phiT[NSLOT * DD];        // [16][1024]
__device__ float g_x1[ROWS * DD];
__device__ float g_m[ROWS * DD];
__device__ float g_logits[ROWS * NSLOT];
__device__ float g_dispatch[ROWS * NSLOT];
__device__ float g_combine[ROWS * NSLOT];
__device__ float g_xs[BB * NSLOT * DD];
__device__ float g_xs_part[SSEG * BB * NSLOT * DD];
__device__ float g_h1p[DS1 * 8 * EE * DFF]; // [ds][r][e][f]
__device__ float g_hidT[EE * DFF * 8];      // [e][f][8 rows]
__device__ float g_ys_part[FSEG * BB * NSLOT * DD];
__device__ float g_ys[BB * NSLOT * DD];

// ---------------- asm helpers ----------------
__device__ __forceinline__ unsigned smem_u32(const void* p) {
    return (unsigned)__cvta_generic_to_shared(p);
}
__device__ __forceinline__ void mma16816(float* d, const unsigned* a, const unsigned* b) {
    asm volatile("mma.sync.aligned.m16n8k16.row.col.f32.bf16.bf16.f32 "
                 "{%0,%1,%2,%3}, {%4,%5,%6,%7}, {%8,%9}, {%0,%1,%2,%3};\n"
                 : "+f"(d[0]), "+f"(d[1]), "+f"(d[2]), "+f"(d[3])
                 : "r"(a[0]), "r"(a[1]), "r"(a[2]), "r"(a[3]), "r"(b[0]), "r"(b[1]));
}
__device__ __forceinline__ void ldsm4(unsigned* r, unsigned a) {
    asm volatile("ldmatrix.sync.aligned.m8n8.x4.shared.b16 {%0,%1,%2,%3}, [%4];\n"
                 : "=r"(r[0]), "=r"(r[1]), "=r"(r[2]), "=r"(r[3]) : "r"(a));
}
__device__ __forceinline__ void ldsm4t(unsigned* r, unsigned a) {
    asm volatile("ldmatrix.sync.aligned.m8n8.x4.trans.shared.b16 {%0,%1,%2,%3}, [%4];\n"
                 : "=r"(r[0]), "=r"(r[1]), "=r"(r[2]), "=r"(r[3]) : "r"(a));
}
__device__ __forceinline__ unsigned pack_bf16(float a, float b) {
    __nv_bfloat162 t;
    t.x = __float2bfloat16(a);
    t.y = __float2bfloat16(b);
    return *reinterpret_cast<unsigned*>(&t);
}
__device__ __forceinline__ float ex2(float x) {
    float y;
    asm("ex2.approx.f32 %0, %1;" : "=f"(y) : "f"(x));
    return y;
}
__device__ __forceinline__ void cp16(unsigned dst, const void* src) {
    asm volatile("cp.async.cg.shared.global [%0], [%1], 16;\n" :: "r"(dst), "l"(src));
}
__device__ __forceinline__ void cp_commit() {
    asm volatile("cp.async.commit_group;\n");
}
template<int N>
__device__ __forceinline__ void cp_wait() {
    asm volatile("cp.async.wait_group %0;\n" :: "n"(N));
}

#if TCOK
// ---------------- tcgen05 helpers (arch-specific pass only) ----------------
__device__ __forceinline__ uint32_t elect_one() {
    uint32_t pred;
    asm volatile("{\n\t.reg .pred p;\n\telect.sync _|p, 0xFFFFFFFF;\n\t"
                 "selp.b32 %0, 1, 0, p;\n\t}" : "=r"(pred));
    return pred;
}
#define TC_ALLOC(smem_addr, ncols) \
    asm volatile("tcgen05.alloc.cta_group::1.sync.aligned.shared::cta.b32 [%0], %1;" \
                 :: "r"((uint32_t)(smem_addr)), "r"((uint32_t)(ncols)) : "memory")
#define TC_RELINQ() \
    asm volatile("tcgen05.relinquish_alloc_permit.cta_group::1.sync.aligned;")
#define TC_DEALLOC(tmem, ncols) \
    asm volatile("tcgen05.dealloc.cta_group::1.sync.aligned.b32 %0, %1;" \
                 :: "r"(tmem), "r"((uint32_t)(ncols)))
#define TC_COMMIT(mbar) \
    asm volatile("tcgen05.commit.cta_group::1.mbarrier::arrive::one.shared::cluster.b64 [%0];" \
                 :: "r"((uint32_t)(mbar)) : "memory")
#define TC_FENCE_AFTER()  asm volatile("tcgen05.fence::after_thread_sync;" ::: "memory")
#define TC_FENCE_BEFORE() asm volatile("tcgen05.fence::before_thread_sync;" ::: "memory")
#define TC_WAIT_LD()      asm volatile("tcgen05.wait::ld.sync.aligned;" ::: "memory")
#define MBAR_INIT(mbar, cnt) \
    asm volatile("mbarrier.init.shared.b64 [%0], %1;" \
                 :: "r"((uint32_t)(mbar)), "r"((uint32_t)(cnt)) : "memory")
#define MBAR_INVAL(mbar) \
    asm volatile("mbarrier.inval.shared.b64 [%0];" :: "r"((uint32_t)(mbar)) : "memory")
#define FENCE_PROXY() asm volatile("fence.proxy.async.shared::cta;" ::: "memory")

__device__ __forceinline__ void mbar_wait(uint32_t mbar, uint32_t parity) {
    uint32_t done;
    asm volatile("{\n\t.reg .pred p;\n\t"
                 "mbarrier.try_wait.parity.acquire.cta.shared::cta.b64 p, [%1], %2;\n\t"
                 "selp.b32 %0, 1, 0, p;\n\t}"
                 : "=r"(done) : "r"(mbar), "r"(parity) : "memory");
    if (!done) {
        asm volatile("{\n\t.reg .pred P1;\n\t"
                     "WL_%=:\n\t"
                     "mbarrier.try_wait.parity.acquire.cta.shared::cta.b64 P1, [%0], %1, 0x989680;\n\t"
                     "@P1 bra.uni WD_%=;\n\t"
                     "bra.uni WL_%=;\n\t"
                     "WD_%=:\n\t}"
                     :: "r"(mbar), "r"(parity) : "memory");
    }
}
__device__ __forceinline__ void tc_mma_f16_ss(uint32_t d, uint64_t ad, uint64_t bd,
                                              uint32_t idesc, bool en) {
    uint32_t e = en ? 1u : 0u, z = 0u;
    asm volatile("{\n\t.reg .pred p;\n\tsetp.ne.u32 p, %5, 0;\n\t"
                 "tcgen05.mma.cta_group::1.kind::f16 [%0], %1, %2, %3, {%4,%4,%4,%4}, p;\n\t}"
                 :: "r"(d), "l"(ad), "l"(bd), "r"(idesc), "r"(z), "r"(e) : "memory");
}
__device__ __forceinline__ uint32_t ld_shared_u32(uint32_t addr) {
    uint32_t v;
    asm volatile("ld.shared.b32 %0, [%1];" : "=r"(v) : "r"(addr));
    return v;
}
// SW128 smem descriptor, K-major: layout 2, version 1, SBO=64, LBO=1
__device__ __forceinline__ uint64_t make_desc(uint32_t addr) {
    const uint64_t base = (uint64_t(2) << 61) | (uint64_t(1) << 46)
                        | (uint64_t(64) << 32) | (uint64_t(1) << 16);
    return base | ((uint64_t)(addr >> 4) & 0x3FFF);
}
#define LDTM_X32(r, addr) \
    asm volatile("tcgen05.ld.sync.aligned.32x32b.x32.b32 " \
        "{%0,%1,%2,%3,%4,%5,%6,%7,%8,%9,%10,%11,%12,%13,%14,%15," \
        "%16,%17,%18,%19,%20,%21,%22,%23,%24,%25,%26,%27,%28,%29,%30,%31}, [%32];" \
        : "=r"((r)[0]),"=r"((r)[1]),"=r"((r)[2]),"=r"((r)[3]), \
          "=r"((r)[4]),"=r"((r)[5]),"=r"((r)[6]),"=r"((r)[7]), \
          "=r"((r)[8]),"=r"((r)[9]),"=r"((r)[10]),"=r"((r)[11]), \
          "=r"((r)[12]),"=r"((r)[13]),"=r"((r)[14]),"=r"((r)[15]), \
          "=r"((r)[16]),"=r"((r)[17]),"=r"((r)[18]),"=r"((r)[19]), \
          "=r"((r)[20]),"=r"((r)[21]),"=r"((r)[22]),"=r"((r)[23]), \
          "=r"((r)[24]),"=r"((r)[25]),"=r"((r)[26]),"=r"((r)[27]), \
          "=r"((r)[28]),"=r"((r)[29]),"=r"((r)[30]),"=r"((r)[31]) \
        : "r"(addr))
#endif // TCOK

// ---------------- layernorm ----------------
__global__ void ln_kernel(const float* __restrict__ x, const float* __restrict__ gamma,
                          float* __restrict__ out, __nv_bfloat16* __restrict__ ob) {
    long long row = blockIdx.x;
    const float* p = x + row * DD;
    float v[4];
    float s = 0.f, sq = 0.f;
#pragma unroll
    for (int i = 0; i < 4; i++) {
        v[i] = p[threadIdx.x + i * 256];
        s += v[i];
        sq += v[i] * v[i];
    }
    __shared__ float rs[8], rq[8];
#pragma unroll
    for (int o = 16; o; o >>= 1) {
        s  += __shfl_xor_sync(0xFFFFFFFFu, s, o);
        sq += __shfl_xor_sync(0xFFFFFFFFu, sq, o);
    }
    int w = threadIdx.x >> 5;
    if ((threadIdx.x & 31) == 0) { rs[w] = s; rq[w] = sq; }
    __syncthreads();
    if (threadIdx.x == 0) {
        float ts = 0.f, tq = 0.f;
        for (int i = 0; i < 8; i++) { ts += rs[i]; tq += rq[i]; }
        rs[0] = ts; rq[0] = tq;
    }
    __syncthreads();
    float mean = rs[0] * (1.f / (float)DD);
    float var  = rq[0] * (1.f / (float)DD) - mean * mean;
    float rstd = rsqrtf(var + 1e-5f);
    float* o = out + row * DD;
#pragma unroll
    for (int i = 0; i < 4; i++) {
        int d = threadIdx.x + i * 256;
        float val = gamma[d] * (v[i] - mean) * rstd;
        o[d] = val;
        if (ob) ob[row * DD + d] = __float2bfloat16(val);
    }
}

// ---------------- weight transpose + convert ----------------
__global__ void transpose_cvt_kernel(const float* __restrict__ in,
                                     __nv_bfloat16* __restrict__ out, int R, int C) {
    __shared__ float t[32][33];
    int c0 = blockIdx.x * 32, r0 = blockIdx.y * 32;
    for (int i = threadIdx.y; i < 32; i += 8)
        t[i][threadIdx.x] = in[(long long)(r0 + i) * C + c0 + threadIdx.x];
    __syncthreads();
    for (int i = threadIdx.y; i < 32; i += 8)
        out[(long long)(c0 + i) * R + r0 + threadIdx.x] = __float2bfloat16(t[threadIdx.x][i]);
}

// ---------------- phi transpose ----------------
__global__ void phiT_kernel(const float* __restrict__ phi, float* __restrict__ phiT) {
    int d = blockIdx.x * 256 + threadIdx.x;
#pragma unroll
    for (int e = 0; e < NSLOT; e++)
        phiT[e * DD + d] = phi[d * NSLOT + e];
}

// ---------------- v transpose ----------------
__global__ void vT_kernel(const __nv_bfloat16* __restrict__ kvb,
                          __nv_bfloat16* __restrict__ vT) {
    __shared__ __nv_bfloat16 t[32][33];
    int s0 = blockIdx.x * 32, d0 = blockIdx.y * 32, b = blockIdx.z;
    for (int i = threadIdx.y; i < 32; i += 8)
        t[i][threadIdx.x] = kvb[((long long)(b * SS + s0 + i)) * 128 + 64 + d0 + threadIdx.x];
    __syncthreads();
    for (int i = threadIdx.y; i < 32; i += 8)
        vT[((long long)(b * HD + d0 + i)) * SS + s0 + threadIdx.x] = t[threadIdx.x][i];
}

// ---------------- unified bf16 GEMM (R11 version, passing) ----------------
template<bool ADD, bool OUTBF>
__global__ __launch_bounds__(256) __cluster_dims__(1, 1, 1) void gemm_kernel(
    const __nv_bfloat16* __restrict__ A, const __nv_bfloat16* __restrict__ BT,
    const float* __restrict__ AddP, float* __restrict__ Cf,
    __nv_bfloat16* __restrict__ Cb, int M, int N, int K, float alpha) {
    extern __shared__ char smraw[];
    uint32_t sb0 = smem_u32(smraw);
    uint32_t sbase = (sb0 + 1023u) & ~1023u;
    int tid = threadIdx.x, lane = tid & 31, wrp = tid >> 5;
    int row0 = blockIdx.y * 128, col0 = blockIdx.x * 128;
    const uint32_t T0 = sbase + 1024;

    auto loadA = [&](uint32_t off, int k0) {
#pragma unroll
        for (int i = 0; i < 4; i++) {
            int idx = i * 256 + tid;
            int r = idx >> 3, ch = idx & 7;
            cp16(off + r * 128 + ((ch ^ (r & 7)) << 4),
                 A + (long long)(row0 + r) * K + k0 + ch * 8);
        }
    };
    auto loadB = [&](uint32_t off, int k0) {
#pragma unroll
        for (int i = 0; i < 4; i++) {
            int idx = i * 256 + tid;
            int r = idx >> 3, ch = idx & 7;
            cp16(off + r * 128 + ((ch ^ (r & 7)) << 4),
                 BT + (long long)(col0 + r) * K + k0 + ch * 8);
        }
    };
    int NT = K / 64;

#if TCOK
    const uint32_t BOFF = T0 + 3 * 16384;
    if (wrp == 0) { TC_ALLOC(sbase, 128); TC_RELINQ(); }
    if (tid == 0) {
        MBAR_INIT(sbase + 8, 1);
        MBAR_INIT(sbase + 16, 1);
        MBAR_INIT(sbase + 24, 1);
    }
    __syncthreads();
    uint32_t tmem = ld_shared_u32(sbase);
    const uint32_t IDESC = 0x490u | (16u << 17) | (8u << 24);
    auto mb = [&](int i) -> uint32_t { return sbase + 8 + (uint32_t)i * 8; };

    loadA(T0, 0); loadB(BOFF, 0); cp_commit();
    if (NT > 1) { loadA(T0 + 16384, 64); loadB(BOFF + 16384, 64); cp_commit(); }

    for (int t = 0; t < NT; t++) {
        uint32_t sA = T0 + (uint32_t)(t % 3) * 16384;
        uint32_t sB = BOFF + (uint32_t)(t % 3) * 16384;
        if (t + 1 < NT) cp_wait<1>();
        else cp_wait<0>();
        FENCE_PROXY();
        __syncthreads();
        if (wrp == 0 && elect_one()) {
            uint64_t ad = make_desc(sA);
            uint64_t bd = make_desc(sB);
#pragma unroll
            for (int kk = 0; kk < 4; kk++)
                tc_mma_f16_ss(tmem, ad + kk * 2, bd + kk * 2, IDESC, (t > 0) || (kk > 0));
            TC_COMMIT(mb(t % 3));
        }
        if (t + 2 < NT) {
            if (t >= 1) mbar_wait(mb((t - 1) % 3), (uint32_t)(((t - 1) / 3) & 1));
            loadA(T0 + (uint32_t)((t + 2) % 3) * 16384, (t + 2) * 64);
            loadB(BOFF + (uint32_t)((t + 2) % 3) * 16384, (t + 2) * 64);
            cp_commit();
        }
    }
    for (int tt = (NT >= 3 ? NT - 3 : 0); tt < NT; tt++)
        mbar_wait(mb(tt % 3), (uint32_t)((tt / 3) & 1));
    TC_FENCE_AFTER();

    {
        long long r = row0 + (wrp & 3) * 32 + lane;
        int cbase = (wrp >> 2) * 64;
#pragma unroll
        for (int cg = 0; cg < 2; cg++) {
            uint32_t regs[32];
            LDTM_X32(regs, tmem + cbase + cg * 32);
            TC_WAIT_LD();
            int c0 = col0 + cbase + cg * 32;
            if (OUTBF) {
#pragma unroll
                for (int i = 0; i < 32; i += 2) {
                    __nv_bfloat162 p;
                    p.x = __float2bfloat16(__uint_as_float(regs[i]) * alpha);
                    p.y = __float2bfloat16(__uint_as_float(regs[i + 1]) * alpha);
                    *(__nv_bfloat162*)(Cb + r * N + c0 + i) = p;
                }
            } else {
#pragma unroll
                for (int i = 0; i < 32; i += 2) {
                    float v0 = __uint_as_float(regs[i]) * alpha;
                    float v1 = __uint_as_float(regs[i + 1]) * alpha;
                    if (ADD) {
                        float2 a = *(const float2*)(AddP + r * N + c0 + i);
                        v0 += a.x; v1 += a.y;
                    }
                    *(float2*)(Cf + r * N + c0 + i) = make_float2(v0, v1);
                }
            }
        }
    }
    TC_FENCE_BEFORE();
    __syncthreads();
    if (tid == 0) { MBAR_INVAL(mb(0)); MBAR_INVAL(mb(1)); MBAR_INVAL(mb(2)); }
    __syncthreads();
    if (wrp == 0) TC_DEALLOC(tmem, 128);
#else
    const __nv_bfloat16* As[2] = { (const __nv_bfloat16*)(smraw + (T0 - sb0)),
                                   (const __nv_bfloat16*)(smraw + (T0 - sb0) + 16384) };
    const __nv_bfloat16* Bs[2] = { (const __nv_bfloat16*)(smraw + (T0 - sb0) + 32768),
                                   (const __nv_bfloat16*)(smraw + (T0 - sb0) + 49152) };
    int wm = wrp >> 2, wn = wrp & 3;

    float acc[4][4][4];
#pragma unroll
    for (int mt = 0; mt < 4; mt++)
#pragma unroll
        for (int nt = 0; nt < 4; nt++)
#pragma unroll
            for (int i = 0; i < 4; i++) acc[mt][nt][i] = 0.f;

    loadA(T0, 0); loadB(T0 + 32768, 0); cp_commit();
    for (int t = 0; t < NT; t++) {
        if (t + 1 < NT) {
            loadA(T0 + (uint32_t)((t + 1) & 1) * 16384, (t + 1) * 64);
            loadB(T0 + 32768 + (uint32_t)((t + 1) & 1) * 16384, (t + 1) * 64);
            cp_commit();
            cp_wait<1>();
        } else cp_wait<0>();
        __syncthreads();
        const __nv_bfloat16* as = As[t & 1];
        const __nv_bfloat16* bs = Bs[t & 1];
#pragma unroll
        for (int kk = 0; kk < 4; kk++) {
            unsigned af[4][4], bf[2][4];
#pragma unroll
            for (int mt = 0; mt < 4; mt++) {
                int r = wm * 64 + mt * 16 + (lane & 15);
                int chunk = ((kk * 2 + (lane >> 4)) ^ (r & 7));
                ldsm4(af[mt], smem_u32(as + r * 64 + chunk * 8));
            }
#pragma unroll
            for (int np = 0; np < 2; np++) {
                int nrow = wn * 32 + (2 * np + ((lane >> 4) & 1)) * 8 + (lane & 7);
                int chunk = ((kk * 2 + ((lane >> 3) & 1)) ^ (nrow & 7));
                ldsm4(bf[np], smem_u32(bs + nrow * 64 + chunk * 8));
            }
#pragma unroll
            for (int mt = 0; mt < 4; mt++)
#pragma unroll
                for (int nt = 0; nt < 4; nt++)
                    mma16816(acc[mt][nt], af[mt], bf[nt >> 1] + (nt & 1) * 2);
        }
        __syncthreads();
    }
#pragma unroll
    for (int mt = 0; mt < 4; mt++) {
#pragma unroll
        for (int nt = 0; nt < 4; nt++) {
            int r = row0 + wm * 64 + mt * 16 + (lane >> 2);
            int c = col0 + wn * 32 + nt * 8 + 2 * (lane & 3);
            float v0 = acc[mt][nt][0] * alpha, v1 = acc[mt][nt][1] * alpha;
            float v2 = acc[mt][nt][2] * alpha, v3 = acc[mt][nt][3] * alpha;
            if (OUTBF) {
                __nv_bfloat162 p0; p0.x = __float2bfloat16(v0); p0.y = __float2bfloat16(v1);
                __nv_bfloat162 p1; p1.x = __float2bfloat16(v2); p1.y = __float2bfloat16(v3);
                *(__nv_bfloat162*)(Cb + (long long)r * N + c) = p0;
                *(__nv_bfloat162*)(Cb + (long long)(r + 8) * N + c) = p1;
            } else {
                if (ADD) {
                    float2 a0 = *(const float2*)(AddP + (long long)r * N + c);
                    float2 a1 = *(const float2*)(AddP + (long long)(r + 8) * N + c);
                    v0 += a0.x; v1 += a0.y; v2 += a1.x; v3 += a1.y;
                }
                *(float2*)(Cf + (long long)r * N + c) = make_float2(v0, v1);
                *(float2*)(Cf + (long long)(r + 8) * N + c) = make_float2(v2, v3);
            }
        }
    }
#endif
}

// ---------------- flash attention: PIPELINED tcgen05 / HMMA fallback ----------------
// Loop order per tile kt: wait S(kt) -> wait PV(kt-1) -> prefetch KV(kt+1) ->
// LDTM+ex2+pack -> store P + sync -> issue PV(kt) -> cp_wait + issue S(kt+1).
// Wrap-free: at every mbar wait, commits issued on that barrier exceed the waited
// index by at most 1, so the phase can flip at most once past the target.
__global__ __launch_bounds__(256) __cluster_dims__(1, 1, 1) void flash_kernel(
    const __nv_bfloat16* __restrict__ qb, const __nv_bfloat16* __restrict__ kvb,
    const __nv_bfloat16* __restrict__ vT, __nv_bfloat16* __restrict__ ccb) {
    int tid = threadIdx.x, lane = tid & 31, wrp = tid >> 5;
    int b = blockIdx.y >> 4, h = blockIdx.y & 15;
    long long qrow0 = (long long)b * SS + blockIdx.x * 128;

#if TCOK
    extern __shared__ char smraw[];
    uint32_t sb0 = smem_u32(smraw);
    uint32_t sbase = (sb0 + 1023u) & ~1023u;
    const uint32_t QOFF = sbase + 2048;
    const uint32_t K0 = QOFF + 16384;
    const uint32_t V0 = K0 + 16384;
    const uint32_t POFF = V0 + 16384;
    float* lsp = (float*)(smraw + (sbase - sb0) + 512);
    char* pgen = smraw + (POFF - sb0);

    if (wrp == 0) { TC_ALLOC(sbase, 128); TC_RELINQ(); }
    if (tid == 0) { MBAR_INIT(sbase + 8, 1); MBAR_INIT(sbase + 16, 1); }
    __syncthreads();
    uint32_t tmem = ld_shared_u32(sbase);
    const uint32_t mbS = sbase + 8, mbP = sbase + 16;
    const int S_OFF = 0, O_OFF = 64;

#pragma unroll
    for (int i = 0; i < 4; i++) {
        int idx = i * 256 + tid;
        int r = idx >> 3, ch = idx & 7;
        cp16(QOFF + r * 128 + ((ch ^ (r & 7)) << 4),
             qb + (qrow0 + r) * DD + h * 64 + ch * 8);
    }
    auto loadKV = [&](int buf, int kt) {
#pragma unroll
        for (int i = 0; i < 2; i++) {
            int idx = i * 256 + tid;
            int r = idx >> 3, ch = idx & 7;
            uint32_t sw = r * 128 + ((ch ^ (r & 7)) << 4);
            cp16(K0 + buf * 8192 + sw,
                 kvb + ((long long)b * SS + kt * 64 + r) * 128 + ch * 8);
            cp16(V0 + buf * 8192 + sw,
                 vT + ((long long)(b * HD + r)) * SS + kt * 64 + ch * 8);
        }
        cp_commit();
    };

    const uint32_t IDESC = 0x490u | (8u << 17) | (8u << 24);
    int my_half = wrp >> 2;
    int rrow = (wrp & 3) * 32 + lane;
    float ls = 0.f;
    uint64_t qd = make_desc(QOFF);
    const int NKT = SS / 64;

    // preamble: load Q + KV(0), then issue S(0)
    loadKV(0, 0);
    cp_wait<0>();
    FENCE_PROXY();
    __syncthreads();
    if (wrp == 0 && elect_one()) {
        uint64_t kd = make_desc(K0);
#pragma unroll
        for (int kk = 0; kk < 4; kk++)
            tc_mma_f16_ss(tmem + S_OFF, qd + kk * 2, kd + kk * 2, IDESC, kk > 0);
        TC_COMMIT(mbS);
    }

    for (int kt = 0; kt < NKT; kt++) {
        // 1. S(kt) done (commits on mbS so far: kt+1; completions in [kt, kt+1])
        mbar_wait(mbS, (uint32_t)(kt & 1));
        TC_FENCE_AFTER();

        // 2. PV(kt-1) done -> P smem and KV buf (kt+1)&1 reusable
        if (kt >= 1) mbar_wait(mbP, (uint32_t)((kt - 1) & 1));

        // 3. prefetch KV(kt+1) (overlaps LDTM/exp/store below)
        if (kt + 1 < NKT) loadKV((kt + 1) & 1, kt + 1);

        // 4. LDTM S + exp2 + row-sum + pack
        uint32_t sreg[32];
        LDTM_X32(sreg, tmem + S_OFF + my_half * 32);
        TC_WAIT_LD();
        float p[32];
#pragma unroll
        for (int i = 0; i < 32; i++) {
            p[i] = ex2(__uint_as_float(sreg[i]));
            ls += p[i];
        }
        uint32_t pw[16];
#pragma unroll
        for (int i = 0; i < 16; i++) pw[i] = pack_bf16(p[2 * i], p[2 * i + 1]);

        // 5. store P to smem; visible to async proxy; sync also fences all LDTM
#pragma unroll
        for (int j = 0; j < 4; j++) {
            int ch = my_half * 4 + j;
            *(uint4*)(pgen + rrow * 128 + ((ch ^ (rrow & 7)) << 4)) =
                make_uint4(pw[4 * j], pw[4 * j + 1], pw[4 * j + 2], pw[4 * j + 3]);
        }
        FENCE_PROXY();
        TC_FENCE_BEFORE();
        __syncthreads();

        // 6. PV(kt): O += P @ VT
        if (wrp == 0 && elect_one()) {
            TC_FENCE_AFTER();
            uint64_t pd = make_desc(POFF);
            uint64_t vd = make_desc(V0 + (uint32_t)(kt & 1) * 8192);
#pragma unroll
            for (int kk = 0; kk < 4; kk++)
                tc_mma_f16_ss(tmem + O_OFF, pd + kk * 2, vd + kk * 2,
                              IDESC, (kt > 0) || (kk > 0));
            TC_COMMIT(mbP);
        }

        // 7. once KV(kt+1) resident, issue S(kt+1) (S TMEM freed at step-5 sync)
        if (kt + 1 < NKT) {
            cp_wait<0>();
            FENCE_PROXY();
            __syncthreads();
            if (wrp == 0 && elect_one()) {
                uint64_t kd = make_desc(K0 + (uint32_t)((kt + 1) & 1) * 8192);
#pragma unroll
                for (int kk = 0; kk < 4; kk++)
                    tc_mma_f16_ss(tmem + S_OFF, qd + kk * 2, kd + kk * 2, IDESC, kk > 0);
                TC_COMMIT(mbS);
            }
        }
    }
    // drain: last PV (commits NKT, completions needed NKT; no further commits)
    mbar_wait(mbP, (uint32_t)((NKT - 1) & 1));
    TC_FENCE_AFTER();

    lsp[my_half * 128 + rrow] = ls;
    __syncthreads();
    float inv = 1.f / (lsp[rrow] + lsp[128 + rrow]);

    uint32_t oreg[32];
    LDTM_X32(oreg, tmem + O_OFF + my_half * 32);
    TC_WAIT_LD();
    long long gr = qrow0 + rrow;
    int c0 = h * 64 + my_half * 32;
#pragma unroll
    for (int i = 0; i < 32; i += 2) {
        __nv_bfloat162 pv;
        pv.x = __float2bfloat16(__uint_as_float(oreg[i]) * inv);
        pv.y = __float2bfloat16(__uint_as_float(oreg[i + 1]) * inv);
        *(__nv_bfloat162*)(ccb + gr * DD + c0 + i) = pv;
    }
    TC_FENCE_BEFORE();
    __syncthreads();
    if (tid == 0) { MBAR_INVAL(mbS); MBAR_INVAL(mbP); }
    __syncthreads();
    if (wrp == 0) TC_DEALLOC(tmem, 128);
#else
    // ================= HMMA fallback (R6 version) =================
    __shared__ __nv_bfloat16 Qs[128 * 64];
    __shared__ __nv_bfloat16 Ks[2][64 * 64];
    __shared__ __nv_bfloat16 Vs[2][64 * 64];
    int w = wrp;

    auto loadKV = [&](int st, int kt) {
#pragma unroll
        for (int i = 0; i < 2; i++) {
            int idx = i * 2048 + tid * 8;
            int r = idx >> 6, c = idx & 63;
            int chunk = (c >> 3) ^ (r & 7);
            long long grow = (long long)b * SS + kt * 64 + r;
            cp16(smem_u32(&Ks[st][r * 64 + chunk * 8]), kvb + grow * 128 + c);
            cp16(smem_u32(&Vs[st][r * 64 + chunk * 8]), kvb + grow * 128 + 64 + c);
        }
        cp_commit();
    };

#pragma unroll
    for (int i = 0; i < 4; i++) {
        int idx = i * 2048 + tid * 8;
        int r = idx >> 6, c = idx & 63;
        int chunk = (c >> 3) ^ (r & 7);
        cp16(smem_u32(Qs + r * 64 + chunk * 8), qb + (qrow0 + r) * DD + h * 64 + c);
    }
    loadKV(0, 0);
    cp_wait<0>();
    __syncthreads();

    unsigned qa[4][4];
    {
        int r = w * 16 + (lane & 15);
#pragma unroll
        for (int kk = 0; kk < 4; kk++) {
            int chunk = ((kk * 2 + (lane >> 4)) ^ (r & 7));
            ldsm4(qa[kk], smem_u32(Qs + r * 64 + chunk * 8));
        }
    }

    float o[8][4];
#pragma unroll
    for (int nt = 0; nt < 8; nt++)
#pragma unroll
        for (int i = 0; i < 4; i++) o[nt][i] = 0.f;
    float ls0 = 0.f, ls1 = 0.f;

    for (int kt = 0; kt < SS / 64; kt++) {
        if (kt + 1 < SS / 64) { loadKV((kt + 1) & 1, kt + 1); cp_wait<1>(); }
        else cp_wait<0>();
        __syncthreads();
        const __nv_bfloat16* ks = Ks[kt & 1];
        const __nv_bfloat16* vs = Vs[kt & 1];

        float sf[8][4];
#pragma unroll
        for (int nt = 0; nt < 8; nt++)
#pragma unroll
            for (int i = 0; i < 4; i++) sf[nt][i] = 0.f;
#pragma unroll
        for (int kk = 0; kk < 4; kk++) {
#pragma unroll
            for (int np = 0; np < 4; np++) {
                unsigned bbf[4];
                int krow = (2 * np + ((lane >> 4) & 1)) * 8 + (lane & 7);
                int chunk = ((kk * 2 + ((lane >> 3) & 1)) ^ (krow & 7));
                ldsm4(bbf, smem_u32(ks + krow * 64 + chunk * 8));
                mma16816(sf[2 * np], qa[kk], bbf);
                mma16816(sf[2 * np + 1], qa[kk], bbf + 2);
            }
        }
#pragma unroll
        for (int nt = 0; nt < 8; nt++) {
            sf[nt][0] = ex2(sf[nt][0]);
            sf[nt][1] = ex2(sf[nt][1]);
            sf[nt][2] = ex2(sf[nt][2]);
            sf[nt][3] = ex2(sf[nt][3]);
            ls0 += sf[nt][0] + sf[nt][1];
            ls1 += sf[nt][2] + sf[nt][3];
        }
#pragma unroll
        for (int j = 0; j < 4; j++) {
            unsigned pa[4];
            pa[0] = pack_bf16(sf[2 * j][0], sf[2 * j][1]);
            pa[1] = pack_bf16(sf[2 * j][2], sf[2 * j][3]);
            pa[2] = pack_bf16(sf[2 * j + 1][0], sf[2 * j + 1][1]);
            pa[3] = pack_bf16(sf[2 * j + 1][2], sf[2 * j + 1][3]);
#pragma unroll
            for (int np = 0; np < 4; np++) {
                unsigned vv[4];
                int vrow = j * 16 + (lane & 7) + ((lane >> 3) & 1) * 8;
                int cgrp = 2 * np + ((lane >> 4) & 1);
                int chunk = (cgrp ^ (vrow & 7));
                ldsm4t(vv, smem_u32(vs + vrow * 64 + chunk * 8));
                mma16816(o[2 * np], pa, vv);
                mma16816(o[2 * np + 1], pa, vv + 2);
            }
        }
        __syncthreads();
    }

    ls0 += __shfl_xor_sync(0xFFFFFFFFu, ls0, 1);
    ls0 += __shfl_xor_sync(0xFFFFFFFFu, ls0, 2);
    ls1 += __shfl_xor_sync(0xFFFFFFFFu, ls1, 1);
    ls1 += __shfl_xor_sync(0xFFFFFFFFu, ls1, 2);
    float inv0 = 1.f / ls0, inv1 = 1.f / ls1;

    long long gr = qrow0 + w * 16 + (lane >> 2);
#pragma unroll
    for (int nt = 0; nt < 8; nt++) {
        int c = h * 64 + nt * 8 + 2 * (lane & 3);
        __nv_bfloat162 p0, p1;
        p0.x = __float2bfloat16(o[nt][0] * inv0);
        p0.y = __float2bfloat16(o[nt][1] * inv0);
        p1.x = __float2bfloat16(o[nt][2] * inv1);
        p1.y = __float2bfloat16(o[nt][3] * inv1);
        *(__nv_bfloat162*)(ccb + gr * DD + c) = p0;
        *(__nv_bfloat162*)(ccb + (gr + 8) * DD + c) = p1;
    }
#endif
}

// ---------------- logits + dispatch softmax (vectorized, phiT) ----------------
__global__ __launch_bounds__(128) void logits_kernel(
    const float* __restrict__ m, const float* __restrict__ phiT,
    float* __restrict__ logits, float* __restrict__ dispatch) {
    __shared__ float4 msv[DD / 4];
    __shared__ float part[8][NSLOT];
    __shared__ float lsm[NSLOT];
    long long row = blockIdx.x;
    int tid = threadIdx.x;
    const float4* mr = (const float4*)(m + row * DD);
    msv[tid] = mr[tid];
    msv[tid + 128] = mr[tid + 128];
    __syncthreads();
    int e = tid & 15, seg = tid >> 4;
    const float4* pe = (const float4*)(phiT + e * DD) + seg * 32;
    const float4* ms = msv + seg * 32;
    float acc = 0.f;
#pragma unroll
    for (int i = 0; i < 32; i++) {
        float4 mv = ms[i];
        float4 pv = pe[i];
        acc += mv.x * pv.x + mv.y * pv.y + mv.z * pv.z + mv.w * pv.w;
    }
    part[seg][e] = acc;
    __syncthreads();
    if (tid < NSLOT) {
        float l = 0.f;
#pragma unroll
        for (int s = 0; s < 8; s++) l += part[s][tid];
        logits[row * NSLOT + tid] = l;
        lsm[tid] = l;
    }
    __syncthreads();
    if (tid < NSLOT) {
        float mx = lsm[0];
        for (int j = 1; j < NSLOT; j++) mx = fmaxf(mx, lsm[j]);
        float s = 0.f;
        for (int j = 0; j < NSLOT; j++) s += expf(lsm[j] - mx);
        dispatch[row * NSLOT + tid] = expf(lsm[tid] - mx) / s;
    }
}

// ---------------- combine softmax over sequence axis ----------------
__global__ void combine_kernel(const float* __restrict__ logits, float* __restrict__ comb) {
    int b = blockIdx.x >> 4, e = blockIdx.x & 15;
    const float* base = logits + ((long long)b * SS) * NSLOT + e;
    float v[8];
    float mx = -1e30f;
#pragma unroll
    for (int i = 0; i < 8; i++) {
        int s = threadIdx.x + i * 256;
        v[i] = base[(long long)s * NSLOT];
        mx = fmaxf(mx, v[i]);
    }
    __shared__ float red[8];
#pragma unroll
    for (int o = 16; o; o >>= 1) mx = fmaxf(mx, __shfl_xor_sync(0xFFFFFFFFu, mx, o));
    int w = threadIdx.x >> 5;
    if ((threadIdx.x & 31) == 0) red[w] = mx;
    __syncthreads();
    if (threadIdx.x == 0) {
        float t = red[0];
        for (int i = 1; i < 8; i++) t = fmaxf(t, red[i]);
        red[0] = t;
    }
    __syncthreads();
    mx = red[0];
    __syncthreads();
    float s = 0.f;
#pragma unroll
    for (int i = 0; i < 8; i++) { v[i] = expf(v[i] - mx); s += v[i]; }
#pragma unroll
    for (int o = 16; o; o >>= 1) s += __shfl_xor_sync(0xFFFFFFFFu, s, o);
    if ((threadIdx.x & 31) == 0) red[w] = s;
    __syncthreads();
    if (threadIdx.x == 0) {
        float t = 0.f;
        for (int i = 0; i < 8; i++) t += red[i];
        red[0] = t;
    }
    __syncthreads();
    float inv = 1.0f / red[0];
    float* ob = comb + ((long long)b * SS) * NSLOT + e;
#pragma unroll
    for (int i = 0; i < 8; i++) {
        int sidx = threadIdx.x + i * 256;
        ob[(long long)sidx * NSLOT] = v[i] * inv;
    }
}

// ---------------- xs partials + reduce ----------------
__global__ void xs_part_kernel(const float* __restrict__ dispatch, const float* __restrict__ m,
                               float* __restrict__ part) {
    int d = blockIdx.x * 256 + threadIdx.x;
    int b = blockIdx.y, seg = blockIdx.z;
    int s0 = seg * SCHUNK;
    __shared__ __align__(16) float ds[SCHUNK][NSLOT];
    for (int i = threadIdx.x; i < SCHUNK * NSLOT; i += 256)
        ds[i >> 4][i & 15] = dispatch[((long long)b * SS + s0) * NSLOT + i];
    __syncthreads();
    float acc[NSLOT];
#pragma unroll
    for (int e = 0; e < NSLOT; e++) acc[e] = 0.f;
    const float* mb = m + ((long long)b * SS + s0) * DD + d;
    for (int s = 0; s < SCHUNK; s++) {
        float mv = mb[(long long)s * DD];
        const float4* dr = (const float4*)ds[s];
#pragma unroll
        for (int q = 0; q < 4; q++) {
            float4 dv = dr[q];
            acc[q * 4 + 0] += dv.x * mv;
            acc[q * 4 + 1] += dv.y * mv;
            acc[q * 4 + 2] += dv.z * mv;
            acc[q * 4 + 3] += dv.w * mv;
        }
    }
#pragma unroll
    for (int e = 0; e < NSLOT; e++)
        part[(((long long)seg * BB + b) * NSLOT + e) * DD + d] = acc[e];
}

__global__ void xs_reduce_kernel(const float* __restrict__ part, float* __restrict__ xs) {
    int i = blockIdx.x * 256 + threadIdx.x;
    float a = 0.f;
#pragma unroll
    for (int seg = 0; seg < SSEG; seg++)
        a += part[(long long)seg * BB * NSLOT * DD + i];
    xs[i] = a;
}

// ---------------- expert FFN1 partials: h1p[ds][r][e][f] (float4 w1 loads) ----------------
__global__ __launch_bounds__(256) void ffn1_kernel(
    const float* __restrict__ xs, const float* __restrict__ w1,
    float* __restrict__ h1p) {
    int e = blockIdx.x, fs = blockIdx.y, ds = blockIdx.z;
    int f0 = fs * F1CH, d0 = ds * D1CH;
    int tid = threadIdx.x;
    __shared__ __align__(16) float xst[D1CH][8];
    for (int i = tid; i < D1CH * 8; i += 256) {
        int d = i & (D1CH - 1), r = i >> 8;  // D1CH==256
        int b = r >> 1, slot = r & 1;
        xst[d][r] = xs[((long long)(b * NSLOT + e * 2 + slot)) * DD + d0 + d];
    }
    __syncthreads();
    float4 acc[8];
#pragma unroll
    for (int r = 0; r < 8; r++) acc[r] = make_float4(0.f, 0.f, 0.f, 0.f);
    const float4* w = (const float4*)(w1 + (long long)e * DD * DFF
                                      + (long long)d0 * DFF + f0) + tid;
    for (int d = 0; d < D1CH; d++) {
        float4 wv = w[(long long)d * (DFF / 4)];
        float4 x0 = *(const float4*)&xst[d][0];
        float4 x1 = *(const float4*)&xst[d][4];
        acc[0].x += wv.x * x0.x; acc[0].y += wv.y * x0.x; acc[0].z += wv.z * x0.x; acc[0].w += wv.w * x0.x;
        acc[1].x += wv.x * x0.y; acc[1].y += wv.y * x0.y; acc[1].z += wv.z * x0.y; acc[1].w += wv.w * x0.y;
        acc[2].x += wv.x * x0.z; acc[2].y += wv.y * x0.z; acc[2].z += wv.z * x0.z; acc[2].w += wv.w * x0.z;
        acc[3].x += wv.x * x0.w; acc[3].y += wv.y * x0.w; acc[3].z += wv.z * x0.w; acc[3].w += wv.w * x0.w;
        acc[4].x += wv.x * x1.x; acc[4].y += wv.y * x1.x; acc[4].z += wv.z * x1.x; acc[4].w += wv.w * x1.x;
        acc[5].x += wv.x * x1.y; acc[5].y += wv.y * x1.y; acc[5].z += wv.z * x1.y; acc[5].w += wv.w * x1.y;
        acc[6].x += wv.x * x1.z; acc[6].y += wv.y * x1.z; acc[6].z += wv.z * x1.z; acc[6].w += wv.w * x1.z;
        acc[7].x += wv.x * x1.w; acc[7].y += wv.y * x1.w; acc[7].z += wv.z * x1.w; acc[7].w += wv.w * x1.w;
    }
#pragma unroll
    for (int r = 0; r < 8; r++) {
        *(float4*)(h1p + (((long long)ds * 8 + r) * EE + e) * DFF + f0 + tid * 4) = acc[r];
    }
}

// ---------------- h1 reduce + bias + gelu -> hidT[e][f][r] ----------------
__global__ void h1_reduce_kernel(const float* __restrict__ h1p, const float* __restrict__ b1,
                                 float* __restrict__ hidT) {
    int i = blockIdx.x * 256 + threadIdx.x;      // over 8 * EE * DFF
    int r = i / (EE * DFF);
    int rem = i - r * (EE * DFF);                // e*DFF + f
    float a = b1[rem];
#pragma unroll
    for (int ds = 0; ds < DS1; ds++)
        a += h1p[((long long)ds * 8 + r) * EE * DFF + rem];
    hidT[(long long)rem * 8 + r] = 0.5f * a * (1.0f + erff(a * 0.70710678118654752f));
}

// ---------------- expert FFN2 partials: ysp[fs][row][d] ----------------
__global__ __launch_bounds__(256) void ffn2_kernel(
    const float* __restrict__ hidT, const float* __restrict__ w2,
    float* __restrict__ ysp) {
    int e = blockIdx.x, fs = blockIdx.y;
    int f0 = fs * FCH;
    int tid = threadIdx.x;
    __shared__ __align__(16) float hs[FCH][8];
    for (int i = tid; i < FCH * 8; i += 256) {
        int f = i >> 3, r = i & 7;
        hs[f][r] = hidT[((long long)e * DFF + f0 + f) * 8 + r];
    }
    __syncthreads();
    float4 acc[8];
#pragma unroll
    for (int r = 0; r < 8; r++) acc[r] = make_float4(0.f, 0.f, 0.f, 0.f);
    const float4* w = (const float4*)(w2 + (long long)e * DFF * DD + (long long)f0 * DD) + tid;
    for (int f = 0; f < FCH; f++) {
        float4 wv = w[(long long)f * (DD / 4)];
        float4 h0 = *(const float4*)&hs[f][0];
        float4 h1 = *(const float4*)&hs[f][4];
        acc[0].x += wv.x * h0.x; acc[0].y += wv.y * h0.x; acc[0].z += wv.z * h0.x; acc[0].w += wv.w * h0.x;
        acc[1].x += wv.x * h0.y; acc[1].y += wv.y * h0.y; acc[1].z += wv.z * h0.y; acc[1].w += wv.w * h0.y;
        acc[2].x += wv.x * h0.z; acc[2].y += wv.y * h0.z; acc[2].z += wv.z * h0.z; acc[2].w += wv.w * h0.z;
        acc[3].x += wv.x * h0.w; acc[3].y += wv.y * h0.w; acc[3].z += wv.z * h0.w; acc[3].w += wv.w * h0.w;
        acc[4].x += wv.x * h1.x; acc[4].y += wv.y * h1.x; acc[4].z += wv.z * h1.x; acc[4].w += wv.w * h1.x;
        acc[5].x += wv.x * h1.y; acc[5].y += wv.y * h1.y; acc[5].z += wv.z * h1.y; acc[5].w += wv.w * h1.y;
        acc[6].x += wv.x * h1.z; acc[6].y += wv.y * h1.z; acc[6].z += wv.z * h1.z; acc[6].w += wv.w * h1.z;
        acc[7].x += wv.x * h1.w; acc[7].y += wv.y * h1.w; acc[7].z += wv.z * h1.w; acc[7].w += wv.w * h1.w;
    }
#pragma unroll
    for (int r = 0; r < 8; r++) {
        int b = r >> 1, slot = r & 1;
        int rowl = b * NSLOT + e * 2 + slot;
        *(float4*)(ysp + ((long long)fs * BB * NSLOT + rowl) * DD + tid * 4) = acc[r];
    }
}

// ---------------- ys reduce + bias ----------------
__global__ void ys_reduce_kernel(const float* __restrict__ ysp, const float* __restrict__ b2,
                                 float* __restrict__ ys) {
    int i = blockIdx.x * 256 + threadIdx.x;   // over BB*NSLOT*DD
    int row = i >> 10, d = i & 1023;
    int e = (row & 15) >> 1;
    float a = b2[e * DD + d];
#pragma unroll
    for (int fs = 0; fs < FSEG; fs++)
        a += ysp[(long long)fs * BB * NSLOT * DD + i];
    ys[i] = a;
}

// ---------------- final: out = m + combine @ ys (row per block, float4) ----------------
__global__ __launch_bounds__(256) void final_kernel(
    const float* __restrict__ m, const float* __restrict__ comb,
    const float* __restrict__ ys, float* __restrict__ out) {
    long long row = blockIdx.x;
    int b = (int)(row >> 11);
    int tid = threadIdx.x;
    __shared__ float cs[NSLOT];
    if (tid < NSLOT) cs[tid] = comb[row * NSLOT + tid];
    __syncthreads();
    float4 acc = *(const float4*)(m + row * DD + tid * 4);
    const float* yb = ys + (long long)b * NSLOT * DD + tid * 4;
#pragma unroll
    for (int j = 0; j < NSLOT; j++) {
        float4 yv = *(const float4*)(yb + (long long)j * DD);
        float c = cs[j];
        acc.x += c * yv.x; acc.y += c * yv.y;
        acc.z += c * yv.z; acc.w += c * yv.w;
    }
    *(float4*)(out + row * DD + tid * 4) = acc;
}

// ---------------- launch ----------------
extern "C" void kernel_launch(void* const* d_in, const int* in_sizes, int n_in,
                              void* d_out, int out_size) {
    const float* x        = (const float*)d_in[0];
    const float* wq       = (const float*)d_in[1];
    const float* wkv      = (const float*)d_in[2];
    const float* wo       = (const float*)d_in[3];
    const float* gm_attn  = (const float*)d_in[4];
    const float* gm_moe   = (const float*)d_in[5];
    const float* phi      = (const float*)d_in[6];
    const float* w1       = (const float*)d_in[7];
    const float* b1       = (const float*)d_in[8];
    const float* w2       = (const float*)d_in[9];
    const float* b2       = (const float*)d_in[10];
    float* out = (float*)d_out;

    float *h, *x1, *m, *lg, *dp, *cb, *xs, *xsp, *h1p, *hidT, *ysp, *ys, *phiT;
    __nv_bfloat16 *hb, *qb, *kvb, *vt, *ccb, *wqT, *wkvT, *woT;
    cudaGetSymbolAddress((void**)&h,    g_h);
    cudaGetSymbolAddress((void**)&hb,   g_hb);
    cudaGetSymbolAddress((void**)&qb,   g_qb);
    cudaGetSymbolAddress((void**)&kvb,  g_kvb);
    cudaGetSymbolAddress((void**)&vt,   g_vT);
    cudaGetSymbolAddress((void**)&ccb,  g_ccb);
    cudaGetSymbolAddress((void**)&wqT,  g_wqT);
    cudaGetSymbolAddress((void**)&wkvT, g_wkvT);
    cudaGetSymbolAddress((void**)&woT,  g_woT);
    cudaGetSymbolAddress((void**)&phiT, g_phiT);
    cudaGetSymbolAddress((void**)&x1,   g_x1);
    cudaGetSymbolAddress((void**)&m,    g_m);
    cudaGetSymbolAddress((void**)&lg,   g_logits);
    cudaGetSymbolAddress((void**)&dp,   g_dispatch);
    cudaGetSymbolAddress((void**)&cb,   g_combine);
    cudaGetSymbolAddress((void**)&xs,   g_xs);
    cudaGetSymbolAddress((void**)&xsp,  g_xs_part);
    cudaGetSymbolAddress((void**)&h1p,  g_h1p);
    cudaGetSymbolAddress((void**)&hidT, g_hidT);
    cudaGetSymbolAddress((void**)&ysp,  g_ys_part);
    cudaGetSymbolAddress((void**)&ys,   g_ys);

    const int G_SMEM = 1024 + 1024 + 6 * 16384; // 100352
    cudaFuncSetAttribute(gemm_kernel<false, true>,
                         cudaFuncAttributeMaxDynamicSharedMemorySize, G_SMEM);
    cudaFuncSetAttribute(gemm_kernel<true, false>,
                         cudaFuncAttributeMaxDynamicSharedMemorySize, G_SMEM);
    const int F_SMEM = 1024 + 2048 + 4 * 16384;
    cudaFuncSetAttribute(flash_kernel,
                         cudaFuncAttributeMaxDynamicSharedMemorySize, F_SMEM);

    // 0) ln: h = LN(x), hb
    ln_kernel<<<ROWS, 256>>>(x, gm_attn, h, hb);
    // 1) wq transpose
    transpose_cvt_kernel<<<dim3(32, 32), dim3(32, 8)>>>(wq, wqT, DD, DD);
    // 2) wkv transpose
    transpose_cvt_kernel<<<dim3(4, 32), dim3(32, 8)>>>(wkv, wkvT, DD, 128);
    // 3) gemm_q (ncu capture slot)
    gemm_kernel<false, true><<<dim3(8, 64), 256, G_SMEM>>>(
        hb, wqT, nullptr, nullptr, qb, ROWS, DD, DD, 0.125f * 1.4426950408889634f);
    // 4) wo transpose
    transpose_cvt_kernel<<<dim3(32, 32), dim3(32, 8)>>>(wo, woT, DD, DD);
    // 5) phi transpose
    phiT_kernel<<<DD / 256, 256>>>(phi, phiT);
    // 6) gemm_kv
    gemm_kernel<false, true><<<dim3(1, 64), 256, G_SMEM>>>(
        hb, wkvT, nullptr, nullptr, kvb, ROWS, 128, DD, 1.0f);
    // 7) vT
    vT_kernel<<<dim3(SS / 32, HD / 32, BB), dim3(32, 8)>>>(kvb, vt);
    // 8) flash (pipelined)
    flash_kernel<<<dim3(SS / 128, BB * HH), 256, F_SMEM>>>(qb, kvb, vt, ccb);
    // 9) x1 = concat @ wo + h
    gemm_kernel<true, false><<<dim3(8, 64), 256, G_SMEM>>>(
        ccb, woT, h, x1, nullptr, ROWS, DD, DD, 1.0f);
    // 10) m = LN(x1)
    ln_kernel<<<ROWS, 256>>>(x1, gm_moe, m, nullptr);
    // 11) logits + dispatch
    logits_kernel<<<ROWS, 128>>>(m, phiT, lg, dp);
    // 12) combine
    combine_kernel<<<BB * NSLOT, 256>>>(lg, cb);
    // 13) xs partials
    xs_part_kernel<<<dim3(DD / 256, BB, SSEG), 256>>>(dp, m, xsp);
    // 14) xs reduce
    xs_reduce_kernel<<<(BB * NSLOT * DD) / 256, 256>>>(xsp, xs);
    // 15) ffn1 partials
    ffn1_kernel<<<dim3(EE, FS1, DS1), 256>>>(xs, w1, h1p);
    // 16) h1 reduce + bias + gelu
    h1_reduce_kernel<<<(8 * EE * DFF) / 256, 256>>>(h1p, b1, hidT);
    // 17) ffn2 partials
    ffn2_kernel<<<dim3(EE, FSEG), 256>>>(hidT, w2, ysp);
    // 18) ys reduce + bias
    ys_reduce_kernel<<<(BB * NSLOT * DD) / 256, 256>>>(ysp, b2, ys);
    // 19) final
    final_kernel<<<ROWS, 256>>>(m, cb, ys, out);
}

// round 16
// speedup vs baseline: 4.1781x; 1.1918x over previous
#include <cuda_runtime.h>
#include <cuda_bf16.h>
#include <math.h>
#include <stdint.h>

// Problem constants
#define BB 4
#define SS 2048
#define DD 1024
#define HH 16
#define HD 64
#define EE 8
#define DFF 4096
#define NSLOT 16        // E*SLOTS
#define ROWS (BB*SS)    // 8192
#define SSEG 8
#define SCHUNK (SS/SSEG)  // 256
#define FSEG 32
#define FCH (DFF/FSEG)    // 128
#define FS1 4
#define DS1 4
#define F1CH (DFF/FS1)    // 1024
#define D1CH (DD/DS1)     // 256

// tcgen05 availability: only in arch-specific (sm_103a/sm_100a-family) device pass
#if defined(__CUDA_ARCH__) && (defined(__CUDA_ARCH_FEAT_SM103_ALL) || defined(__CUDA_ARCH_FEAT_SM100_ALL) || defined(__CUDA_ARCH_SPECIFIC__) || defined(__CUDA_ARCH_FAMILY_SPECIFIC__))
#define TCOK 1
#else
#define TCOK 0
#endif

// ---------------- scratch (static __device__ globals; no allocation) ----------------
__device__ float g_h[ROWS * DD];
__device__ __nv_bfloat16 g_hb[ROWS * DD];
__device__ __nv_bfloat16 g_qb[ROWS * DD];
__device__ __nv_bfloat16 g_kvb[ROWS * 128];
__device__ __nv_bfloat16 g_vT[BB * HD * SS];   // [b][dim][seq]
__device__ __nv_bfloat16 g_ccb[ROWS * DD];
__device__ __nv_bfloat16 g_wqT[DD * DD];    // [N=D][K=D]
__device__ __nv_bfloat16 g_wkvT[128 * DD];  // [N=128][K=D]
__device__ __nv_bfloat16 g_woT[DD * DD];    // [N=D][K=D]
__device__ float g_phiT[NSLOT * DD];        // [16][1024]
__device__ float g_x1[ROWS * DD];
__device__ float g_m[ROWS * DD];
__device__ float g_logits[ROWS * NSLOT];
__device__ float g_dispatch[ROWS * NSLOT];
__device__ float g_combine[ROWS * NSLOT];
__device__ float g_xs[BB * NSLOT * DD];
__device__ float g_xs_part[SSEG * BB * NSLOT * DD];
__device__ float g_h1p[DS1 * 8 * EE * DFF]; // [ds][r][e][f]
__device__ float g_hidT[EE * DFF * 8];      // [e][f][8 rows]
__device__ float g_ys_part[FSEG * BB * NSLOT * DD];
__device__ float g_ys[BB * NSLOT * DD];

// ---------------- asm helpers ----------------
__device__ __forceinline__ unsigned smem_u32(const void* p) {
    return (unsigned)__cvta_generic_to_shared(p);
}
__device__ __forceinline__ void mma16816(float* d, const unsigned* a, const unsigned* b) {
    asm volatile("mma.sync.aligned.m16n8k16.row.col.f32.bf16.bf16.f32 "
                 "{%0,%1,%2,%3}, {%4,%5,%6,%7}, {%8,%9}, {%0,%1,%2,%3};\n"
                 : "+f"(d[0]), "+f"(d[1]), "+f"(d[2]), "+f"(d[3])
                 : "r"(a[0]), "r"(a[1]), "r"(a[2]), "r"(a[3]), "r"(b[0]), "r"(b[1]));
}
__device__ __forceinline__ void ldsm4(unsigned* r, unsigned a) {
    asm volatile("ldmatrix.sync.aligned.m8n8.x4.shared.b16 {%0,%1,%2,%3}, [%4];\n"
                 : "=r"(r[0]), "=r"(r[1]), "=r"(r[2]), "=r"(r[3]) : "r"(a));
}
__device__ __forceinline__ void ldsm4t(unsigned* r, unsigned a) {
    asm volatile("ldmatrix.sync.aligned.m8n8.x4.trans.shared.b16 {%0,%1,%2,%3}, [%4];\n"
                 : "=r"(r[0]), "=r"(r[1]), "=r"(r[2]), "=r"(r[3]) : "r"(a));
}
__device__ __forceinline__ unsigned pack_bf16(float a, float b) {
    __nv_bfloat162 t;
    t.x = __float2bfloat16(a);
    t.y = __float2bfloat16(b);
    return *reinterpret_cast<unsigned*>(&t);
}
__device__ __forceinline__ float ex2(float x) {
    float y;
    asm("ex2.approx.f32 %0, %1;" : "=f"(y) : "f"(x));
    return y;
}
__device__ __forceinline__ void cp16(unsigned dst, const void* src) {
    asm volatile("cp.async.cg.shared.global [%0], [%1], 16;\n" :: "r"(dst), "l"(src));
}
__device__ __forceinline__ void cp_commit() {
    asm volatile("cp.async.commit_group;\n");
}
template<int N>
__device__ __forceinline__ void cp_wait() {
    asm volatile("cp.async.wait_group %0;\n" :: "n"(N));
}

#if TCOK
// ---------------- tcgen05 helpers (arch-specific pass only) ----------------
__device__ __forceinline__ uint32_t elect_one() {
    uint32_t pred;
    asm volatile("{\n\t.reg .pred p;\n\telect.sync _|p, 0xFFFFFFFF;\n\t"
                 "selp.b32 %0, 1, 0, p;\n\t}" : "=r"(pred));
    return pred;
}
#define TC_ALLOC(smem_addr, ncols) \
    asm volatile("tcgen05.alloc.cta_group::1.sync.aligned.shared::cta.b32 [%0], %1;" \
                 :: "r"((uint32_t)(smem_addr)), "r"((uint32_t)(ncols)) : "memory")
#define TC_RELINQ() \
    asm volatile("tcgen05.relinquish_alloc_permit.cta_group::1.sync.aligned;")
#define TC_DEALLOC(tmem, ncols) \
    asm volatile("tcgen05.dealloc.cta_group::1.sync.aligned.b32 %0, %1;" \
                 :: "r"(tmem), "r"((uint32_t)(ncols)))
#define TC_COMMIT(mbar) \
    asm volatile("tcgen05.commit.cta_group::1.mbarrier::arrive::one.shared::cluster.b64 [%0];" \
                 :: "r"((uint32_t)(mbar)) : "memory")
#define TC_FENCE_AFTER()  asm volatile("tcgen05.fence::after_thread_sync;" ::: "memory")
#define TC_FENCE_BEFORE() asm volatile("tcgen05.fence::before_thread_sync;" ::: "memory")
#define TC_WAIT_LD()      asm volatile("tcgen05.wait::ld.sync.aligned;" ::: "memory")
#define MBAR_INIT(mbar, cnt) \
    asm volatile("mbarrier.init.shared.b64 [%0], %1;" \
                 :: "r"((uint32_t)(mbar)), "r"((uint32_t)(cnt)) : "memory")
#define MBAR_INVAL(mbar) \
    asm volatile("mbarrier.inval.shared.b64 [%0];" :: "r"((uint32_t)(mbar)) : "memory")
#define FENCE_PROXY() asm volatile("fence.proxy.async.shared::cta;" ::: "memory")

__device__ __forceinline__ void mbar_wait(uint32_t mbar, uint32_t parity) {
    uint32_t done;
    asm volatile("{\n\t.reg .pred p;\n\t"
                 "mbarrier.try_wait.parity.acquire.cta.shared::cta.b64 p, [%1], %2;\n\t"
                 "selp.b32 %0, 1, 0, p;\n\t}"
                 : "=r"(done) : "r"(mbar), "r"(parity) : "memory");
    if (!done) {
        asm volatile("{\n\t.reg .pred P1;\n\t"
                     "WL_%=:\n\t"
                     "mbarrier.try_wait.parity.acquire.cta.shared::cta.b64 P1, [%0], %1, 0x989680;\n\t"
                     "@P1 bra.uni WD_%=;\n\t"
                     "bra.uni WL_%=;\n\t"
                     "WD_%=:\n\t}"
                     :: "r"(mbar), "r"(parity) : "memory");
    }
}
__device__ __forceinline__ void tc_mma_f16_ss(uint32_t d, uint64_t ad, uint64_t bd,
                                              uint32_t idesc, bool en) {
    uint32_t e = en ? 1u : 0u, z = 0u;
    asm volatile("{\n\t.reg .pred p;\n\tsetp.ne.u32 p, %5, 0;\n\t"
                 "tcgen05.mma.cta_group::1.kind::f16 [%0], %1, %2, %3, {%4,%4,%4,%4}, p;\n\t}"
                 :: "r"(d), "l"(ad), "l"(bd), "r"(idesc), "r"(z), "r"(e) : "memory");
}
__device__ __forceinline__ uint32_t ld_shared_u32(uint32_t addr) {
    uint32_t v;
    asm volatile("ld.shared.b32 %0, [%1];" : "=r"(v) : "r"(addr));
    return v;
}
// SW128 smem descriptor, K-major: layout 2, version 1, SBO=64, LBO=1
__device__ __forceinline__ uint64_t make_desc(uint32_t addr) {
    const uint64_t base = (uint64_t(2) << 61) | (uint64_t(1) << 46)
                        | (uint64_t(64) << 32) | (uint64_t(1) << 16);
    return base | ((uint64_t)(addr >> 4) & 0x3FFF);
}
#define LDTM_X32(r, addr) \
    asm volatile("tcgen05.ld.sync.aligned.32x32b.x32.b32 " \
        "{%0,%1,%2,%3,%4,%5,%6,%7,%8,%9,%10,%11,%12,%13,%14,%15," \
        "%16,%17,%18,%19,%20,%21,%22,%23,%24,%25,%26,%27,%28,%29,%30,%31}, [%32];" \
        : "=r"((r)[0]),"=r"((r)[1]),"=r"((r)[2]),"=r"((r)[3]), \
          "=r"((r)[4]),"=r"((r)[5]),"=r"((r)[6]),"=r"((r)[7]), \
          "=r"((r)[8]),"=r"((r)[9]),"=r"((r)[10]),"=r"((r)[11]), \
          "=r"((r)[12]),"=r"((r)[13]),"=r"((r)[14]),"=r"((r)[15]), \
          "=r"((r)[16]),"=r"((r)[17]),"=r"((r)[18]),"=r"((r)[19]), \
          "=r"((r)[20]),"=r"((r)[21]),"=r"((r)[22]),"=r"((r)[23]), \
          "=r"((r)[24]),"=r"((r)[25]),"=r"((r)[26]),"=r"((r)[27]), \
          "=r"((r)[28]),"=r"((r)[29]),"=r"((r)[30]),"=r"((r)[31]) \
        : "r"(addr))
#endif // TCOK

// ---------------- layernorm ----------------
__global__ void ln_kernel(const float* __restrict__ x, const float* __restrict__ gamma,
                          float* __restrict__ out, __nv_bfloat16* __restrict__ ob) {
    long long row = blockIdx.x;
    const float* p = x + row * DD;
    float v[4];
    float s = 0.f, sq = 0.f;
#pragma unroll
    for (int i = 0; i < 4; i++) {
        v[i] = p[threadIdx.x + i * 256];
        s += v[i];
        sq += v[i] * v[i];
    }
    __shared__ float rs[8], rq[8];
#pragma unroll
    for (int o = 16; o; o >>= 1) {
        s  += __shfl_xor_sync(0xFFFFFFFFu, s, o);
        sq += __shfl_xor_sync(0xFFFFFFFFu, sq, o);
    }
    int w = threadIdx.x >> 5;
    if ((threadIdx.x & 31) == 0) { rs[w] = s; rq[w] = sq; }
    __syncthreads();
    if (threadIdx.x == 0) {
        float ts = 0.f, tq = 0.f;
        for (int i = 0; i < 8; i++) { ts += rs[i]; tq += rq[i]; }
        rs[0] = ts; rq[0] = tq;
    }
    __syncthreads();
    float mean = rs[0] * (1.f / (float)DD);
    float var  = rq[0] * (1.f / (float)DD) - mean * mean;
    float rstd = rsqrtf(var + 1e-5f);
    float* o = out + row * DD;
#pragma unroll
    for (int i = 0; i < 4; i++) {
        int d = threadIdx.x + i * 256;
        float val = gamma[d] * (v[i] - mean) * rstd;
        o[d] = val;
        if (ob) ob[row * DD + d] = __float2bfloat16(val);
    }
}

// ---------------- weight transpose + convert ----------------
__global__ void transpose_cvt_kernel(const float* __restrict__ in,
                                     __nv_bfloat16* __restrict__ out, int R, int C) {
    __shared__ float t[32][33];
    int c0 = blockIdx.x * 32, r0 = blockIdx.y * 32;
    for (int i = threadIdx.y; i < 32; i += 8)
        t[i][threadIdx.x] = in[(long long)(r0 + i) * C + c0 + threadIdx.x];
    __syncthreads();
    for (int i = threadIdx.y; i < 32; i += 8)
        out[(long long)(c0 + i) * R + r0 + threadIdx.x] = __float2bfloat16(t[threadIdx.x][i]);
}

// ---------------- phi transpose ----------------
__global__ void phiT_kernel(const float* __restrict__ phi, float* __restrict__ phiT) {
    int d = blockIdx.x * 256 + threadIdx.x;
#pragma unroll
    for (int e = 0; e < NSLOT; e++)
        phiT[e * DD + d] = phi[d * NSLOT + e];
}

// ---------------- v transpose ----------------
__global__ void vT_kernel(const __nv_bfloat16* __restrict__ kvb,
                          __nv_bfloat16* __restrict__ vT) {
    __shared__ __nv_bfloat16 t[32][33];
    int s0 = blockIdx.x * 32, d0 = blockIdx.y * 32, b = blockIdx.z;
    for (int i = threadIdx.y; i < 32; i += 8)
        t[i][threadIdx.x] = kvb[((long long)(b * SS + s0 + i)) * 128 + 64 + d0 + threadIdx.x];
    __syncthreads();
    for (int i = threadIdx.y; i < 32; i += 8)
        vT[((long long)(b * HD + d0 + i)) * SS + s0 + threadIdx.x] = t[threadIdx.x][i];
}

// ---------------- unified bf16 GEMM, templated N tile ----------------
// A [M,K] rm bf16; BT [N,K] rm bf16. BM=128, BN in {128,256}. 3-stage ring,
// one mbarrier per buffer (R11-proven). smem: hdr | A0 A1 A2 (16K) | B0 B1 B2 (BN*128).
template<int BN, bool ADD, bool OUTBF>
__global__ __launch_bounds__(256) __cluster_dims__(1, 1, 1) void gemm_kernel(
    const __nv_bfloat16* __restrict__ A, const __nv_bfloat16* __restrict__ BT,
    const float* __restrict__ AddP, float* __restrict__ Cf,
    __nv_bfloat16* __restrict__ Cb, int M, int N, int K, float alpha) {
    extern __shared__ char smraw[];
    uint32_t sb0 = smem_u32(smraw);
    uint32_t sbase = (sb0 + 1023u) & ~1023u;
    int tid = threadIdx.x, lane = tid & 31, wrp = tid >> 5;
    int row0 = blockIdx.y * 128, col0 = blockIdx.x * BN;
    const uint32_t T0 = sbase + 1024;
    const uint32_t BBUF = (uint32_t)BN * 128;

    auto loadA = [&](uint32_t off, int k0) {
#pragma unroll
        for (int i = 0; i < 4; i++) {
            int idx = i * 256 + tid;
            int r = idx >> 3, ch = idx & 7;
            cp16(off + r * 128 + ((ch ^ (r & 7)) << 4),
                 A + (long long)(row0 + r) * K + k0 + ch * 8);
        }
    };
    auto loadB = [&](uint32_t off, int k0) {
#pragma unroll
        for (int i = 0; i < BN / 32; i++) {
            int idx = i * 256 + tid;
            int r = idx >> 3, ch = idx & 7;
            cp16(off + r * 128 + ((ch ^ (r & 7)) << 4),
                 BT + (long long)(col0 + r) * K + k0 + ch * 8);
        }
    };
    int NT = K / 64;

#if TCOK
    const uint32_t BOFF = T0 + 3 * 16384;
    if (wrp == 0) { TC_ALLOC(sbase, BN); TC_RELINQ(); }
    if (tid == 0) {
        MBAR_INIT(sbase + 8, 1);
        MBAR_INIT(sbase + 16, 1);
        MBAR_INIT(sbase + 24, 1);
    }
    __syncthreads();
    uint32_t tmem = ld_shared_u32(sbase);
    const uint32_t IDESC = 0x490u | (((uint32_t)BN / 8) << 17) | (8u << 24);
    auto mb = [&](int i) -> uint32_t { return sbase + 8 + (uint32_t)i * 8; };

    loadA(T0, 0); loadB(BOFF, 0); cp_commit();
    if (NT > 1) { loadA(T0 + 16384, 64); loadB(BOFF + BBUF, 64); cp_commit(); }

    for (int t = 0; t < NT; t++) {
        uint32_t sA = T0 + (uint32_t)(t % 3) * 16384;
        uint32_t sB = BOFF + (uint32_t)(t % 3) * BBUF;
        if (t + 1 < NT) cp_wait<1>();
        else cp_wait<0>();
        FENCE_PROXY();
        __syncthreads();
        if (wrp == 0 && elect_one()) {
            uint64_t ad = make_desc(sA);
            uint64_t bd = make_desc(sB);
#pragma unroll
            for (int kk = 0; kk < 4; kk++)
                tc_mma_f16_ss(tmem, ad + kk * 2, bd + kk * 2, IDESC, (t > 0) || (kk > 0));
            TC_COMMIT(mb(t % 3));
        }
        if (t + 2 < NT) {
            if (t >= 1) mbar_wait(mb((t - 1) % 3), (uint32_t)(((t - 1) / 3) & 1));
            loadA(T0 + (uint32_t)((t + 2) % 3) * 16384, (t + 2) * 64);
            loadB(BOFF + (uint32_t)((t + 2) % 3) * BBUF, (t + 2) * 64);
            cp_commit();
        }
    }
    for (int tt = (NT >= 3 ? NT - 3 : 0); tt < NT; tt++)
        mbar_wait(mb(tt % 3), (uint32_t)((tt / 3) & 1));
    TC_FENCE_AFTER();

    {
        long long r = row0 + (wrp & 3) * 32 + lane;
        int cbase = (wrp >> 2) * (BN / 2);
#pragma unroll
        for (int cg = 0; cg < BN / 64; cg++) {
            uint32_t regs[32];
            LDTM_X32(regs, tmem + cbase + cg * 32);
            TC_WAIT_LD();
            int c0 = col0 + cbase + cg * 32;
            if (OUTBF) {
#pragma unroll
                for (int i = 0; i < 32; i += 2) {
                    __nv_bfloat162 p;
                    p.x = __float2bfloat16(__uint_as_float(regs[i]) * alpha);
                    p.y = __float2bfloat16(__uint_as_float(regs[i + 1]) * alpha);
                    *(__nv_bfloat162*)(Cb + r * N + c0 + i) = p;
                }
            } else {
#pragma unroll
                for (int i = 0; i < 32; i += 2) {
                    float v0 = __uint_as_float(regs[i]) * alpha;
                    float v1 = __uint_as_float(regs[i + 1]) * alpha;
                    if (ADD) {
                        float2 a = *(const float2*)(AddP + r * N + c0 + i);
                        v0 += a.x; v1 += a.y;
                    }
                    *(float2*)(Cf + r * N + c0 + i) = make_float2(v0, v1);
                }
            }
        }
    }
    TC_FENCE_BEFORE();
    __syncthreads();
    if (tid == 0) { MBAR_INVAL(mb(0)); MBAR_INVAL(mb(1)); MBAR_INVAL(mb(2)); }
    __syncthreads();
    if (wrp == 0) TC_DEALLOC(tmem, BN);
#else
    // HMMA fallback: process BN in 128-wide chunks (compile-correct; never runs on sm_103a)
    const __nv_bfloat16* As[2] = { (const __nv_bfloat16*)(smraw + (T0 - sb0)),
                                   (const __nv_bfloat16*)(smraw + (T0 - sb0) + 16384) };
    const __nv_bfloat16* Bs[2] = { (const __nv_bfloat16*)(smraw + (T0 - sb0) + 32768),
                                   (const __nv_bfloat16*)(smraw + (T0 - sb0) + 49152) };
    int wm = wrp >> 2, wn = wrp & 3;

    for (int cc = 0; cc < BN / 128; cc++) {
        int col0c = col0 + cc * 128;
        auto loadB128 = [&](uint32_t off, int k0) {
#pragma unroll
            for (int i = 0; i < 4; i++) {
                int idx = i * 256 + tid;
                int r = idx >> 3, ch = idx & 7;
                cp16(off + r * 128 + ((ch ^ (r & 7)) << 4),
                     BT + (long long)(col0c + r) * K + k0 + ch * 8);
            }
        };
        float acc[4][4][4];
#pragma unroll
        for (int mt = 0; mt < 4; mt++)
#pragma unroll
            for (int nt = 0; nt < 4; nt++)
#pragma unroll
                for (int i = 0; i < 4; i++) acc[mt][nt][i] = 0.f;

        loadA(T0, 0); loadB128(T0 + 32768, 0); cp_commit();
        for (int t = 0; t < NT; t++) {
            if (t + 1 < NT) {
                loadA(T0 + (uint32_t)((t + 1) & 1) * 16384, (t + 1) * 64);
                loadB128(T0 + 32768 + (uint32_t)((t + 1) & 1) * 16384, (t + 1) * 64);
                cp_commit();
                cp_wait<1>();
            } else cp_wait<0>();
            __syncthreads();
            const __nv_bfloat16* as = As[t & 1];
            const __nv_bfloat16* bs = Bs[t & 1];
#pragma unroll
            for (int kk = 0; kk < 4; kk++) {
                unsigned af[4][4], bf[2][4];
#pragma unroll
                for (int mt = 0; mt < 4; mt++) {
                    int r = wm * 64 + mt * 16 + (lane & 15);
                    int chunk = ((kk * 2 + (lane >> 4)) ^ (r & 7));
                    ldsm4(af[mt], smem_u32(as + r * 64 + chunk * 8));
                }
#pragma unroll
                for (int np = 0; np < 2; np++) {
                    int nrow = wn * 32 + (2 * np + ((lane >> 4) & 1)) * 8 + (lane & 7);
                    int chunk = ((kk * 2 + ((lane >> 3) & 1)) ^ (nrow & 7));
                    ldsm4(bf[np], smem_u32(bs + nrow * 64 + chunk * 8));
                }
#pragma unroll
                for (int mt = 0; mt < 4; mt++)
#pragma unroll
                    for (int nt = 0; nt < 4; nt++)
                        mma16816(acc[mt][nt], af[mt], bf[nt >> 1] + (nt & 1) * 2);
            }
            __syncthreads();
        }
#pragma unroll
        for (int mt = 0; mt < 4; mt++) {
#pragma unroll
            for (int nt = 0; nt < 4; nt++) {
                int r = row0 + wm * 64 + mt * 16 + (lane >> 2);
                int c = col0c + wn * 32 + nt * 8 + 2 * (lane & 3);
                float v0 = acc[mt][nt][0] * alpha, v1 = acc[mt][nt][1] * alpha;
                float v2 = acc[mt][nt][2] * alpha, v3 = acc[mt][nt][3] * alpha;
                if (OUTBF) {
                    __nv_bfloat162 p0; p0.x = __float2bfloat16(v0); p0.y = __float2bfloat16(v1);
                    __nv_bfloat162 p1; p1.x = __float2bfloat16(v2); p1.y = __float2bfloat16(v3);
                    *(__nv_bfloat162*)(Cb + (long long)r * N + c) = p0;
                    *(__nv_bfloat162*)(Cb + (long long)(r + 8) * N + c) = p1;
                } else {
                    if (ADD) {
                        float2 a0 = *(const float2*)(AddP + (long long)r * N + c);
                        float2 a1 = *(const float2*)(AddP + (long long)(r + 8) * N + c);
                        v0 += a0.x; v1 += a0.y; v2 += a1.x; v3 += a1.y;
                    }
                    *(float2*)(Cf + (long long)r * N + c) = make_float2(v0, v1);
                    *(float2*)(Cf + (long long)(r + 8) * N + c) = make_float2(v2, v3);
                }
            }
        }
        __syncthreads();
    }
#endif
}

// ---------------- flash attention: R15 pipelined version (passing, unchanged) ----------------
__global__ __launch_bounds__(256) __cluster_dims__(1, 1, 1) void flash_kernel(
    const __nv_bfloat16* __restrict__ qb, const __nv_bfloat16* __restrict__ kvb,
    const __nv_bfloat16* __restrict__ vT, __nv_bfloat16* __restrict__ ccb) {
    int tid = threadIdx.x, lane = tid & 31, wrp = tid >> 5;
    int b = blockIdx.y >> 4, h = blockIdx.y & 15;
    long long qrow0 = (long long)b * SS + blockIdx.x * 128;

#if TCOK
    extern __shared__ char smraw[];
    uint32_t sb0 = smem_u32(smraw);
    uint32_t sbase = (sb0 + 1023u) & ~1023u;
    const uint32_t QOFF = sbase + 2048;
    const uint32_t K0 = QOFF + 16384;
    const uint32_t V0 = K0 + 16384;
    const uint32_t POFF = V0 + 16384;
    float* lsp = (float*)(smraw + (sbase - sb0) + 512);
    char* pgen = smraw + (POFF - sb0);

    if (wrp == 0) { TC_ALLOC(sbase, 128); TC_RELINQ(); }
    if (tid == 0) { MBAR_INIT(sbase + 8, 1); MBAR_INIT(sbase + 16, 1); }
    __syncthreads();
    uint32_t tmem = ld_shared_u32(sbase);
    const uint32_t mbS = sbase + 8, mbP = sbase + 16;
    const int S_OFF = 0, O_OFF = 64;

#pragma unroll
    for (int i = 0; i < 4; i++) {
        int idx = i * 256 + tid;
        int r = idx >> 3, ch = idx & 7;
        cp16(QOFF + r * 128 + ((ch ^ (r & 7)) << 4),
             qb + (qrow0 + r) * DD + h * 64 + ch * 8);
    }
    auto loadKV = [&](int buf, int kt) {
#pragma unroll
        for (int i = 0; i < 2; i++) {
            int idx = i * 256 + tid;
            int r = idx >> 3, ch = idx & 7;
            uint32_t sw = r * 128 + ((ch ^ (r & 7)) << 4);
            cp16(K0 + buf * 8192 + sw,
                 kvb + ((long long)b * SS + kt * 64 + r) * 128 + ch * 8);
            cp16(V0 + buf * 8192 + sw,
                 vT + ((long long)(b * HD + r)) * SS + kt * 64 + ch * 8);
        }
        cp_commit();
    };

    const uint32_t IDESC = 0x490u | (8u << 17) | (8u << 24);
    int my_half = wrp >> 2;
    int rrow = (wrp & 3) * 32 + lane;
    float ls = 0.f;
    uint64_t qd = make_desc(QOFF);
    const int NKT = SS / 64;

    loadKV(0, 0);
    cp_wait<0>();
    FENCE_PROXY();
    __syncthreads();
    if (wrp == 0 && elect_one()) {
        uint64_t kd = make_desc(K0);
#pragma unroll
        for (int kk = 0; kk < 4; kk++)
            tc_mma_f16_ss(tmem + S_OFF, qd + kk * 2, kd + kk * 2, IDESC, kk > 0);
        TC_COMMIT(mbS);
    }

    for (int kt = 0; kt < NKT; kt++) {
        mbar_wait(mbS, (uint32_t)(kt & 1));
        TC_FENCE_AFTER();
        if (kt >= 1) mbar_wait(mbP, (uint32_t)((kt - 1) & 1));
        if (kt + 1 < NKT) loadKV((kt + 1) & 1, kt + 1);

        uint32_t sreg[32];
        LDTM_X32(sreg, tmem + S_OFF + my_half * 32);
        TC_WAIT_LD();
        float p[32];
#pragma unroll
        for (int i = 0; i < 32; i++) {
            p[i] = ex2(__uint_as_float(sreg[i]));
            ls += p[i];
        }
        uint32_t pw[16];
#pragma unroll
        for (int i = 0; i < 16; i++) pw[i] = pack_bf16(p[2 * i], p[2 * i + 1]);
#pragma unroll
        for (int j = 0; j < 4; j++) {
            int ch = my_half * 4 + j;
            *(uint4*)(pgen + rrow * 128 + ((ch ^ (rrow & 7)) << 4)) =
                make_uint4(pw[4 * j], pw[4 * j + 1], pw[4 * j + 2], pw[4 * j + 3]);
        }
        FENCE_PROXY();
        TC_FENCE_BEFORE();
        __syncthreads();

        if (wrp == 0 && elect_one()) {
            TC_FENCE_AFTER();
            uint64_t pd = make_desc(POFF);
            uint64_t vd = make_desc(V0 + (uint32_t)(kt & 1) * 8192);
#pragma unroll
            for (int kk = 0; kk < 4; kk++)
                tc_mma_f16_ss(tmem + O_OFF, pd + kk * 2, vd + kk * 2,
                              IDESC, (kt > 0) || (kk > 0));
            TC_COMMIT(mbP);
        }

        if (kt + 1 < NKT) {
            cp_wait<0>();
            FENCE_PROXY();
            __syncthreads();
            if (wrp == 0 && elect_one()) {
                uint64_t kd = make_desc(K0 + (uint32_t)((kt + 1) & 1) * 8192);
#pragma unroll
                for (int kk = 0; kk < 4; kk++)
                    tc_mma_f16_ss(tmem + S_OFF, qd + kk * 2, kd + kk * 2, IDESC, kk > 0);
                TC_COMMIT(mbS);
            }
        }
    }
    mbar_wait(mbP, (uint32_t)((NKT - 1) & 1));
    TC_FENCE_AFTER();

    lsp[my_half * 128 + rrow] = ls;
    __syncthreads();
    float inv = 1.f / (lsp[rrow] + lsp[128 + rrow]);

    uint32_t oreg[32];
    LDTM_X32(oreg, tmem + O_OFF + my_half * 32);
    TC_WAIT_LD();
    long long gr = qrow0 + rrow;
    int c0 = h * 64 + my_half * 32;
#pragma unroll
    for (int i = 0; i < 32; i += 2) {
        __nv_bfloat162 pv;
        pv.x = __float2bfloat16(__uint_as_float(oreg[i]) * inv);
        pv.y = __float2bfloat16(__uint_as_float(oreg[i + 1]) * inv);
        *(__nv_bfloat162*)(ccb + gr * DD + c0 + i) = pv;
    }
    TC_FENCE_BEFORE();
    __syncthreads();
    if (tid == 0) { MBAR_INVAL(mbS); MBAR_INVAL(mbP); }
    __syncthreads();
    if (wrp == 0) TC_DEALLOC(tmem, 128);
#else
    // ================= HMMA fallback (R6 version) =================
    __shared__ __nv_bfloat16 Qs[128 * 64];
    __shared__ __nv_bfloat16 Ks[2][64 * 64];
    __shared__ __nv_bfloat16 Vs[2][64 * 64];
    int w = wrp;

    auto loadKV = [&](int st, int kt) {
#pragma unroll
        for (int i = 0; i < 2; i++) {
            int idx = i * 2048 + tid * 8;
            int r = idx >> 6, c = idx & 63;
            int chunk = (c >> 3) ^ (r & 7);
            long long grow = (long long)b * SS + kt * 64 + r;
            cp16(smem_u32(&Ks[st][r * 64 + chunk * 8]), kvb + grow * 128 + c);
            cp16(smem_u32(&Vs[st][r * 64 + chunk * 8]), kvb + grow * 128 + 64 + c);
        }
        cp_commit();
    };

#pragma unroll
    for (int i = 0; i < 4; i++) {
        int idx = i * 2048 + tid * 8;
        int r = idx >> 6, c = idx & 63;
        int chunk = (c >> 3) ^ (r & 7);
        cp16(smem_u32(Qs + r * 64 + chunk * 8), qb + (qrow0 + r) * DD + h * 64 + c);
    }
    loadKV(0, 0);
    cp_wait<0>();
    __syncthreads();

    unsigned qa[4][4];
    {
        int r = w * 16 + (lane & 15);
#pragma unroll
        for (int kk = 0; kk < 4; kk++) {
            int chunk = ((kk * 2 + (lane >> 4)) ^ (r & 7));
            ldsm4(qa[kk], smem_u32(Qs + r * 64 + chunk * 8));
        }
    }

    float o[8][4];
#pragma unroll
    for (int nt = 0; nt < 8; nt++)
#pragma unroll
        for (int i = 0; i < 4; i++) o[nt][i] = 0.f;
    float ls0 = 0.f, ls1 = 0.f;

    for (int kt = 0; kt < SS / 64; kt++) {
        if (kt + 1 < SS / 64) { loadKV((kt + 1) & 1, kt + 1); cp_wait<1>(); }
        else cp_wait<0>();
        __syncthreads();
        const __nv_bfloat16* ks = Ks[kt & 1];
        const __nv_bfloat16* vs = Vs[kt & 1];

        float sf[8][4];
#pragma unroll
        for (int nt = 0; nt < 8; nt++)
#pragma unroll
            for (int i = 0; i < 4; i++) sf[nt][i] = 0.f;
#pragma unroll
        for (int kk = 0; kk < 4; kk++) {
#pragma unroll
            for (int np = 0; np < 4; np++) {
                unsigned bbf[4];
                int krow = (2 * np + ((lane >> 4) & 1)) * 8 + (lane & 7);
                int chunk = ((kk * 2 + ((lane >> 3) & 1)) ^ (krow & 7));
                ldsm4(bbf, smem_u32(ks + krow * 64 + chunk * 8));
                mma16816(sf[2 * np], qa[kk], bbf);
                mma16816(sf[2 * np + 1], qa[kk], bbf + 2);
            }
        }
#pragma unroll
        for (int nt = 0; nt < 8; nt++) {
            sf[nt][0] = ex2(sf[nt][0]);
            sf[nt][1] = ex2(sf[nt][1]);
            sf[nt][2] = ex2(sf[nt][2]);
            sf[nt][3] = ex2(sf[nt][3]);
            ls0 += sf[nt][0] + sf[nt][1];
            ls1 += sf[nt][2] + sf[nt][3];
        }
#pragma unroll
        for (int j = 0; j < 4; j++) {
            unsigned pa[4];
            pa[0] = pack_bf16(sf[2 * j][0], sf[2 * j][1]);
            pa[1] = pack_bf16(sf[2 * j][2], sf[2 * j][3]);
            pa[2] = pack_bf16(sf[2 * j + 1][0], sf[2 * j + 1][1]);
            pa[3] = pack_bf16(sf[2 * j + 1][2], sf[2 * j + 1][3]);
#pragma unroll
            for (int np = 0; np < 4; np++) {
                unsigned vv[4];
                int vrow = j * 16 + (lane & 7) + ((lane >> 3) & 1) * 8;
                int cgrp = 2 * np + ((lane >> 4) & 1);
                int chunk = (cgrp ^ (vrow & 7));
                ldsm4t(vv, smem_u32(vs + vrow * 64 + chunk * 8));
                mma16816(o[2 * np], pa, vv);
                mma16816(o[2 * np + 1], pa, vv + 2);
            }
        }
        __syncthreads();
    }

    ls0 += __shfl_xor_sync(0xFFFFFFFFu, ls0, 1);
    ls0 += __shfl_xor_sync(0xFFFFFFFFu, ls0, 2);
    ls1 += __shfl_xor_sync(0xFFFFFFFFu, ls1, 1);
    ls1 += __shfl_xor_sync(0xFFFFFFFFu, ls1, 2);
    float inv0 = 1.f / ls0, inv1 = 1.f / ls1;

    long long gr = qrow0 + w * 16 + (lane >> 2);
#pragma unroll
    for (int nt = 0; nt < 8; nt++) {
        int c = h * 64 + nt * 8 + 2 * (lane & 3);
        __nv_bfloat162 p0, p1;
        p0.x = __float2bfloat16(o[nt][0] * inv0);
        p0.y = __float2bfloat16(o[nt][1] * inv0);
        p1.x = __float2bfloat16(o[nt][2] * inv1);
        p1.y = __float2bfloat16(o[nt][3] * inv1);
        *(__nv_bfloat162*)(ccb + gr * DD + c) = p0;
        *(__nv_bfloat162*)(ccb + (gr + 8) * DD + c) = p1;
    }
#endif
}

// ---------------- logits + dispatch softmax: 4 rows per block, phiT reg-reuse ----------------
__global__ __launch_bounds__(128) void logits_kernel(
    const float* __restrict__ m, const float* __restrict__ phiT,
    float* __restrict__ logits, float* __restrict__ dispatch) {
    __shared__ float4 msv[4][DD / 4];
    __shared__ float part[4][8][NSLOT];
    __shared__ float lsm[4][NSLOT];
    long long row0 = (long long)blockIdx.x * 4;
    int tid = threadIdx.x;
    const float4* mr = (const float4*)(m + row0 * DD);
#pragma unroll
    for (int i = 0; i < 8; i++) {
        int idx = i * 128 + tid;
        msv[idx >> 8][idx & 255] = mr[idx];
    }
    __syncthreads();
    int e = tid & 15, seg = tid >> 4;
    const float4* pe = (const float4*)(phiT + e * DD) + seg * 32;
    float a0 = 0.f, a1 = 0.f, a2 = 0.f, a3 = 0.f;
#pragma unroll
    for (int i = 0; i < 32; i++) {
        float4 pv = pe[i];
        int idx = seg * 32 + i;
        float4 m0 = msv[0][idx];
        float4 m1 = msv[1][idx];
        float4 m2 = msv[2][idx];
        float4 m3 = msv[3][idx];
        a0 += m0.x * pv.x + m0.y * pv.y + m0.z * pv.z + m0.w * pv.w;
        a1 += m1.x * pv.x + m1.y * pv.y + m1.z * pv.z + m1.w * pv.w;
        a2 += m2.x * pv.x + m2.y * pv.y + m2.z * pv.z + m2.w * pv.w;
        a3 += m3.x * pv.x + m3.y * pv.y + m3.z * pv.z + m3.w * pv.w;
    }
    part[0][seg][e] = a0;
    part[1][seg][e] = a1;
    part[2][seg][e] = a2;
    part[3][seg][e] = a3;
    __syncthreads();
    if (tid < 64) {
        int r = tid >> 4, ee = tid & 15;
        float l = 0.f;
#pragma unroll
        for (int s = 0; s < 8; s++) l += part[r][s][ee];
        logits[(row0 + r) * NSLOT + ee] = l;
        lsm[r][ee] = l;
    }
    __syncthreads();
    if (tid < 64) {
        int r = tid >> 4, ee = tid & 15;
        float mx = lsm[r][0];
        for (int j = 1; j < NSLOT; j++) mx = fmaxf(mx, lsm[r][j]);
        float s = 0.f;
        for (int j = 0; j < NSLOT; j++) s += expf(lsm[r][j] - mx);
        dispatch[(row0 + r) * NSLOT + ee] = expf(lsm[r][ee] - mx) / s;
    }
}

// ---------------- combine softmax over sequence axis ----------------
__global__ void combine_kernel(const float* __restrict__ logits, float* __restrict__ comb) {
    int b = blockIdx.x >> 4, e = blockIdx.x & 15;
    const float* base = logits + ((long long)b * SS) * NSLOT + e;
    float v[8];
    float mx = -1e30f;
#pragma unroll
    for (int i = 0; i < 8; i++) {
        int s = threadIdx.x + i * 256;
        v[i] = base[(long long)s * NSLOT];
        mx = fmaxf(mx, v[i]);
    }
    __shared__ float red[8];
#pragma unroll
    for (int o = 16; o; o >>= 1) mx = fmaxf(mx, __shfl_xor_sync(0xFFFFFFFFu, mx, o));
    int w = threadIdx.x >> 5;
    if ((threadIdx.x & 31) == 0) red[w] = mx;
    __syncthreads();
    if (threadIdx.x == 0) {
        float t = red[0];
        for (int i = 1; i < 8; i++) t = fmaxf(t, red[i]);
        red[0] = t;
    }
    __syncthreads();
    mx = red[0];
    __syncthreads();
    float s = 0.f;
#pragma unroll
    for (int i = 0; i < 8; i++) { v[i] = expf(v[i] - mx); s += v[i]; }
#pragma unroll
    for (int o = 16; o; o >>= 1) s += __shfl_xor_sync(0xFFFFFFFFu, s, o);
    if ((threadIdx.x & 31) == 0) red[w] = s;
    __syncthreads();
    if (threadIdx.x == 0) {
        float t = 0.f;
        for (int i = 0; i < 8; i++) t += red[i];
        red[0] = t;
    }
    __syncthreads();
    float inv = 1.0f / red[0];
    float* ob = comb + ((long long)b * SS) * NSLOT + e;
#pragma unroll
    for (int i = 0; i < 8; i++) {
        int sidx = threadIdx.x + i * 256;
        ob[(long long)sidx * NSLOT] = v[i] * inv;
    }
}

// ---------------- xs partials + reduce ----------------
__global__ void xs_part_kernel(const float* __restrict__ dispatch, const float* __restrict__ m,
                               float* __restrict__ part) {
    int d = blockIdx.x * 256 + threadIdx.x;
    int b = blockIdx.y, seg = blockIdx.z;
    int s0 = seg * SCHUNK;
    __shared__ __align__(16) float ds[SCHUNK][NSLOT];
    for (int i = threadIdx.x; i < SCHUNK * NSLOT; i += 256)
        ds[i >> 4][i & 15] = dispatch[((long long)b * SS + s0) * NSLOT + i];
    __syncthreads();
    float acc[NSLOT];
#pragma unroll
    for (int e = 0; e < NSLOT; e++) acc[e] = 0.f;
    const float* mb = m + ((long long)b * SS + s0) * DD + d;
    for (int s = 0; s < SCHUNK; s++) {
        float mv = mb[(long long)s * DD];
        const float4* dr = (const float4*)ds[s];
#pragma unroll
        for (int q = 0; q < 4; q++) {
            float4 dv = dr[q];
            acc[q * 4 + 0] += dv.x * mv;
            acc[q * 4 + 1] += dv.y * mv;
            acc[q * 4 + 2] += dv.z * mv;
            acc[q * 4 + 3] += dv.w * mv;
        }
    }
#pragma unroll
    for (int e = 0; e < NSLOT; e++)
        part[(((long long)seg * BB + b) * NSLOT + e) * DD + d] = acc[e];
}

__global__ void xs_reduce_kernel(const float* __restrict__ part, float* __restrict__ xs) {
    int i = blockIdx.x * 256 + threadIdx.x;
    float a = 0.f;
#pragma unroll
    for (int seg = 0; seg < SSEG; seg++)
        a += part[(long long)seg * BB * NSLOT * DD + i];
    xs[i] = a;
}

// ---------------- expert FFN1 partials: h1p[ds][r][e][f] (float4 w1 loads) ----------------
__global__ __launch_bounds__(256) void ffn1_kernel(
    const float* __restrict__ xs, const float* __restrict__ w1,
    float* __restrict__ h1p) {
    int e = blockIdx.x, fs = blockIdx.y, ds = blockIdx.z;
    int f0 = fs * F1CH, d0 = ds * D1CH;
    int tid = threadIdx.x;
    __shared__ __align__(16) float xst[D1CH][8];
    for (int i = tid; i < D1CH * 8; i += 256) {
        int d = i & (D1CH - 1), r = i >> 8;  // D1CH==256
        int b = r >> 1, slot = r & 1;
        xst[d][r] = xs[((long long)(b * NSLOT + e * 2 + slot)) * DD + d0 + d];
    }
    __syncthreads();
    float4 acc[8];
#pragma unroll
    for (int r = 0; r < 8; r++) acc[r] = make_float4(0.f, 0.f, 0.f, 0.f);
    const float4* w = (const float4*)(w1 + (long long)e * DD * DFF
                                      + (long long)d0 * DFF + f0) + tid;
    for (int d = 0; d < D1CH; d++) {
        float4 wv = w[(long long)d * (DFF / 4)];
        float4 x0 = *(const float4*)&xst[d][0];
        float4 x1 = *(const float4*)&xst[d][4];
        acc[0].x += wv.x * x0.x; acc[0].y += wv.y * x0.x; acc[0].z += wv.z * x0.x; acc[0].w += wv.w * x0.x;
        acc[1].x += wv.x * x0.y; acc[1].y += wv.y * x0.y; acc[1].z += wv.z * x0.y; acc[1].w += wv.w * x0.y;
        acc[2].x += wv.x * x0.z; acc[2].y += wv.y * x0.z; acc[2].z += wv.z * x0.z; acc[2].w += wv.w * x0.z;
        acc[3].x += wv.x * x0.w; acc[3].y += wv.y * x0.w; acc[3].z += wv.z * x0.w; acc[3].w += wv.w * x0.w;
        acc[4].x += wv.x * x1.x; acc[4].y += wv.y * x1.x; acc[4].z += wv.z * x1.x; acc[4].w += wv.w * x1.x;
        acc[5].x += wv.x * x1.y; acc[5].y += wv.y * x1.y; acc[5].z += wv.z * x1.y; acc[5].w += wv.w * x1.y;
        acc[6].x += wv.x * x1.z; acc[6].y += wv.y * x1.z; acc[6].z += wv.z * x1.z; acc[6].w += wv.w * x1.z;
        acc[7].x += wv.x * x1.w; acc[7].y += wv.y * x1.w; acc[7].z += wv.z * x1.w; acc[7].w += wv.w * x1.w;
    }
#pragma unroll
    for (int r = 0; r < 8; r++) {
        *(float4*)(h1p + (((long long)ds * 8 + r) * EE + e) * DFF + f0 + tid * 4) = acc[r];
    }
}

// ---------------- h1 reduce + bias + gelu -> hidT[e][f][r] ----------------
__global__ void h1_reduce_kernel(const float* __restrict__ h1p, const float* __restrict__ b1,
                                 float* __restrict__ hidT) {
    int i = blockIdx.x * 256 + threadIdx.x;      // over 8 * EE * DFF
    int r = i / (EE * DFF);
    int rem = i - r * (EE * DFF);                // e*DFF + f
    float a = b1[rem];
#pragma unroll
    for (int ds = 0; ds < DS1; ds++)
        a += h1p[((long long)ds * 8 + r) * EE * DFF + rem];
    hidT[(long long)rem * 8 + r] = 0.5f * a * (1.0f + erff(a * 0.70710678118654752f));
}

// ---------------- expert FFN2 partials: ysp[fs][row][d] ----------------
__global__ __launch_bounds__(256) void ffn2_kernel(
    const float* __restrict__ hidT, const float* __restrict__ w2,
    float* __restrict__ ysp) {
    int e = blockIdx.x, fs = blockIdx.y;
    int f0 = fs * FCH;
    int tid = threadIdx.x;
    __shared__ __align__(16) float hs[FCH][8];
    for (int i = tid; i < FCH * 8; i += 256) {
        int f = i >> 3, r = i & 7;
        hs[f][r] = hidT[((long long)e * DFF + f0 + f) * 8 + r];
    }
    __syncthreads();
    float4 acc[8];
#pragma unroll
    for (int r = 0; r < 8; r++) acc[r] = make_float4(0.f, 0.f, 0.f, 0.f);
    const float4* w = (const float4*)(w2 + (long long)e * DFF * DD + (long long)f0 * DD) + tid;
    for (int f = 0; f < FCH; f++) {
        float4 wv = w[(long long)f * (DD / 4)];
        float4 h0 = *(const float4*)&hs[f][0];
        float4 h1 = *(const float4*)&hs[f][4];
        acc[0].x += wv.x * h0.x; acc[0].y += wv.y * h0.x; acc[0].z += wv.z * h0.x; acc[0].w += wv.w * h0.x;
        acc[1].x += wv.x * h0.y; acc[1].y += wv.y * h0.y; acc[1].z += wv.z * h0.y; acc[1].w += wv.w * h0.y;
        acc[2].x += wv.x * h0.z; acc[2].y += wv.y * h0.z; acc[2].z += wv.z * h0.z; acc[2].w += wv.w * h0.z;
        acc[3].x += wv.x * h0.w; acc[3].y += wv.y * h0.w; acc[3].z += wv.z * h0.w; acc[3].w += wv.w * h0.w;
        acc[4].x += wv.x * h1.x; acc[4].y += wv.y * h1.x; acc[4].z += wv.z * h1.x; acc[4].w += wv.w * h1.x;
        acc[5].x += wv.x * h1.y; acc[5].y += wv.y * h1.y; acc[5].z += wv.z * h1.y; acc[5].w += wv.w * h1.y;
        acc[6].x += wv.x * h1.z; acc[6].y += wv.y * h1.z; acc[6].z += wv.z * h1.z; acc[6].w += wv.w * h1.z;
        acc[7].x += wv.x * h1.w; acc[7].y += wv.y * h1.w; acc[7].z += wv.z * h1.w; acc[7].w += wv.w * h1.w;
    }
#pragma unroll
    for (int r = 0; r < 8; r++) {
        int b = r >> 1, slot = r & 1;
        int rowl = b * NSLOT + e * 2 + slot;
        *(float4*)(ysp + ((long long)fs * BB * NSLOT + rowl) * DD + tid * 4) = acc[r];
    }
}

// ---------------- ys reduce + bias ----------------
__global__ void ys_reduce_kernel(const float* __restrict__ ysp, const float* __restrict__ b2,
                                 float* __restrict__ ys) {
    int i = blockIdx.x * 256 + threadIdx.x;   // over BB*NSLOT*DD
    int row = i >> 10, d = i & 1023;
    int e = (row & 15) >> 1;
    float a = b2[e * DD + d];
#pragma unroll
    for (int fs = 0; fs < FSEG; fs++)
        a += ysp[(long long)fs * BB * NSLOT * DD + i];
    ys[i] = a;
}

// ---------------- final: out = m + combine @ ys (row per block, float4) ----------------
__global__ __launch_bounds__(256) void final_kernel(
    const float* __restrict__ m, const float* __restrict__ comb,
    const float* __restrict__ ys, float* __restrict__ out) {
    long long row = blockIdx.x;
    int b = (int)(row >> 11);
    int tid = threadIdx.x;
    __shared__ float cs[NSLOT];
    if (tid < NSLOT) cs[tid] = comb[row * NSLOT + tid];
    __syncthreads();
    float4 acc = *(const float4*)(m + row * DD + tid * 4);
    const float* yb = ys + (long long)b * NSLOT * DD + tid * 4;
#pragma unroll
    for (int j = 0; j < NSLOT; j++) {
        float4 yv = *(const float4*)(yb + (long long)j * DD);
        float c = cs[j];
        acc.x += c * yv.x; acc.y += c * yv.y;
        acc.z += c * yv.z; acc.w += c * yv.w;
    }
    *(float4*)(out + row * DD + tid * 4) = acc;
}

// ---------------- launch ----------------
extern "C" void kernel_launch(void* const* d_in, const int* in_sizes, int n_in,
                              void* d_out, int out_size) {
    const float* x        = (const float*)d_in[0];
    const float* wq       = (const float*)d_in[1];
    const float* wkv      = (const float*)d_in[2];
    const float* wo       = (const float*)d_in[3];
    const float* gm_attn  = (const float*)d_in[4];
    const float* gm_moe   = (const float*)d_in[5];
    const float* phi      = (const float*)d_in[6];
    const float* w1       = (const float*)d_in[7];
    const float* b1       = (const float*)d_in[8];
    const float* w2       = (const float*)d_in[9];
    const float* b2       = (const float*)d_in[10];
    float* out = (float*)d_out;

    float *h, *x1, *m, *lg, *dp, *cb, *xs, *xsp, *h1p, *hidT, *ysp, *ys, *phiT;
    __nv_bfloat16 *hb, *qb, *kvb, *vt, *ccb, *wqT, *wkvT, *woT;
    cudaGetSymbolAddress((void**)&h,    g_h);
    cudaGetSymbolAddress((void**)&hb,   g_hb);
    cudaGetSymbolAddress((void**)&qb,   g_qb);
    cudaGetSymbolAddress((void**)&kvb,  g_kvb);
    cudaGetSymbolAddress((void**)&vt,   g_vT);
    cudaGetSymbolAddress((void**)&ccb,  g_ccb);
    cudaGetSymbolAddress((void**)&wqT,  g_wqT);
    cudaGetSymbolAddress((void**)&wkvT, g_wkvT);
    cudaGetSymbolAddress((void**)&woT,  g_woT);
    cudaGetSymbolAddress((void**)&phiT, g_phiT);
    cudaGetSymbolAddress((void**)&x1,   g_x1);
    cudaGetSymbolAddress((void**)&m,    g_m);
    cudaGetSymbolAddress((void**)&lg,   g_logits);
    cudaGetSymbolAddress((void**)&dp,   g_dispatch);
    cudaGetSymbolAddress((void**)&cb,   g_combine);
    cudaGetSymbolAddress((void**)&xs,   g_xs);
    cudaGetSymbolAddress((void**)&xsp,  g_xs_part);
    cudaGetSymbolAddress((void**)&h1p,  g_h1p);
    cudaGetSymbolAddress((void**)&hidT, g_hidT);
    cudaGetSymbolAddress((void**)&ysp,  g_ys_part);
    cudaGetSymbolAddress((void**)&ys,   g_ys);

    const int G_SMEM128 = 2048 + 3 * 16384 + 3 * 128 * 128; // 100352
    const int G_SMEM256 = 2048 + 3 * 16384 + 3 * 256 * 128; // 149504
    cudaFuncSetAttribute(gemm_kernel<256, false, true>,
                         cudaFuncAttributeMaxDynamicSharedMemorySize, G_SMEM256);
    cudaFuncSetAttribute(gemm_kernel<128, false, true>,
                         cudaFuncAttributeMaxDynamicSharedMemorySize, G_SMEM128);
    cudaFuncSetAttribute(gemm_kernel<256, true, false>,
                         cudaFuncAttributeMaxDynamicSharedMemorySize, G_SMEM256);
    const int F_SMEM = 1024 + 2048 + 4 * 16384;
    cudaFuncSetAttribute(flash_kernel,
                         cudaFuncAttributeMaxDynamicSharedMemorySize, F_SMEM);

    // 0) ln: h = LN(x), hb
    ln_kernel<<<ROWS, 256>>>(x, gm_attn, h, hb);
    // 1) wq transpose
    transpose_cvt_kernel<<<dim3(32, 32), dim3(32, 8)>>>(wq, wqT, DD, DD);
    // 2) wkv transpose
    transpose_cvt_kernel<<<dim3(4, 32), dim3(32, 8)>>>(wkv, wkvT, DD, 128);
    // 3) gemm_q (BN=256; ncu capture slot)
    gemm_kernel<256, false, true><<<dim3(4, 64), 256, G_SMEM256>>>(
        hb, wqT, nullptr, nullptr, qb, ROWS, DD, DD, 0.125f * 1.4426950408889634f);
    // 4) wo transpose
    transpose_cvt_kernel<<<dim3(32, 32), dim3(32, 8)>>>(wo, woT, DD, DD);
    // 5) phi transpose
    phiT_kernel<<<DD / 256, 256>>>(phi, phiT);
    // 6) gemm_kv (BN=128)
    gemm_kernel<128, false, true><<<dim3(1, 64), 256, G_SMEM128>>>(
        hb, wkvT, nullptr, nullptr, kvb, ROWS, 128, DD, 1.0f);
    // 7) vT
    vT_kernel<<<dim3(SS / 32, HD / 32, BB), dim3(32, 8)>>>(kvb, vt);
    // 8) flash (pipelined)
    flash_kernel<<<dim3(SS / 128, BB * HH), 256, F_SMEM>>>(qb, kvb, vt, ccb);
    // 9) x1 = concat @ wo + h (BN=256)
    gemm_kernel<256, true, false><<<dim3(4, 64), 256, G_SMEM256>>>(
        ccb, woT, h, x1, nullptr, ROWS, DD, DD, 1.0f);
    // 10) m = LN(x1)
    ln_kernel<<<ROWS, 256>>>(x1, gm_moe, m, nullptr);
    // 11) logits + dispatch (4 rows per block)
    logits_kernel<<<ROWS / 4, 128>>>(m, phiT, lg, dp);
    // 12) combine
    combine_kernel<<<BB * NSLOT, 256>>>(lg, cb);
    // 13) xs partials
    xs_part_kernel<<<dim3(DD / 256, BB, SSEG), 256>>>(dp, m, xsp);
    // 14) xs reduce
    xs_reduce_kernel<<<(BB * NSLOT * DD) / 256, 256>>>(xsp, xs);
    // 15) ffn1 partials
    ffn1_kernel<<<dim3(EE, FS1, DS1), 256>>>(xs, w1, h1p);
    // 16) h1 reduce + bias + gelu
    h1_reduce_kernel<<<(8 * EE * DFF) / 256, 256>>>(h1p, b1, hidT);
    // 17) ffn2 partials
    ffn2_kernel<<<dim3(EE, FSEG), 256>>>(hidT, w2, ysp);
    // 18) ys reduce + bias
    ys_reduce_kernel<<<(BB * NSLOT * DD) / 256, 256>>>(ysp, b2, ys);
    // 19) final
    final_kernel<<<ROWS, 256>>>(m, cb, ys, out);
}

// round 17
// speedup vs baseline: 4.7163x; 1.1288x over previous
#include <cuda_runtime.h>
#include <cuda_bf16.h>
#include <math.h>
#include <stdint.h>

// Problem constants
#define BB 4
#define SS 2048
#define DD 1024
#define HH 16
#define HD 64
#define EE 8
#define DFF 4096
#define NSLOT 16        // E*SLOTS
#define ROWS (BB*SS)    // 8192
#define SSEG 16
#define SCHUNK (SS/SSEG)  // 128
#define FSEG 32
#define FCH (DFF/FSEG)    // 128
#define FS1 4
#define DS1 8
#define F1CH (DFF/FS1)    // 1024
#define D1CH (DD/DS1)     // 128

// tcgen05 availability: only in arch-specific (sm_103a/sm_100a-family) device pass
#if defined(__CUDA_ARCH__) && (defined(__CUDA_ARCH_FEAT_SM103_ALL) || defined(__CUDA_ARCH_FEAT_SM100_ALL) || defined(__CUDA_ARCH_SPECIFIC__) || defined(__CUDA_ARCH_FAMILY_SPECIFIC__))
#define TCOK 1
#else
#define TCOK 0
#endif

// ---------------- scratch (static __device__ globals; no allocation) ----------------
__device__ float g_h[ROWS * DD];
__device__ __nv_bfloat16 g_hb[ROWS * DD];
__device__ __nv_bfloat16 g_qb[ROWS * DD];
__device__ __nv_bfloat16 g_kvb[ROWS * 128];
__device__ __nv_bfloat16 g_vT[BB * HD * SS];   // [b][dim][seq]
__device__ __nv_bfloat16 g_ccb[ROWS * DD];
__device__ __nv_bfloat16 g_wqkvT[(DD + 128) * DD];  // rows 0..1023 wq^T, 1024..1151 wkv^T
__device__ __nv_bfloat16 g_woT[DD * DD];    // [N=D][K=D]
__device__ float g_phiT[NSLOT * DD];        // [16][1024]
__device__ float g_x1[ROWS * DD];
__device__ float g_m[ROWS * DD];
__device__ float g_logits[ROWS * NSLOT];
__device__ float g_dispatch[ROWS * NSLOT];
__device__ float g_combine[ROWS * NSLOT];
__device__ float g_xs[BB * NSLOT * DD];
__device__ float g_xs_part[SSEG * BB * NSLOT * DD];
__device__ float g_h1p[DS1 * 8 * EE * DFF]; // [ds][r][e][f]
__device__ float g_hidT[EE * DFF * 8];      // [e][f][8 rows]
__device__ float g_ys_part[FSEG * BB * NSLOT * DD];
__device__ float g_ys[BB * NSLOT * DD];

// ---------------- asm helpers ----------------
__device__ __forceinline__ unsigned smem_u32(const void* p) {
    return (unsigned)__cvta_generic_to_shared(p);
}
__device__ __forceinline__ void mma16816(float* d, const unsigned* a, const unsigned* b) {
    asm volatile("mma.sync.aligned.m16n8k16.row.col.f32.bf16.bf16.f32 "
                 "{%0,%1,%2,%3}, {%4,%5,%6,%7}, {%8,%9}, {%0,%1,%2,%3};\n"
                 : "+f"(d[0]), "+f"(d[1]), "+f"(d[2]), "+f"(d[3])
                 : "r"(a[0]), "r"(a[1]), "r"(a[2]), "r"(a[3]), "r"(b[0]), "r"(b[1]));
}
__device__ __forceinline__ void ldsm4(unsigned* r, unsigned a) {
    asm volatile("ldmatrix.sync.aligned.m8n8.x4.shared.b16 {%0,%1,%2,%3}, [%4];\n"
                 : "=r"(r[0]), "=r"(r[1]), "=r"(r[2]), "=r"(r[3]) : "r"(a));
}
__device__ __forceinline__ void ldsm4t(unsigned* r, unsigned a) {
    asm volatile("ldmatrix.sync.aligned.m8n8.x4.trans.shared.b16 {%0,%1,%2,%3}, [%4];\n"
                 : "=r"(r[0]), "=r"(r[1]), "=r"(r[2]), "=r"(r[3]) : "r"(a));
}
__device__ __forceinline__ unsigned pack_bf16(float a, float b) {
    __nv_bfloat162 t;
    t.x = __float2bfloat16(a);
    t.y = __float2bfloat16(b);
    return *reinterpret_cast<unsigned*>(&t);
}
__device__ __forceinline__ float ex2(float x) {
    float y;
    asm("ex2.approx.f32 %0, %1;" : "=f"(y) : "f"(x));
    return y;
}
__device__ __forceinline__ void cp16(unsigned dst, const void* src) {
    asm volatile("cp.async.cg.shared.global [%0], [%1], 16;\n" :: "r"(dst), "l"(src));
}
__device__ __forceinline__ void cp_commit() {
    asm volatile("cp.async.commit_group;\n");
}
template<int N>
__device__ __forceinline__ void cp_wait() {
    asm volatile("cp.async.wait_group %0;\n" :: "n"(N));
}

#if TCOK
// ---------------- tcgen05 helpers (arch-specific pass only) ----------------
__device__ __forceinline__ uint32_t elect_one() {
    uint32_t pred;
    asm volatile("{\n\t.reg .pred p;\n\telect.sync _|p, 0xFFFFFFFF;\n\t"
                 "selp.b32 %0, 1, 0, p;\n\t}" : "=r"(pred));
    return pred;
}
#define TC_ALLOC(smem_addr, ncols) \
    asm volatile("tcgen05.alloc.cta_group::1.sync.aligned.shared::cta.b32 [%0], %1;" \
                 :: "r"((uint32_t)(smem_addr)), "r"((uint32_t)(ncols)) : "memory")
#define TC_RELINQ() \
    asm volatile("tcgen05.relinquish_alloc_permit.cta_group::1.sync.aligned;")
#define TC_DEALLOC(tmem, ncols) \
    asm volatile("tcgen05.dealloc.cta_group::1.sync.aligned.b32 %0, %1;" \
                 :: "r"(tmem), "r"((uint32_t)(ncols)))
#define TC_COMMIT(mbar) \
    asm volatile("tcgen05.commit.cta_group::1.mbarrier::arrive::one.shared::cluster.b64 [%0];" \
                 :: "r"((uint32_t)(mbar)) : "memory")
#define TC_FENCE_AFTER()  asm volatile("tcgen05.fence::after_thread_sync;" ::: "memory")
#define TC_FENCE_BEFORE() asm volatile("tcgen05.fence::before_thread_sync;" ::: "memory")
#define TC_WAIT_LD()      asm volatile("tcgen05.wait::ld.sync.aligned;" ::: "memory")
#define MBAR_INIT(mbar, cnt) \
    asm volatile("mbarrier.init.shared.b64 [%0], %1;" \
                 :: "r"((uint32_t)(mbar)), "r"((uint32_t)(cnt)) : "memory")
#define MBAR_INVAL(mbar) \
    asm volatile("mbarrier.inval.shared.b64 [%0];" :: "r"((uint32_t)(mbar)) : "memory")
#define FENCE_PROXY() asm volatile("fence.proxy.async.shared::cta;" ::: "memory")

__device__ __forceinline__ void mbar_wait(uint32_t mbar, uint32_t parity) {
    uint32_t done;
    asm volatile("{\n\t.reg .pred p;\n\t"
                 "mbarrier.try_wait.parity.acquire.cta.shared::cta.b64 p, [%1], %2;\n\t"
                 "selp.b32 %0, 1, 0, p;\n\t}"
                 : "=r"(done) : "r"(mbar), "r"(parity) : "memory");
    if (!done) {
        asm volatile("{\n\t.reg .pred P1;\n\t"
                     "WL_%=:\n\t"
                     "mbarrier.try_wait.parity.acquire.cta.shared::cta.b64 P1, [%0], %1, 0x989680;\n\t"
                     "@P1 bra.uni WD_%=;\n\t"
                     "bra.uni WL_%=;\n\t"
                     "WD_%=:\n\t}"
                     :: "r"(mbar), "r"(parity) : "memory");
    }
}
__device__ __forceinline__ void tc_mma_f16_ss(uint32_t d, uint64_t ad, uint64_t bd,
                                              uint32_t idesc, bool en) {
    uint32_t e = en ? 1u : 0u, z = 0u;
    asm volatile("{\n\t.reg .pred p;\n\tsetp.ne.u32 p, %5, 0;\n\t"
                 "tcgen05.mma.cta_group::1.kind::f16 [%0], %1, %2, %3, {%4,%4,%4,%4}, p;\n\t}"
                 :: "r"(d), "l"(ad), "l"(bd), "r"(idesc), "r"(z), "r"(e) : "memory");
}
__device__ __forceinline__ uint32_t ld_shared_u32(uint32_t addr) {
    uint32_t v;
    asm volatile("ld.shared.b32 %0, [%1];" : "=r"(v) : "r"(addr));
    return v;
}
// SW128 smem descriptor, K-major: layout 2, version 1, SBO=64, LBO=1
__device__ __forceinline__ uint64_t make_desc(uint32_t addr) {
    const uint64_t base = (uint64_t(2) << 61) | (uint64_t(1) << 46)
                        | (uint64_t(64) << 32) | (uint64_t(1) << 16);
    return base | ((uint64_t)(addr >> 4) & 0x3FFF);
}
#define LDTM_X32(r, addr) \
    asm volatile("tcgen05.ld.sync.aligned.32x32b.x32.b32 " \
        "{%0,%1,%2,%3,%4,%5,%6,%7,%8,%9,%10,%11,%12,%13,%14,%15," \
        "%16,%17,%18,%19,%20,%21,%22,%23,%24,%25,%26,%27,%28,%29,%30,%31}, [%32];" \
        : "=r"((r)[0]),"=r"((r)[1]),"=r"((r)[2]),"=r"((r)[3]), \
          "=r"((r)[4]),"=r"((r)[5]),"=r"((r)[6]),"=r"((r)[7]), \
          "=r"((r)[8]),"=r"((r)[9]),"=r"((r)[10]),"=r"((r)[11]), \
          "=r"((r)[12]),"=r"((r)[13]),"=r"((r)[14]),"=r"((r)[15]), \
          "=r"((r)[16]),"=r"((r)[17]),"=r"((r)[18]),"=r"((r)[19]), \
          "=r"((r)[20]),"=r"((r)[21]),"=r"((r)[22]),"=r"((r)[23]), \
          "=r"((r)[24]),"=r"((r)[25]),"=r"((r)[26]),"=r"((r)[27]), \
          "=r"((r)[28]),"=r"((r)[29]),"=r"((r)[30]),"=r"((r)[31]) \
        : "r"(addr))
#endif // TCOK

// ---------------- layernorm ----------------
__global__ void ln_kernel(const float* __restrict__ x, const float* __restrict__ gamma,
                          float* __restrict__ out, __nv_bfloat16* __restrict__ ob) {
    long long row = blockIdx.x;
    const float* p = x + row * DD;
    float v[4];
    float s = 0.f, sq = 0.f;
#pragma unroll
    for (int i = 0; i < 4; i++) {
        v[i] = p[threadIdx.x + i * 256];
        s += v[i];
        sq += v[i] * v[i];
    }
    __shared__ float rs[8], rq[8];
#pragma unroll
    for (int o = 16; o; o >>= 1) {
        s  += __shfl_xor_sync(0xFFFFFFFFu, s, o);
        sq += __shfl_xor_sync(0xFFFFFFFFu, sq, o);
    }
    int w = threadIdx.x >> 5;
    if ((threadIdx.x & 31) == 0) { rs[w] = s; rq[w] = sq; }
    __syncthreads();
    if (threadIdx.x == 0) {
        float ts = 0.f, tq = 0.f;
        for (int i = 0; i < 8; i++) { ts += rs[i]; tq += rq[i]; }
        rs[0] = ts; rq[0] = tq;
    }
    __syncthreads();
    float mean = rs[0] * (1.f / (float)DD);
    float var  = rq[0] * (1.f / (float)DD) - mean * mean;
    float rstd = rsqrtf(var + 1e-5f);
    float* o = out + row * DD;
#pragma unroll
    for (int i = 0; i < 4; i++) {
        int d = threadIdx.x + i * 256;
        float val = gamma[d] * (v[i] - mean) * rstd;
        o[d] = val;
        if (ob) ob[row * DD + d] = __float2bfloat16(val);
    }
}

// ---------------- weight transpose + convert ----------------
__global__ void transpose_cvt_kernel(const float* __restrict__ in,
                                     __nv_bfloat16* __restrict__ out, int R, int C) {
    __shared__ float t[32][33];
    int c0 = blockIdx.x * 32, r0 = blockIdx.y * 32;
    for (int i = threadIdx.y; i < 32; i += 8)
        t[i][threadIdx.x] = in[(long long)(r0 + i) * C + c0 + threadIdx.x];
    __syncthreads();
    for (int i = threadIdx.y; i < 32; i += 8)
        out[(long long)(c0 + i) * R + r0 + threadIdx.x] = __float2bfloat16(t[threadIdx.x][i]);
}

// ---------------- phi transpose ----------------
__global__ void phiT_kernel(const float* __restrict__ phi, float* __restrict__ phiT) {
    int d = blockIdx.x * 256 + threadIdx.x;
#pragma unroll
    for (int e = 0; e < NSLOT; e++)
        phiT[e * DD + d] = phi[d * NSLOT + e];
}

// ---------------- v transpose ----------------
__global__ void vT_kernel(const __nv_bfloat16* __restrict__ kvb,
                          __nv_bfloat16* __restrict__ vT) {
    __shared__ __nv_bfloat16 t[32][33];
    int s0 = blockIdx.x * 32, d0 = blockIdx.y * 32, b = blockIdx.z;
    for (int i = threadIdx.y; i < 32; i += 8)
        t[i][threadIdx.x] = kvb[((long long)(b * SS + s0 + i)) * 128 + 64 + d0 + threadIdx.x];
    __syncthreads();
    for (int i = threadIdx.y; i < 32; i += 8)
        vT[((long long)(b * HD + d0 + i)) * SS + s0 + threadIdx.x] = t[threadIdx.x][i];
}

// ---------------- unified bf16 GEMM, templated N tile + QKV routing ----------------
// A [M,K] rm bf16; BT [N,K] rm bf16. BM=128. 3-stage ring, one mbarrier/buffer.
// QKV: grid.x covers N=1152; blocks with col0<1024 write q (alpha), block 8 writes kv (ldc 128).
template<int BN, bool ADD, bool OUTBF, bool QKV>
__global__ __launch_bounds__(256) __cluster_dims__(1, 1, 1) void gemm_kernel(
    const __nv_bfloat16* __restrict__ A, const __nv_bfloat16* __restrict__ BT,
    const float* __restrict__ AddP, float* __restrict__ Cf,
    __nv_bfloat16* __restrict__ Cb, __nv_bfloat16* __restrict__ Cb2,
    int M, int N, int K, float alpha) {
    extern __shared__ char smraw[];
    uint32_t sb0 = smem_u32(smraw);
    uint32_t sbase = (sb0 + 1023u) & ~1023u;
    int tid = threadIdx.x, lane = tid & 31, wrp = tid >> 5;
    int row0 = blockIdx.y * 128, col0 = blockIdx.x * BN;
    const uint32_t T0 = sbase + 1024;
    const uint32_t BBUF = (uint32_t)BN * 128;

    auto loadA = [&](uint32_t off, int k0) {
#pragma unroll
        for (int i = 0; i < 4; i++) {
            int idx = i * 256 + tid;
            int r = idx >> 3, ch = idx & 7;
            cp16(off + r * 128 + ((ch ^ (r & 7)) << 4),
                 A + (long long)(row0 + r) * K + k0 + ch * 8);
        }
    };
    auto loadB = [&](uint32_t off, int k0) {
#pragma unroll
        for (int i = 0; i < BN / 32; i++) {
            int idx = i * 256 + tid;
            int r = idx >> 3, ch = idx & 7;
            cp16(off + r * 128 + ((ch ^ (r & 7)) << 4),
                 BT + (long long)(col0 + r) * K + k0 + ch * 8);
        }
    };
    int NT = K / 64;

#if TCOK
    const uint32_t BOFF = T0 + 3 * 16384;
    if (wrp == 0) { TC_ALLOC(sbase, BN); TC_RELINQ(); }
    if (tid == 0) {
        MBAR_INIT(sbase + 8, 1);
        MBAR_INIT(sbase + 16, 1);
        MBAR_INIT(sbase + 24, 1);
    }
    __syncthreads();
    uint32_t tmem = ld_shared_u32(sbase);
    const uint32_t IDESC = 0x490u | (((uint32_t)BN / 8) << 17) | (8u << 24);
    auto mb = [&](int i) -> uint32_t { return sbase + 8 + (uint32_t)i * 8; };

    loadA(T0, 0); loadB(BOFF, 0); cp_commit();
    if (NT > 1) { loadA(T0 + 16384, 64); loadB(BOFF + BBUF, 64); cp_commit(); }

    for (int t = 0; t < NT; t++) {
        uint32_t sA = T0 + (uint32_t)(t % 3) * 16384;
        uint32_t sB = BOFF + (uint32_t)(t % 3) * BBUF;
        if (t + 1 < NT) cp_wait<1>();
        else cp_wait<0>();
        FENCE_PROXY();
        __syncthreads();
        if (wrp == 0 && elect_one()) {
            uint64_t ad = make_desc(sA);
            uint64_t bd = make_desc(sB);
#pragma unroll
            for (int kk = 0; kk < 4; kk++)
                tc_mma_f16_ss(tmem, ad + kk * 2, bd + kk * 2, IDESC, (t > 0) || (kk > 0));
            TC_COMMIT(mb(t % 3));
        }
        if (t + 2 < NT) {
            if (t >= 1) mbar_wait(mb((t - 1) % 3), (uint32_t)(((t - 1) / 3) & 1));
            loadA(T0 + (uint32_t)((t + 2) % 3) * 16384, (t + 2) * 64);
            loadB(BOFF + (uint32_t)((t + 2) % 3) * BBUF, (t + 2) * 64);
            cp_commit();
        }
    }
    for (int tt = (NT >= 3 ? NT - 3 : 0); tt < NT; tt++)
        mbar_wait(mb(tt % 3), (uint32_t)((tt / 3) & 1));
    TC_FENCE_AFTER();

    {
        long long r = row0 + (wrp & 3) * 32 + lane;
        int cbase = (wrp >> 2) * (BN / 2);
        bool is_kv = QKV && (col0 >= 1024);
        float alp = is_kv ? 1.0f : alpha;
#pragma unroll
        for (int cg = 0; cg < BN / 64; cg++) {
            uint32_t regs[32];
            LDTM_X32(regs, tmem + cbase + cg * 32);
            TC_WAIT_LD();
            int c0 = col0 + cbase + cg * 32;
            if (OUTBF) {
                __nv_bfloat16* dst;
                long long base;
                if (QKV) {
                    if (is_kv) { dst = Cb2; base = r * 128 + (c0 - 1024); }
                    else       { dst = Cb;  base = r * (long long)N + c0; }
                } else { dst = Cb; base = r * (long long)N + c0; }
#pragma unroll
                for (int i = 0; i < 32; i += 2) {
                    __nv_bfloat162 p;
                    p.x = __float2bfloat16(__uint_as_float(regs[i]) * alp);
                    p.y = __float2bfloat16(__uint_as_float(regs[i + 1]) * alp);
                    *(__nv_bfloat162*)(dst + base + i) = p;
                }
            } else {
#pragma unroll
                for (int i = 0; i < 32; i += 2) {
                    float v0 = __uint_as_float(regs[i]) * alp;
                    float v1 = __uint_as_float(regs[i + 1]) * alp;
                    if (ADD) {
                        float2 a = *(const float2*)(AddP + r * N + c0 + i);
                        v0 += a.x; v1 += a.y;
                    }
                    *(float2*)(Cf + r * N + c0 + i) = make_float2(v0, v1);
                }
            }
        }
    }
    TC_FENCE_BEFORE();
    __syncthreads();
    if (tid == 0) { MBAR_INVAL(mb(0)); MBAR_INVAL(mb(1)); MBAR_INVAL(mb(2)); }
    __syncthreads();
    if (wrp == 0) TC_DEALLOC(tmem, BN);
#else
    // HMMA fallback: BN in 128-wide chunks (compile-correct; never runs on sm_103a)
    const __nv_bfloat16* As[2] = { (const __nv_bfloat16*)(smraw + (T0 - sb0)),
                                   (const __nv_bfloat16*)(smraw + (T0 - sb0) + 16384) };
    const __nv_bfloat16* Bs[2] = { (const __nv_bfloat16*)(smraw + (T0 - sb0) + 32768),
                                   (const __nv_bfloat16*)(smraw + (T0 - sb0) + 49152) };
    int wm = wrp >> 2, wn = wrp & 3;

    for (int cc = 0; cc < BN / 128; cc++) {
        int col0c = col0 + cc * 128;
        bool is_kv = QKV && (col0c >= 1024);
        float alp = is_kv ? 1.0f : alpha;
        auto loadB128 = [&](uint32_t off, int k0) {
#pragma unroll
            for (int i = 0; i < 4; i++) {
                int idx = i * 256 + tid;
                int r = idx >> 3, ch = idx & 7;
                cp16(off + r * 128 + ((ch ^ (r & 7)) << 4),
                     BT + (long long)(col0c + r) * K + k0 + ch * 8);
            }
        };
        float acc[4][4][4];
#pragma unroll
        for (int mt = 0; mt < 4; mt++)
#pragma unroll
            for (int nt = 0; nt < 4; nt++)
#pragma unroll
                for (int i = 0; i < 4; i++) acc[mt][nt][i] = 0.f;

        loadA(T0, 0); loadB128(T0 + 32768, 0); cp_commit();
        for (int t = 0; t < NT; t++) {
            if (t + 1 < NT) {
                loadA(T0 + (uint32_t)((t + 1) & 1) * 16384, (t + 1) * 64);
                loadB128(T0 + 32768 + (uint32_t)((t + 1) & 1) * 16384, (t + 1) * 64);
                cp_commit();
                cp_wait<1>();
            } else cp_wait<0>();
            __syncthreads();
            const __nv_bfloat16* as = As[t & 1];
            const __nv_bfloat16* bs = Bs[t & 1];
#pragma unroll
            for (int kk = 0; kk < 4; kk++) {
                unsigned af[4][4], bf[2][4];
#pragma unroll
                for (int mt = 0; mt < 4; mt++) {
                    int r = wm * 64 + mt * 16 + (lane & 15);
                    int chunk = ((kk * 2 + (lane >> 4)) ^ (r & 7));
                    ldsm4(af[mt], smem_u32(as + r * 64 + chunk * 8));
                }
#pragma unroll
                for (int np = 0; np < 2; np++) {
                    int nrow = wn * 32 + (2 * np + ((lane >> 4) & 1)) * 8 + (lane & 7);
                    int chunk = ((kk * 2 + ((lane >> 3) & 1)) ^ (nrow & 7));
                    ldsm4(bf[np], smem_u32(bs + nrow * 64 + chunk * 8));
                }
#pragma unroll
                for (int mt = 0; mt < 4; mt++)
#pragma unroll
                    for (int nt = 0; nt < 4; nt++)
                        mma16816(acc[mt][nt], af[mt], bf[nt >> 1] + (nt & 1) * 2);
            }
            __syncthreads();
        }
#pragma unroll
        for (int mt = 0; mt < 4; mt++) {
#pragma unroll
            for (int nt = 0; nt < 4; nt++) {
                int r = row0 + wm * 64 + mt * 16 + (lane >> 2);
                int cl = wn * 32 + nt * 8 + 2 * (lane & 3);
                float v0 = acc[mt][nt][0] * alp, v1 = acc[mt][nt][1] * alp;
                float v2 = acc[mt][nt][2] * alp, v3 = acc[mt][nt][3] * alp;
                if (OUTBF) {
                    __nv_bfloat16* dst; long long b0, b1;
                    if (QKV && is_kv) {
                        dst = Cb2;
                        b0 = (long long)r * 128 + (col0c - 1024) + cl;
                        b1 = (long long)(r + 8) * 128 + (col0c - 1024) + cl;
                    } else {
                        dst = Cb;
                        b0 = (long long)r * N + col0c + cl;
                        b1 = (long long)(r + 8) * N + col0c + cl;
                    }
                    __nv_bfloat162 p0; p0.x = __float2bfloat16(v0); p0.y = __float2bfloat16(v1);
                    __nv_bfloat162 p1; p1.x = __float2bfloat16(v2); p1.y = __float2bfloat16(v3);
                    *(__nv_bfloat162*)(dst + b0) = p0;
                    *(__nv_bfloat162*)(dst + b1) = p1;
                } else {
                    int c = col0c + cl;
                    if (ADD) {
                        float2 a0 = *(const float2*)(AddP + (long long)r * N + c);
                        float2 a1 = *(const float2*)(AddP + (long long)(r + 8) * N + c);
                        v0 += a0.x; v1 += a0.y; v2 += a1.x; v3 += a1.y;
                    }
                    *(float2*)(Cf + (long long)r * N + c) = make_float2(v0, v1);
                    *(float2*)(Cf + (long long)(r + 8) * N + c) = make_float2(v2, v3);
                }
            }
        }
        __syncthreads();
    }
#endif
}

// ---------------- flash attention: R15 pipelined version (passing, unchanged) ----------------
__global__ __launch_bounds__(256) __cluster_dims__(1, 1, 1) void flash_kernel(
    const __nv_bfloat16* __restrict__ qb, const __nv_bfloat16* __restrict__ kvb,
    const __nv_bfloat16* __restrict__ vT, __nv_bfloat16* __restrict__ ccb) {
    int tid = threadIdx.x, lane = tid & 31, wrp = tid >> 5;
    int b = blockIdx.y >> 4, h = blockIdx.y & 15;
    long long qrow0 = (long long)b * SS + blockIdx.x * 128;

#if TCOK
    extern __shared__ char smraw[];
    uint32_t sb0 = smem_u32(smraw);
    uint32_t sbase = (sb0 + 1023u) & ~1023u;
    const uint32_t QOFF = sbase + 2048;
    const uint32_t K0 = QOFF + 16384;
    const uint32_t V0 = K0 + 16384;
    const uint32_t POFF = V0 + 16384;
    float* lsp = (float*)(smraw + (sbase - sb0) + 512);
    char* pgen = smraw + (POFF - sb0);

    if (wrp == 0) { TC_ALLOC(sbase, 128); TC_RELINQ(); }
    if (tid == 0) { MBAR_INIT(sbase + 8, 1); MBAR_INIT(sbase + 16, 1); }
    __syncthreads();
    uint32_t tmem = ld_shared_u32(sbase);
    const uint32_t mbS = sbase + 8, mbP = sbase + 16;
    const int S_OFF = 0, O_OFF = 64;

#pragma unroll
    for (int i = 0; i < 4; i++) {
        int idx = i * 256 + tid;
        int r = idx >> 3, ch = idx & 7;
        cp16(QOFF + r * 128 + ((ch ^ (r & 7)) << 4),
             qb + (qrow0 + r) * DD + h * 64 + ch * 8);
    }
    auto loadKV = [&](int buf, int kt) {
#pragma unroll
        for (int i = 0; i < 2; i++) {
            int idx = i * 256 + tid;
            int r = idx >> 3, ch = idx & 7;
            uint32_t sw = r * 128 + ((ch ^ (r & 7)) << 4);
            cp16(K0 + buf * 8192 + sw,
                 kvb + ((long long)b * SS + kt * 64 + r) * 128 + ch * 8);
            cp16(V0 + buf * 8192 + sw,
                 vT + ((long long)(b * HD + r)) * SS + kt * 64 + ch * 8);
        }
        cp_commit();
    };

    const uint32_t IDESC = 0x490u | (8u << 17) | (8u << 24);
    int my_half = wrp >> 2;
    int rrow = (wrp & 3) * 32 + lane;
    float ls = 0.f;
    uint64_t qd = make_desc(QOFF);
    const int NKT = SS / 64;

    loadKV(0, 0);
    cp_wait<0>();
    FENCE_PROXY();
    __syncthreads();
    if (wrp == 0 && elect_one()) {
        uint64_t kd = make_desc(K0);
#pragma unroll
        for (int kk = 0; kk < 4; kk++)
            tc_mma_f16_ss(tmem + S_OFF, qd + kk * 2, kd + kk * 2, IDESC, kk > 0);
        TC_COMMIT(mbS);
    }

    for (int kt = 0; kt < NKT; kt++) {
        mbar_wait(mbS, (uint32_t)(kt & 1));
        TC_FENCE_AFTER();
        if (kt >= 1) mbar_wait(mbP, (uint32_t)((kt - 1) & 1));
        if (kt + 1 < NKT) loadKV((kt + 1) & 1, kt + 1);

        uint32_t sreg[32];
        LDTM_X32(sreg, tmem + S_OFF + my_half * 32);
        TC_WAIT_LD();
        float p[32];
#pragma unroll
        for (int i = 0; i < 32; i++) {
            p[i] = ex2(__uint_as_float(sreg[i]));
            ls += p[i];
        }
        uint32_t pw[16];
#pragma unroll
        for (int i = 0; i < 16; i++) pw[i] = pack_bf16(p[2 * i], p[2 * i + 1]);
#pragma unroll
        for (int j = 0; j < 4; j++) {
            int ch = my_half * 4 + j;
            *(uint4*)(pgen + rrow * 128 + ((ch ^ (rrow & 7)) << 4)) =
                make_uint4(pw[4 * j], pw[4 * j + 1], pw[4 * j + 2], pw[4 * j + 3]);
        }
        FENCE_PROXY();
        TC_FENCE_BEFORE();
        __syncthreads();

        if (wrp == 0 && elect_one()) {
            TC_FENCE_AFTER();
            uint64_t pd = make_desc(POFF);
            uint64_t vd = make_desc(V0 + (uint32_t)(kt & 1) * 8192);
#pragma unroll
            for (int kk = 0; kk < 4; kk++)
                tc_mma_f16_ss(tmem + O_OFF, pd + kk * 2, vd + kk * 2,
                              IDESC, (kt > 0) || (kk > 0));
            TC_COMMIT(mbP);
        }

        if (kt + 1 < NKT) {
            cp_wait<0>();
            FENCE_PROXY();
            __syncthreads();
            if (wrp == 0 && elect_one()) {
                uint64_t kd = make_desc(K0 + (uint32_t)((kt + 1) & 1) * 8192);
#pragma unroll
                for (int kk = 0; kk < 4; kk++)
                    tc_mma_f16_ss(tmem + S_OFF, qd + kk * 2, kd + kk * 2, IDESC, kk > 0);
                TC_COMMIT(mbS);
            }
        }
    }
    mbar_wait(mbP, (uint32_t)((NKT - 1) & 1));
    TC_FENCE_AFTER();

    lsp[my_half * 128 + rrow] = ls;
    __syncthreads();
    float inv = 1.f / (lsp[rrow] + lsp[128 + rrow]);

    uint32_t oreg[32];
    LDTM_X32(oreg, tmem + O_OFF + my_half * 32);
    TC_WAIT_LD();
    long long gr = qrow0 + rrow;
    int c0 = h * 64 + my_half * 32;
#pragma unroll
    for (int i = 0; i < 32; i += 2) {
        __nv_bfloat162 pv;
        pv.x = __float2bfloat16(__uint_as_float(oreg[i]) * inv);
        pv.y = __float2bfloat16(__uint_as_float(oreg[i + 1]) * inv);
        *(__nv_bfloat162*)(ccb + gr * DD + c0 + i) = pv;
    }
    TC_FENCE_BEFORE();
    __syncthreads();
    if (tid == 0) { MBAR_INVAL(mbS); MBAR_INVAL(mbP); }
    __syncthreads();
    if (wrp == 0) TC_DEALLOC(tmem, 128);
#else
    // ================= HMMA fallback (R6 version) =================
    __shared__ __nv_bfloat16 Qs[128 * 64];
    __shared__ __nv_bfloat16 Ks[2][64 * 64];
    __shared__ __nv_bfloat16 Vs[2][64 * 64];
    int w = wrp;

    auto loadKV = [&](int st, int kt) {
#pragma unroll
        for (int i = 0; i < 2; i++) {
            int idx = i * 2048 + tid * 8;
            int r = idx >> 6, c = idx & 63;
            int chunk = (c >> 3) ^ (r & 7);
            long long grow = (long long)b * SS + kt * 64 + r;
            cp16(smem_u32(&Ks[st][r * 64 + chunk * 8]), kvb + grow * 128 + c);
            cp16(smem_u32(&Vs[st][r * 64 + chunk * 8]), kvb + grow * 128 + 64 + c);
        }
        cp_commit();
    };

#pragma unroll
    for (int i = 0; i < 4; i++) {
        int idx = i * 2048 + tid * 8;
        int r = idx >> 6, c = idx & 63;
        int chunk = (c >> 3) ^ (r & 7);
        cp16(smem_u32(Qs + r * 64 + chunk * 8), qb + (qrow0 + r) * DD + h * 64 + c);
    }
    loadKV(0, 0);
    cp_wait<0>();
    __syncthreads();

    unsigned qa[4][4];
    {
        int r = w * 16 + (lane & 15);
#pragma unroll
        for (int kk = 0; kk < 4; kk++) {
            int chunk = ((kk * 2 + (lane >> 4)) ^ (r & 7));
            ldsm4(qa[kk], smem_u32(Qs + r * 64 + chunk * 8));
        }
    }

    float o[8][4];
#pragma unroll
    for (int nt = 0; nt < 8; nt++)
#pragma unroll
        for (int i = 0; i < 4; i++) o[nt][i] = 0.f;
    float ls0 = 0.f, ls1 = 0.f;

    for (int kt = 0; kt < SS / 64; kt++) {
        if (kt + 1 < SS / 64) { loadKV((kt + 1) & 1, kt + 1); cp_wait<1>(); }
        else cp_wait<0>();
        __syncthreads();
        const __nv_bfloat16* ks = Ks[kt & 1];
        const __nv_bfloat16* vs = Vs[kt & 1];

        float sf[8][4];
#pragma unroll
        for (int nt = 0; nt < 8; nt++)
#pragma unroll
            for (int i = 0; i < 4; i++) sf[nt][i] = 0.f;
#pragma unroll
        for (int kk = 0; kk < 4; kk++) {
#pragma unroll
            for (int np = 0; np < 4; np++) {
                unsigned bbf[4];
                int krow = (2 * np + ((lane >> 4) & 1)) * 8 + (lane & 7);
                int chunk = ((kk * 2 + ((lane >> 3) & 1)) ^ (krow & 7));
                ldsm4(bbf, smem_u32(ks + krow * 64 + chunk * 8));
                mma16816(sf[2 * np], qa[kk], bbf);
                mma16816(sf[2 * np + 1], qa[kk], bbf + 2);
            }
        }
#pragma unroll
        for (int nt = 0; nt < 8; nt++) {
            sf[nt][0] = ex2(sf[nt][0]);
            sf[nt][1] = ex2(sf[nt][1]);
            sf[nt][2] = ex2(sf[nt][2]);
            sf[nt][3] = ex2(sf[nt][3]);
            ls0 += sf[nt][0] + sf[nt][1];
            ls1 += sf[nt][2] + sf[nt][3];
        }
#pragma unroll
        for (int j = 0; j < 4; j++) {
            unsigned pa[4];
            pa[0] = pack_bf16(sf[2 * j][0], sf[2 * j][1]);
            pa[1] = pack_bf16(sf[2 * j][2], sf[2 * j][3]);
            pa[2] = pack_bf16(sf[2 * j + 1][0], sf[2 * j + 1][1]);
            pa[3] = pack_bf16(sf[2 * j + 1][2], sf[2 * j + 1][3]);
#pragma unroll
            for (int np = 0; np < 4; np++) {
                unsigned vv[4];
                int vrow = j * 16 + (lane & 7) + ((lane >> 3) & 1) * 8;
                int cgrp = 2 * np + ((lane >> 4) & 1);
                int chunk = (cgrp ^ (vrow & 7));
                ldsm4t(vv, smem_u32(vs + vrow * 64 + chunk * 8));
                mma16816(o[2 * np], pa, vv);
                mma16816(o[2 * np + 1], pa, vv + 2);
            }
        }
        __syncthreads();
    }

    ls0 += __shfl_xor_sync(0xFFFFFFFFu, ls0, 1);
    ls0 += __shfl_xor_sync(0xFFFFFFFFu, ls0, 2);
    ls1 += __shfl_xor_sync(0xFFFFFFFFu, ls1, 1);
    ls1 += __shfl_xor_sync(0xFFFFFFFFu, ls1, 2);
    float inv0 = 1.f / ls0, inv1 = 1.f / ls1;

    long long gr = qrow0 + w * 16 + (lane >> 2);
#pragma unroll
    for (int nt = 0; nt < 8; nt++) {
        int c = h * 64 + nt * 8 + 2 * (lane & 3);
        __nv_bfloat162 p0, p1;
        p0.x = __float2bfloat16(o[nt][0] * inv0);
        p0.y = __float2bfloat16(o[nt][1] * inv0);
        p1.x = __float2bfloat16(o[nt][2] * inv1);
        p1.y = __float2bfloat16(o[nt][3] * inv1);
        *(__nv_bfloat162*)(ccb + gr * DD + c) = p0;
        *(__nv_bfloat162*)(ccb + (gr + 8) * DD + c) = p1;
    }
#endif
}

// ---------------- logits + dispatch softmax: 4 rows per block, phiT reg-reuse ----------------
__global__ __launch_bounds__(128) void logits_kernel(
    const float* __restrict__ m, const float* __restrict__ phiT,
    float* __restrict__ logits, float* __restrict__ dispatch) {
    __shared__ float4 msv[4][DD / 4];
    __shared__ float part[4][8][NSLOT];
    __shared__ float lsm[4][NSLOT];
    long long row0 = (long long)blockIdx.x * 4;
    int tid = threadIdx.x;
    const float4* mr = (const float4*)(m + row0 * DD);
#pragma unroll
    for (int i = 0; i < 8; i++) {
        int idx = i * 128 + tid;
        msv[idx >> 8][idx & 255] = mr[idx];
    }
    __syncthreads();
    int e = tid & 15, seg = tid >> 4;
    const float4* pe = (const float4*)(phiT + e * DD) + seg * 32;
    float a0 = 0.f, a1 = 0.f, a2 = 0.f, a3 = 0.f;
#pragma unroll
    for (int i = 0; i < 32; i++) {
        float4 pv = pe[i];
        int idx = seg * 32 + i;
        float4 m0 = msv[0][idx];
        float4 m1 = msv[1][idx];
        float4 m2 = msv[2][idx];
        float4 m3 = msv[3][idx];
        a0 += m0.x * pv.x + m0.y * pv.y + m0.z * pv.z + m0.w * pv.w;
        a1 += m1.x * pv.x + m1.y * pv.y + m1.z * pv.z + m1.w * pv.w;
        a2 += m2.x * pv.x + m2.y * pv.y + m2.z * pv.z + m2.w * pv.w;
        a3 += m3.x * pv.x + m3.y * pv.y + m3.z * pv.z + m3.w * pv.w;
    }
    part[0][seg][e] = a0;
    part[1][seg][e] = a1;
    part[2][seg][e] = a2;
    part[3][seg][e] = a3;
    __syncthreads();
    if (tid < 64) {
        int r = tid >> 4, ee = tid & 15;
        float l = 0.f;
#pragma unroll
        for (int s = 0; s < 8; s++) l += part[r][s][ee];
        logits[(row0 + r) * NSLOT + ee] = l;
        lsm[r][ee] = l;
    }
    __syncthreads();
    if (tid < 64) {
        int r = tid >> 4, ee = tid & 15;
        float mx = lsm[r][0];
        for (int j = 1; j < NSLOT; j++) mx = fmaxf(mx, lsm[r][j]);
        float s = 0.f;
        for (int j = 0; j < NSLOT; j++) s += expf(lsm[r][j] - mx);
        dispatch[(row0 + r) * NSLOT + ee] = expf(lsm[r][ee] - mx) / s;
    }
}

// ---------------- combine softmax over sequence axis ----------------
__global__ void combine_kernel(const float* __restrict__ logits, float* __restrict__ comb) {
    int b = blockIdx.x >> 4, e = blockIdx.x & 15;
    const float* base = logits + ((long long)b * SS) * NSLOT + e;
    float v[8];
    float mx = -1e30f;
#pragma unroll
    for (int i = 0; i < 8; i++) {
        int s = threadIdx.x + i * 256;
        v[i] = base[(long long)s * NSLOT];
        mx = fmaxf(mx, v[i]);
    }
    __shared__ float red[8];
#pragma unroll
    for (int o = 16; o; o >>= 1) mx = fmaxf(mx, __shfl_xor_sync(0xFFFFFFFFu, mx, o));
    int w = threadIdx.x >> 5;
    if ((threadIdx.x & 31) == 0) red[w] = mx;
    __syncthreads();
    if (threadIdx.x == 0) {
        float t = red[0];
        for (int i = 1; i < 8; i++) t = fmaxf(t, red[i]);
        red[0] = t;
    }
    __syncthreads();
    mx = red[0];
    __syncthreads();
    float s = 0.f;
#pragma unroll
    for (int i = 0; i < 8; i++) { v[i] = expf(v[i] - mx); s += v[i]; }
#pragma unroll
    for (int o = 16; o; o >>= 1) s += __shfl_xor_sync(0xFFFFFFFFu, s, o);
    if ((threadIdx.x & 31) == 0) red[w] = s;
    __syncthreads();
    if (threadIdx.x == 0) {
        float t = 0.f;
        for (int i = 0; i < 8; i++) t += red[i];
        red[0] = t;
    }
    __syncthreads();
    float inv = 1.0f / red[0];
    float* ob = comb + ((long long)b * SS) * NSLOT + e;
#pragma unroll
    for (int i = 0; i < 8; i++) {
        int sidx = threadIdx.x + i * 256;
        ob[(long long)sidx * NSLOT] = v[i] * inv;
    }
}

// ---------------- xs partials + reduce (SSEG=16 for occupancy) ----------------
__global__ void xs_part_kernel(const float* __restrict__ dispatch, const float* __restrict__ m,
                               float* __restrict__ part) {
    int d = blockIdx.x * 256 + threadIdx.x;
    int b = blockIdx.y, seg = blockIdx.z;
    int s0 = seg * SCHUNK;
    __shared__ __align__(16) float ds[SCHUNK][NSLOT];
    for (int i = threadIdx.x; i < SCHUNK * NSLOT; i += 256)
        ds[i >> 4][i & 15] = dispatch[((long long)b * SS + s0) * NSLOT + i];
    __syncthreads();
    float acc[NSLOT];
#pragma unroll
    for (int e = 0; e < NSLOT; e++) acc[e] = 0.f;
    const float* mb = m + ((long long)b * SS + s0) * DD + d;
    for (int s = 0; s < SCHUNK; s++) {
        float mv = mb[(long long)s * DD];
        const float4* dr = (const float4*)ds[s];
#pragma unroll
        for (int q = 0; q < 4; q++) {
            float4 dv = dr[q];
            acc[q * 4 + 0] += dv.x * mv;
            acc[q * 4 + 1] += dv.y * mv;
            acc[q * 4 + 2] += dv.z * mv;
            acc[q * 4 + 3] += dv.w * mv;
        }
    }
#pragma unroll
    for (int e = 0; e < NSLOT; e++)
        part[(((long long)seg * BB + b) * NSLOT + e) * DD + d] = acc[e];
}

__global__ void xs_reduce_kernel(const float* __restrict__ part, float* __restrict__ xs) {
    int i = blockIdx.x * 256 + threadIdx.x;
    float a = 0.f;
#pragma unroll
    for (int seg = 0; seg < SSEG; seg++)
        a += part[(long long)seg * BB * NSLOT * DD + i];
    xs[i] = a;
}

// ---------------- expert FFN1 partials: h1p[ds][r][e][f], DS1=8 for occupancy ----------------
__global__ __launch_bounds__(256) void ffn1_kernel(
    const float* __restrict__ xs, const float* __restrict__ w1,
    float* __restrict__ h1p) {
    int e = blockIdx.x, fs = blockIdx.y, ds = blockIdx.z;
    int f0 = fs * F1CH, d0 = ds * D1CH;
    int tid = threadIdx.x;
    __shared__ __align__(16) float xst[D1CH][8];
    for (int i = tid; i < D1CH * 8; i += 256) {
        int d = i & (D1CH - 1), r = i >> 7;  // D1CH==128
        int b = r >> 1, slot = r & 1;
        xst[d][r] = xs[((long long)(b * NSLOT + e * 2 + slot)) * DD + d0 + d];
    }
    __syncthreads();
    float4 acc[8];
#pragma unroll
    for (int r = 0; r < 8; r++) acc[r] = make_float4(0.f, 0.f, 0.f, 0.f);
    const float4* w = (const float4*)(w1 + (long long)e * DD * DFF
                                      + (long long)d0 * DFF + f0) + tid;
    for (int d = 0; d < D1CH; d++) {
        float4 wv = w[(long long)d * (DFF / 4)];
        float4 x0 = *(const float4*)&xst[d][0];
        float4 x1 = *(const float4*)&xst[d][4];
        acc[0].x += wv.x * x0.x; acc[0].y += wv.y * x0.x; acc[0].z += wv.z * x0.x; acc[0].w += wv.w * x0.x;
        acc[1].x += wv.x * x0.y; acc[1].y += wv.y * x0.y; acc[1].z += wv.z * x0.y; acc[1].w += wv.w * x0.y;
        acc[2].x += wv.x * x0.z; acc[2].y += wv.y * x0.z; acc[2].z += wv.z * x0.z; acc[2].w += wv.w * x0.z;
        acc[3].x += wv.x * x0.w; acc[3].y += wv.y * x0.w; acc[3].z += wv.z * x0.w; acc[3].w += wv.w * x0.w;
        acc[4].x += wv.x * x1.x; acc[4].y += wv.y * x1.x; acc[4].z += wv.z * x1.x; acc[4].w += wv.w * x1.x;
        acc[5].x += wv.x * x1.y; acc[5].y += wv.y * x1.y; acc[5].z += wv.z * x1.y; acc[5].w += wv.w * x1.y;
        acc[6].x += wv.x * x1.z; acc[6].y += wv.y * x1.z; acc[6].z += wv.z * x1.z; acc[6].w += wv.w * x1.z;
        acc[7].x += wv.x * x1.w; acc[7].y += wv.y * x1.w; acc[7].z += wv.z * x1.w; acc[7].w += wv.w * x1.w;
    }
#pragma unroll
    for (int r = 0; r < 8; r++) {
        *(float4*)(h1p + (((long long)ds * 8 + r) * EE + e) * DFF + f0 + tid * 4) = acc[r];
    }
}

// ---------------- h1 reduce + bias + gelu -> hidT[e][f][r] ----------------
__global__ void h1_reduce_kernel(const float* __restrict__ h1p, const float* __restrict__ b1,
                                 float* __restrict__ hidT) {
    int i = blockIdx.x * 256 + threadIdx.x;      // over 8 * EE * DFF
    int r = i / (EE * DFF);
    int rem = i - r * (EE * DFF);                // e*DFF + f
    float a = b1[rem];
#pragma unroll
    for (int ds = 0; ds < DS1; ds++)
        a += h1p[((long long)ds * 8 + r) * EE * DFF + rem];
    hidT[(long long)rem * 8 + r] = 0.5f * a * (1.0f + erff(a * 0.70710678118654752f));
}

// ---------------- expert FFN2 partials: ysp[fs][row][d] ----------------
__global__ __launch_bounds__(256) void ffn2_kernel(
    const float* __restrict__ hidT, const float* __restrict__ w2,
    float* __restrict__ ysp) {
    int e = blockIdx.x, fs = blockIdx.y;
    int f0 = fs * FCH;
    int tid = threadIdx.x;
    __shared__ __align__(16) float hs[FCH][8];
    for (int i = tid; i < FCH * 8; i += 256) {
        int f = i >> 3, r = i & 7;
        hs[f][r] = hidT[((long long)e * DFF + f0 + f) * 8 + r];
    }
    __syncthreads();
    float4 acc[8];
#pragma unroll
    for (int r = 0; r < 8; r++) acc[r] = make_float4(0.f, 0.f, 0.f, 0.f);
    const float4* w = (const float4*)(w2 + (long long)e * DFF * DD + (long long)f0 * DD) + tid;
    for (int f = 0; f < FCH; f++) {
        float4 wv = w[(long long)f * (DD / 4)];
        float4 h0 = *(const float4*)&hs[f][0];
        float4 h1 = *(const float4*)&hs[f][4];
        acc[0].x += wv.x * h0.x; acc[0].y += wv.y * h0.x; acc[0].z += wv.z * h0.x; acc[0].w += wv.w * h0.x;
        acc[1].x += wv.x * h0.y; acc[1].y += wv.y * h0.y; acc[1].z += wv.z * h0.y; acc[1].w += wv.w * h0.y;
        acc[2].x += wv.x * h0.z; acc[2].y += wv.y * h0.z; acc[2].z += wv.z * h0.z; acc[2].w += wv.w * h0.z;
        acc[3].x += wv.x * h0.w; acc[3].y += wv.y * h0.w; acc[3].z += wv.z * h0.w; acc[3].w += wv.w * h0.w;
        acc[4].x += wv.x * h1.x; acc[4].y += wv.y * h1.x; acc[4].z += wv.z * h1.x; acc[4].w += wv.w * h1.x;
        acc[5].x += wv.x * h1.y; acc[5].y += wv.y * h1.y; acc[5].z += wv.z * h1.y; acc[5].w += wv.w * h1.y;
        acc[6].x += wv.x * h1.z; acc[6].y += wv.y * h1.z; acc[6].z += wv.z * h1.z; acc[6].w += wv.w * h1.z;
        acc[7].x += wv.x * h1.w; acc[7].y += wv.y * h1.w; acc[7].z += wv.z * h1.w; acc[7].w += wv.w * h1.w;
    }
#pragma unroll
    for (int r = 0; r < 8; r++) {
        int b = r >> 1, slot = r & 1;
        int rowl = b * NSLOT + e * 2 + slot;
        *(float4*)(ysp + ((long long)fs * BB * NSLOT + rowl) * DD + tid * 4) = acc[r];
    }
}

// ---------------- ys reduce + bias ----------------
__global__ void ys_reduce_kernel(const float* __restrict__ ysp, const float* __restrict__ b2,
                                 float* __restrict__ ys) {
    int i = blockIdx.x * 256 + threadIdx.x;   // over BB*NSLOT*DD
    int row = i >> 10, d = i & 1023;
    int e = (row & 15) >> 1;
    float a = b2[e * DD + d];
#pragma unroll
    for (int fs = 0; fs < FSEG; fs++)
        a += ysp[(long long)fs * BB * NSLOT * DD + i];
    ys[i] = a;
}

// ---------------- final: out = m + combine @ ys (row per block, float4) ----------------
__global__ __launch_bounds__(256) void final_kernel(
    const float* __restrict__ m, const float* __restrict__ comb,
    const float* __restrict__ ys, float* __restrict__ out) {
    long long row = blockIdx.x;
    int b = (int)(row >> 11);
    int tid = threadIdx.x;
    __shared__ float cs[NSLOT];
    if (tid < NSLOT) cs[tid] = comb[row * NSLOT + tid];
    __syncthreads();
    float4 acc = *(const float4*)(m + row * DD + tid * 4);
    const float* yb = ys + (long long)b * NSLOT * DD + tid * 4;
#pragma unroll
    for (int j = 0; j < NSLOT; j++) {
        float4 yv = *(const float4*)(yb + (long long)j * DD);
        float c = cs[j];
        acc.x += c * yv.x; acc.y += c * yv.y;
        acc.z += c * yv.z; acc.w += c * yv.w;
    }
    *(float4*)(out + row * DD + tid * 4) = acc;
}

// ---------------- launch ----------------
extern "C" void kernel_launch(void* const* d_in, const int* in_sizes, int n_in,
                              void* d_out, int out_size) {
    const float* x        = (const float*)d_in[0];
    const float* wq       = (const float*)d_in[1];
    const float* wkv      = (const float*)d_in[2];
    const float* wo       = (const float*)d_in[3];
    const float* gm_attn  = (const float*)d_in[4];
    const float* gm_moe   = (const float*)d_in[5];
    const float* phi      = (const float*)d_in[6];
    const float* w1       = (const float*)d_in[7];
    const float* b1       = (const float*)d_in[8];
    const float* w2       = (const float*)d_in[9];
    const float* b2       = (const float*)d_in[10];
    float* out = (float*)d_out;

    float *h, *x1, *m, *lg, *dp, *cb, *xs, *xsp, *h1p, *hidT, *ysp, *ys, *phiT;
    __nv_bfloat16 *hb, *qb, *kvb, *vt, *ccb, *wqkvT, *woT;
    cudaGetSymbolAddress((void**)&h,     g_h);
    cudaGetSymbolAddress((void**)&hb,    g_hb);
    cudaGetSymbolAddress((void**)&qb,    g_qb);
    cudaGetSymbolAddress((void**)&kvb,   g_kvb);
    cudaGetSymbolAddress((void**)&vt,    g_vT);
    cudaGetSymbolAddress((void**)&ccb,   g_ccb);
    cudaGetSymbolAddress((void**)&wqkvT, g_wqkvT);
    cudaGetSymbolAddress((void**)&woT,   g_woT);
    cudaGetSymbolAddress((void**)&phiT,  g_phiT);
    cudaGetSymbolAddress((void**)&x1,    g_x1);
    cudaGetSymbolAddress((void**)&m,     g_m);
    cudaGetSymbolAddress((void**)&lg,    g_logits);
    cudaGetSymbolAddress((void**)&dp,    g_dispatch);
    cudaGetSymbolAddress((void**)&cb,    g_combine);
    cudaGetSymbolAddress((void**)&xs,    g_xs);
    cudaGetSymbolAddress((void**)&xsp,   g_xs_part);
    cudaGetSymbolAddress((void**)&h1p,   g_h1p);
    cudaGetSymbolAddress((void**)&hidT,  g_hidT);
    cudaGetSymbolAddress((void**)&ysp,   g_ys_part);
    cudaGetSymbolAddress((void**)&ys,    g_ys);

    const int G_SMEM128 = 2048 + 3 * 16384 + 3 * 128 * 128; // 100352
    const int G_SMEM256 = 2048 + 3 * 16384 + 3 * 256 * 128; // 149504
    cudaFuncSetAttribute((void*)gemm_kernel<128, false, true, true>,
                         cudaFuncAttributeMaxDynamicSharedMemorySize, G_SMEM128);
    cudaFuncSetAttribute((void*)gemm_kernel<256, true, false, false>,
                         cudaFuncAttributeMaxDynamicSharedMemorySize, G_SMEM256);
    const int F_SMEM = 1024 + 2048 + 4 * 16384;
    cudaFuncSetAttribute(flash_kernel,
                         cudaFuncAttributeMaxDynamicSharedMemorySize, F_SMEM);

    // 0) ln: h = LN(x), hb
    ln_kernel<<<ROWS, 256>>>(x, gm_attn, h, hb);
    // 1) wq transpose -> wqkvT rows 0..1023
    transpose_cvt_kernel<<<dim3(32, 32), dim3(32, 8)>>>(wq, wqkvT, DD, DD);
    // 2) wkv transpose -> wqkvT rows 1024..1151
    transpose_cvt_kernel<<<dim3(4, 32), dim3(32, 8)>>>(wkv, wqkvT + (long long)DD * DD, DD, 128);
    // 3) merged qkv gemm (BN=128, grid 9x64; blocks 0-7 -> q scaled, block 8 -> kv)
    gemm_kernel<128, false, true, true><<<dim3(9, 64), 256, G_SMEM128>>>(
        hb, wqkvT, nullptr, nullptr, qb, kvb, ROWS, DD, DD, 0.125f * 1.4426950408889634f);
    // 4) wo transpose
    transpose_cvt_kernel<<<dim3(32, 32), dim3(32, 8)>>>(wo, woT, DD, DD);
    // 5) phi transpose
    phiT_kernel<<<DD / 256, 256>>>(phi, phiT);
    // 6) vT
    vT_kernel<<<dim3(SS / 32, HD / 32, BB), dim3(32, 8)>>>(kvb, vt);
    // 7) flash (pipelined)
    flash_kernel<<<dim3(SS / 128, BB * HH), 256, F_SMEM>>>(qb, kvb, vt, ccb);
    // 8) x1 = concat @ wo + h (BN=256)
    gemm_kernel<256, true, false, false><<<dim3(4, 64), 256, G_SMEM256>>>(
        ccb, woT, h, x1, nullptr, nullptr, ROWS, DD, DD, 1.0f);
    // 9) m = LN(x1)
    ln_kernel<<<ROWS, 256>>>(x1, gm_moe, m, nullptr);
    // 10) logits + dispatch (4 rows per block)
    logits_kernel<<<ROWS / 4, 128>>>(m, phiT, lg, dp);
    // 11) combine
    combine_kernel<<<BB * NSLOT, 256>>>(lg, cb);
    // 12) xs partials (SSEG=16 -> 256 blocks)
    xs_part_kernel<<<dim3(DD / 256, BB, SSEG), 256>>>(dp, m, xsp);
    // 13) xs reduce
    xs_reduce_kernel<<<(BB * NSLOT * DD) / 256, 256>>>(xsp, xs);
    // 14) ffn1 partials (DS1=8 -> 256 blocks)
    ffn1_kernel<<<dim3(EE, FS1, DS1), 256>>>(xs, w1, h1p);
    // 15) h1 reduce + bias + gelu
    h1_reduce_kernel<<<(8 * EE * DFF) / 256, 256>>>(h1p, b1, hidT);
    // 16) ffn2 partials
    ffn2_kernel<<<dim3(EE, FSEG), 256>>>(hidT, w2, ysp);
    // 17) ys reduce + bias
    ys_reduce_kernel<<<(BB * NSLOT * DD) / 256, 256>>>(ysp, b2, ys);
    // 18) final
    final_kernel<<<ROWS, 256>>>(m, cb, ys, out);
}